// round 1
// baseline (speedup 1.0000x reference)
#include <cuda_runtime.h>

// Problem constants
#define FEAT   224
#define NPAT   32
#define H_IMG  256
#define W_IMG  512
#define W_PAT  1024
#define S_CAM  (H_IMG * W_IMG)   // 131072 samples
#define S_PROJ W_PAT              // 1024 samples

// Scratch (device globals; no runtime allocation allowed)
__device__ float g_P [S_CAM  * FEAT];  // p_cam        (131072 x 224)
__device__ float g_X [S_CAM  * FEAT];  // running x    (131072 x 224)
__device__ float g_Hc[S_CAM  * FEAT];  // hidden / Anorm
__device__ float g_Pp[S_PROJ * FEAT];  // p_proj^T     (1024 x 224)
__device__ float g_Xp[S_PROJ * FEAT];
__device__ float g_Hp[S_PROJ * FEAT];  // hidden / Bnorm

// ---------------------------------------------------------------------------
// Build p_cam: P[s, j*32+k] = cam_code[h, clamp(w + j - 3), k], s = h*512 + w
// Also seeds X = P.
// ---------------------------------------------------------------------------
__global__ void build_pcam(const float* __restrict__ cam,
                           float* __restrict__ P, float* __restrict__ X) {
    int idx = blockIdx.x * blockDim.x + threadIdx.x;
    if (idx >= S_CAM * FEAT) return;
    int s = idx / FEAT;
    int f = idx - s * FEAT;
    int j = f / NPAT;
    int k = f - j * NPAT;
    int w = s & (W_IMG - 1);
    int h = s >> 9;  // /512
    int wc = w + j - 3;
    wc = wc < 0 ? 0 : (wc > W_IMG - 1 ? W_IMG - 1 : wc);
    float v = cam[(h * W_IMG + wc) * NPAT + k];
    P[idx] = v;
    X[idx] = v;
}

// ---------------------------------------------------------------------------
// Build p_proj^T: Pp[m, j*32+k] = proj_code[k, clamp(m + j - 3)]
// ---------------------------------------------------------------------------
__global__ void build_pproj(const float* __restrict__ proj,
                            float* __restrict__ P, float* __restrict__ X) {
    int idx = blockIdx.x * blockDim.x + threadIdx.x;
    if (idx >= S_PROJ * FEAT) return;
    int m = idx / FEAT;
    int f = idx - m * FEAT;
    int j = f / NPAT;
    int k = f - j * NPAT;
    int mp = m + j - 3;
    mp = mp < 0 ? 0 : (mp > W_PAT - 1 ? W_PAT - 1 : mp);
    float v = proj[k * W_PAT + mp];
    P[idx] = v;
    X[idx] = v;
}

// ---------------------------------------------------------------------------
// Tiled SGEMM: C[M,N] = epilogue(A[M,K] @ W[N,K]^T)
// MODE bit 0: + bias[n];  bit 1: relu;  bit 2: + Res[m,n]
// 128x128 tile, BK=8, 256 threads, 8x8 per-thread microtile.
// Requires M % 128 == 0, K % 8 == 0. N edge handled via guards.
// ---------------------------------------------------------------------------
template <int MODE>
__global__ void __launch_bounds__(256)
sgemm(const float* __restrict__ A, const float* __restrict__ W,
      const float* __restrict__ bias, const float* __restrict__ Res,
      float* __restrict__ C, int M, int N, int K) {
    __shared__ float As[8][128];
    __shared__ float Bs[8][128];

    const int t  = threadIdx.x;
    const int m0 = blockIdx.x * 128;
    const int n0 = blockIdx.y * 128;

    // Loader mapping: each thread fetches one float4 per K-step for A and W.
    const int lrow = t >> 1;          // 0..127
    const int lk   = (t & 1) * 4;     // 0 or 4
    const float* Aptr  = A + (long)(m0 + lrow) * K + lk;
    const int    wrow  = n0 + lrow;
    const bool   wval  = wrow < N;
    const float* Wptr  = W + (long)(wval ? wrow : 0) * K + lk;

    // Compute mapping: 16x16 thread grid, 8x8 outputs each.
    const int tx = t & 15;
    const int ty = t >> 4;

    float c[8][8];
#pragma unroll
    for (int i = 0; i < 8; i++)
#pragma unroll
        for (int j = 0; j < 8; j++) c[i][j] = 0.0f;

    for (int k0 = 0; k0 < K; k0 += 8) {
        float4 av = *(const float4*)(Aptr + k0);
        float4 bv = wval ? *(const float4*)(Wptr + k0) : make_float4(0.f, 0.f, 0.f, 0.f);
        __syncthreads();
        As[lk + 0][lrow] = av.x; As[lk + 1][lrow] = av.y;
        As[lk + 2][lrow] = av.z; As[lk + 3][lrow] = av.w;
        Bs[lk + 0][lrow] = bv.x; Bs[lk + 1][lrow] = bv.y;
        Bs[lk + 2][lrow] = bv.z; Bs[lk + 3][lrow] = bv.w;
        __syncthreads();
#pragma unroll
        for (int kk = 0; kk < 8; kk++) {
            float4 a0 = *(const float4*)&As[kk][ty * 8];
            float4 a1 = *(const float4*)&As[kk][ty * 8 + 4];
            float4 b0 = *(const float4*)&Bs[kk][tx * 8];
            float4 b1 = *(const float4*)&Bs[kk][tx * 8 + 4];
            float a[8] = {a0.x, a0.y, a0.z, a0.w, a1.x, a1.y, a1.z, a1.w};
            float b[8] = {b0.x, b0.y, b0.z, b0.w, b1.x, b1.y, b1.z, b1.w};
#pragma unroll
            for (int i = 0; i < 8; i++)
#pragma unroll
                for (int j = 0; j < 8; j++) c[i][j] += a[i] * b[j];
        }
    }

#pragma unroll
    for (int i = 0; i < 8; i++) {
        int m = m0 + ty * 8 + i;
#pragma unroll
        for (int j = 0; j < 8; j++) {
            int n = n0 + tx * 8 + j;
            if (n < N) {
                float v = c[i][j];
                if (MODE & 1) v += bias[n];
                if (MODE & 2) v = fmaxf(v, 0.0f);
                if (MODE & 4) v += Res[(long)m * N + n];
                C[(long)m * N + n] = v;
            }
        }
    }
}

// ---------------------------------------------------------------------------
// Per-row zero-mean + unit-norm of (X + P), 224 features, one warp per row.
// ---------------------------------------------------------------------------
__global__ void normalize_rows(const float* __restrict__ X,
                               const float* __restrict__ P,
                               float* __restrict__ Out, int M) {
    int warp = (blockIdx.x * blockDim.x + threadIdx.x) >> 5;
    int lane = threadIdx.x & 31;
    if (warp >= M) return;
    long base = (long)warp * FEAT;
    float y[7];
    float sum = 0.f;
#pragma unroll
    for (int i = 0; i < 7; i++) {
        int o = lane + i * 32;
        y[i] = X[base + o] + P[base + o];
        sum += y[i];
    }
#pragma unroll
    for (int o = 16; o > 0; o >>= 1) sum += __shfl_xor_sync(0xffffffffu, sum, o);
    float mean = sum * (1.0f / FEAT);
    float sq = 0.f;
#pragma unroll
    for (int i = 0; i < 7; i++) {
        y[i] -= mean;
        sq += y[i] * y[i];
    }
#pragma unroll
    for (int o = 16; o > 0; o >>= 1) sq += __shfl_xor_sync(0xffffffffu, sq, o);
    float inv = rsqrtf(sq);
#pragma unroll
    for (int i = 0; i < 7; i++) Out[base + lane + i * 32] = y[i] * inv;
}

// ---------------------------------------------------------------------------
extern "C" void kernel_launch(void* const* d_in, const int* in_sizes, int n_in,
                              void* d_out, int out_size) {
    const float* cam_code = (const float*)d_in[0];
    const float* proj_code = (const float*)d_in[1];
    const float* cam_w0 = (const float*)d_in[2];
    const float* cam_b0 = (const float*)d_in[3];
    const float* cam_w1 = (const float*)d_in[4];
    const float* cam_b1 = (const float*)d_in[5];
    const float* proj_w0 = (const float*)d_in[6];
    const float* proj_b0 = (const float*)d_in[7];
    const float* proj_w1 = (const float*)d_in[8];
    const float* proj_b1 = (const float*)d_in[9];
    float* out = (float*)d_out;

    float *P, *X, *Hc, *Pp, *Xp, *Hp;
    cudaGetSymbolAddress((void**)&P,  g_P);
    cudaGetSymbolAddress((void**)&X,  g_X);
    cudaGetSymbolAddress((void**)&Hc, g_Hc);
    cudaGetSymbolAddress((void**)&Pp, g_Pp);
    cudaGetSymbolAddress((void**)&Xp, g_Xp);
    cudaGetSymbolAddress((void**)&Hp, g_Hp);

    // 1) Neighbor expansion
    build_pcam<<<(S_CAM * FEAT + 255) / 256, 256>>>(cam_code, P, X);
    build_pproj<<<(S_PROJ * FEAT + 255) / 256, 256>>>(proj_code, Pp, Xp);

    // 2) Residual MLP blocks (2 layers each)
    dim3 gcam(S_CAM / 128, (FEAT + 127) / 128);   // (1024, 2)
    dim3 gprj(S_PROJ / 128, (FEAT + 127) / 128);  // (8, 2)
    for (int l = 0; l < 2; l++) {
        const float* w0c = cam_w0 + (long)l * FEAT * FEAT;
        const float* b0c = cam_b0 + (long)l * FEAT;
        const float* w1c = cam_w1 + (long)l * FEAT * FEAT;
        const float* b1c = cam_b1 + (long)l * FEAT;
        sgemm<3><<<gcam, 256>>>(X, w0c, b0c, nullptr, Hc, S_CAM, FEAT, FEAT);   // H = relu(X W0^T + b0)
        sgemm<5><<<gcam, 256>>>(Hc, w1c, b1c, X, X, S_CAM, FEAT, FEAT);         // X = X + H W1^T + b1

        const float* w0p = proj_w0 + (long)l * FEAT * FEAT;
        const float* b0p = proj_b0 + (long)l * FEAT;
        const float* w1p = proj_w1 + (long)l * FEAT * FEAT;
        const float* b1p = proj_b1 + (long)l * FEAT;
        sgemm<3><<<gprj, 256>>>(Xp, w0p, b0p, nullptr, Hp, S_PROJ, FEAT, FEAT);
        sgemm<5><<<gprj, 256>>>(Hp, w1p, b1p, Xp, Xp, S_PROJ, FEAT, FEAT);
    }

    // 3) y = f + p, zero-mean + unit-norm per sample  (Anorm -> Hc, Bnorm -> Hp)
    normalize_rows<<<(S_CAM + 7) / 8, 256>>>(X, P, Hc, S_CAM);
    normalize_rows<<<(S_PROJ + 7) / 8, 256>>>(Xp, Pp, Hp, S_PROJ);

    // 4) ZNCC correlation: out[s, m] = Anorm[s,:] . Bnorm[m,:]
    dim3 gfin(S_CAM / 128, W_PAT / 128);  // (1024, 8)
    sgemm<0><<<gfin, 256>>>(Hc, Hp, nullptr, nullptr, out, S_CAM, W_PAT, FEAT);
}

// round 2
// speedup vs baseline: 2.8893x; 2.8893x over previous
#include <cuda_runtime.h>
#include <cstdint>

// Problem constants
#define FEAT   224
#define NPAT   32
#define H_IMG  256
#define W_IMG  512
#define W_PAT  1024
#define S_CAM  (H_IMG * W_IMG)   // 131072 samples
#define S_PROJ W_PAT             // 1024 samples

// Scratch (device globals; no runtime allocation allowed)
__device__ float g_P [S_CAM  * FEAT];  // p_cam        (131072 x 224)
__device__ float g_X [S_CAM  * FEAT];  // running x
__device__ float g_Hc[S_CAM  * FEAT];  // hidden / Anorm
__device__ float g_Pp[S_PROJ * FEAT];  // p_proj^T     (1024 x 224)
__device__ float g_Xp[S_PROJ * FEAT];
__device__ float g_Hp[S_PROJ * FEAT];  // hidden / Bnorm

// ---------------------------------------------------------------------------
// Neighbor expansion
// ---------------------------------------------------------------------------
__global__ void build_pcam(const float* __restrict__ cam,
                           float* __restrict__ P, float* __restrict__ X) {
    int idx = blockIdx.x * blockDim.x + threadIdx.x;
    if (idx >= S_CAM * FEAT) return;
    int s = idx / FEAT;
    int f = idx - s * FEAT;
    int j = f / NPAT;
    int k = f - j * NPAT;
    int w = s & (W_IMG - 1);
    int h = s >> 9;
    int wc = w + j - 3;
    wc = wc < 0 ? 0 : (wc > W_IMG - 1 ? W_IMG - 1 : wc);
    float v = cam[(h * W_IMG + wc) * NPAT + k];
    P[idx] = v;
    X[idx] = v;
}

__global__ void build_pproj(const float* __restrict__ proj,
                            float* __restrict__ P, float* __restrict__ X) {
    int idx = blockIdx.x * blockDim.x + threadIdx.x;
    if (idx >= S_PROJ * FEAT) return;
    int m = idx / FEAT;
    int f = idx - m * FEAT;
    int j = f / NPAT;
    int k = f - j * NPAT;
    int mp = m + j - 3;
    mp = mp < 0 ? 0 : (mp > W_PAT - 1 ? W_PAT - 1 : mp);
    float v = proj[k * W_PAT + mp];
    P[idx] = v;
    X[idx] = v;
}

// ---------------------------------------------------------------------------
// TF32 tensor-core GEMM: C[M,N] = epilogue(A[M,K] @ W[N,K]^T)
// MODE bit 0: + bias[n];  bit 1: relu;  bit 2: + Res[m,n]
// Block tile 128x128, BK=16, 256 threads (8 warps as 2m x 4n, 64x32 warp tile)
// mma.sync.m16n8k8.tf32, fp32 accumulate. Requires M%128==0, K%16==0.
// Smem layout: [row][k] padded to stride 20 words -> conflict-free frag loads.
// ---------------------------------------------------------------------------
#define BK     16
#define LDS_S  20   // padded row stride in 32-bit words

__device__ __forceinline__ uint4 cvt_tf32x4(float4 v) {
    uint4 u;
    asm("cvt.rna.tf32.f32 %0, %1;" : "=r"(u.x) : "f"(v.x));
    asm("cvt.rna.tf32.f32 %0, %1;" : "=r"(u.y) : "f"(v.y));
    asm("cvt.rna.tf32.f32 %0, %1;" : "=r"(u.z) : "f"(v.z));
    asm("cvt.rna.tf32.f32 %0, %1;" : "=r"(u.w) : "f"(v.w));
    return u;
}

template <int MODE>
__global__ void __launch_bounds__(256)
tgemm(const float* __restrict__ A, const float* __restrict__ W,
      const float* __restrict__ bias, const float* __restrict__ Res,
      float* __restrict__ C, int M, int N, int K) {
    __shared__ uint32_t As[2][128 * LDS_S];
    __shared__ uint32_t Bs[2][128 * LDS_S];

    const int t    = threadIdx.x;
    const int lane = t & 31;
    const int wid  = t >> 5;
    const int wm   = wid & 1;   // 0..1  (64-row slabs)
    const int wn   = wid >> 1;  // 0..3  (32-col slabs)
    const int m0   = blockIdx.x * 128;
    const int n0   = blockIdx.y * 128;

    // Loader mapping: thread covers rows lrow and lrow+64, 4 floats at lcol.
    const int lrow = t >> 2;          // 0..63
    const int lcol = (t & 3) << 2;    // 0,4,8,12

    const float* Ag0 = A + (size_t)(m0 + lrow) * K + lcol;
    const float* Ag1 = Ag0 + (size_t)64 * K;
    int br0 = n0 + lrow;      if (br0 > N - 1) br0 = N - 1;
    int br1 = n0 + lrow + 64; if (br1 > N - 1) br1 = N - 1;
    const float* Bg0 = W + (size_t)br0 * K + lcol;
    const float* Bg1 = W + (size_t)br1 * K + lcol;

    const int lq = lane >> 2;  // 0..7
    const int lr = lane & 3;   // 0..3

    float c[4][4][4];
#pragma unroll
    for (int i = 0; i < 4; i++)
#pragma unroll
        for (int j = 0; j < 4; j++)
#pragma unroll
            for (int r = 0; r < 4; r++) c[i][j][r] = 0.0f;

    const int nstages = K / BK;   // 14 for K=224

    float4 pa0 = *(const float4*)(Ag0);
    float4 pa1 = *(const float4*)(Ag1);
    float4 pb0 = *(const float4*)(Bg0);
    float4 pb1 = *(const float4*)(Bg1);

    {   // stage 0 STS
        *(uint4*)&As[0][lrow * LDS_S + lcol]        = cvt_tf32x4(pa0);
        *(uint4*)&As[0][(lrow + 64) * LDS_S + lcol] = cvt_tf32x4(pa1);
        *(uint4*)&Bs[0][lrow * LDS_S + lcol]        = cvt_tf32x4(pb0);
        *(uint4*)&Bs[0][(lrow + 64) * LDS_S + lcol] = cvt_tf32x4(pb1);
    }
    __syncthreads();

    for (int kt = 0; kt < nstages; kt++) {
        const int s = kt & 1;
        if (kt + 1 < nstages) {
            int off = (kt + 1) * BK;
            pa0 = *(const float4*)(Ag0 + off);
            pa1 = *(const float4*)(Ag1 + off);
            pb0 = *(const float4*)(Bg0 + off);
            pb1 = *(const float4*)(Bg1 + off);
        }

        const uint32_t* as = As[s];
        const uint32_t* bs = Bs[s];
#pragma unroll
        for (int ks = 0; ks < 2; ks++) {
            const int kb = ks * 8;
            uint32_t af[4][4];
#pragma unroll
            for (int mf = 0; mf < 4; mf++) {
                int r = wm * 64 + mf * 16 + lq;
                const uint32_t* p = as + r * LDS_S + kb + lr;
                af[mf][0] = p[0];
                af[mf][1] = p[8 * LDS_S];
                af[mf][2] = p[4];
                af[mf][3] = p[8 * LDS_S + 4];
            }
            uint32_t bf[4][2];
#pragma unroll
            for (int nf = 0; nf < 4; nf++) {
                int r = wn * 32 + nf * 8 + lq;
                const uint32_t* p = bs + r * LDS_S + kb + lr;
                bf[nf][0] = p[0];
                bf[nf][1] = p[4];
            }
#pragma unroll
            for (int mf = 0; mf < 4; mf++)
#pragma unroll
                for (int nf = 0; nf < 4; nf++) {
                    asm volatile(
                        "mma.sync.aligned.m16n8k8.row.col.f32.tf32.tf32.f32 "
                        "{%0,%1,%2,%3}, {%4,%5,%6,%7}, {%8,%9}, {%0,%1,%2,%3};"
                        : "+f"(c[mf][nf][0]), "+f"(c[mf][nf][1]),
                          "+f"(c[mf][nf][2]), "+f"(c[mf][nf][3])
                        : "r"(af[mf][0]), "r"(af[mf][1]),
                          "r"(af[mf][2]), "r"(af[mf][3]),
                          "r"(bf[nf][0]), "r"(bf[nf][1]));
                }
        }

        if (kt + 1 < nstages) {
            const int sn = (kt + 1) & 1;
            *(uint4*)&As[sn][lrow * LDS_S + lcol]        = cvt_tf32x4(pa0);
            *(uint4*)&As[sn][(lrow + 64) * LDS_S + lcol] = cvt_tf32x4(pa1);
            *(uint4*)&Bs[sn][lrow * LDS_S + lcol]        = cvt_tf32x4(pb0);
            *(uint4*)&Bs[sn][(lrow + 64) * LDS_S + lcol] = cvt_tf32x4(pb1);
            __syncthreads();
        }
    }

    // Epilogue
#pragma unroll
    for (int mf = 0; mf < 4; mf++) {
        int row = m0 + wm * 64 + mf * 16 + lq;
#pragma unroll
        for (int nf = 0; nf < 4; nf++) {
            int col = n0 + wn * 32 + nf * 8 + lr * 2;
            if (col < N) {
                float b0 = 0.f, b1 = 0.f;
                if (MODE & 1) { b0 = bias[col]; b1 = bias[col + 1]; }
#pragma unroll
                for (int half = 0; half < 2; half++) {
                    int r = row + half * 8;
                    float v0 = c[mf][nf][half * 2 + 0];
                    float v1 = c[mf][nf][half * 2 + 1];
                    if (MODE & 1) { v0 += b0; v1 += b1; }
                    if (MODE & 2) { v0 = fmaxf(v0, 0.f); v1 = fmaxf(v1, 0.f); }
                    size_t o = (size_t)r * N + col;
                    if (MODE & 4) {
                        float2 rv = *(const float2*)(Res + o);
                        v0 += rv.x; v1 += rv.y;
                    }
                    *(float2*)(C + o) = make_float2(v0, v1);
                }
            }
        }
    }
}

// ---------------------------------------------------------------------------
// Per-row zero-mean + unit-norm of (X + P), 224 features, one warp per row.
// ---------------------------------------------------------------------------
__global__ void normalize_rows(const float* __restrict__ X,
                               const float* __restrict__ P,
                               float* __restrict__ Out, int M) {
    int warp = (blockIdx.x * blockDim.x + threadIdx.x) >> 5;
    int lane = threadIdx.x & 31;
    if (warp >= M) return;
    size_t base = (size_t)warp * FEAT;
    float y[7];
    float sum = 0.f;
#pragma unroll
    for (int i = 0; i < 7; i++) {
        int o = lane + i * 32;
        y[i] = X[base + o] + P[base + o];
        sum += y[i];
    }
#pragma unroll
    for (int o = 16; o > 0; o >>= 1) sum += __shfl_xor_sync(0xffffffffu, sum, o);
    float mean = sum * (1.0f / FEAT);
    float sq = 0.f;
#pragma unroll
    for (int i = 0; i < 7; i++) {
        y[i] -= mean;
        sq += y[i] * y[i];
    }
#pragma unroll
    for (int o = 16; o > 0; o >>= 1) sq += __shfl_xor_sync(0xffffffffu, sq, o);
    float inv = rsqrtf(sq);
#pragma unroll
    for (int i = 0; i < 7; i++) Out[base + lane + i * 32] = y[i] * inv;
}

// ---------------------------------------------------------------------------
extern "C" void kernel_launch(void* const* d_in, const int* in_sizes, int n_in,
                              void* d_out, int out_size) {
    const float* cam_code  = (const float*)d_in[0];
    const float* proj_code = (const float*)d_in[1];
    const float* cam_w0 = (const float*)d_in[2];
    const float* cam_b0 = (const float*)d_in[3];
    const float* cam_w1 = (const float*)d_in[4];
    const float* cam_b1 = (const float*)d_in[5];
    const float* proj_w0 = (const float*)d_in[6];
    const float* proj_b0 = (const float*)d_in[7];
    const float* proj_w1 = (const float*)d_in[8];
    const float* proj_b1 = (const float*)d_in[9];
    float* out = (float*)d_out;

    float *P, *X, *Hc, *Pp, *Xp, *Hp;
    cudaGetSymbolAddress((void**)&P,  g_P);
    cudaGetSymbolAddress((void**)&X,  g_X);
    cudaGetSymbolAddress((void**)&Hc, g_Hc);
    cudaGetSymbolAddress((void**)&Pp, g_Pp);
    cudaGetSymbolAddress((void**)&Xp, g_Xp);
    cudaGetSymbolAddress((void**)&Hp, g_Hp);

    // 1) Neighbor expansion
    build_pcam <<<(S_CAM  * FEAT + 255) / 256, 256>>>(cam_code,  P,  X);
    build_pproj<<<(S_PROJ * FEAT + 255) / 256, 256>>>(proj_code, Pp, Xp);

    // 2) Residual MLP blocks (2 layers each)
    dim3 gcam(S_CAM / 128, (FEAT + 127) / 128);   // (1024, 2)
    dim3 gprj(S_PROJ / 128, (FEAT + 127) / 128);  // (8, 2)
    for (int l = 0; l < 2; l++) {
        const float* w0c = cam_w0 + (size_t)l * FEAT * FEAT;
        const float* b0c = cam_b0 + (size_t)l * FEAT;
        const float* w1c = cam_w1 + (size_t)l * FEAT * FEAT;
        const float* b1c = cam_b1 + (size_t)l * FEAT;
        tgemm<3><<<gcam, 256>>>(X,  w0c, b0c, nullptr, Hc, S_CAM, FEAT, FEAT);
        tgemm<5><<<gcam, 256>>>(Hc, w1c, b1c, X,       X,  S_CAM, FEAT, FEAT);

        const float* w0p = proj_w0 + (size_t)l * FEAT * FEAT;
        const float* b0p = proj_b0 + (size_t)l * FEAT;
        const float* w1p = proj_w1 + (size_t)l * FEAT * FEAT;
        const float* b1p = proj_b1 + (size_t)l * FEAT;
        tgemm<3><<<gprj, 256>>>(Xp, w0p, b0p, nullptr, Hp, S_PROJ, FEAT, FEAT);
        tgemm<5><<<gprj, 256>>>(Hp, w1p, b1p, Xp,      Xp, S_PROJ, FEAT, FEAT);
    }

    // 3) y = f + p, zero-mean + unit-norm  (Anorm -> Hc, Bnorm -> Hp)
    normalize_rows<<<(S_CAM  + 7) / 8, 256>>>(X,  P,  Hc, S_CAM);
    normalize_rows<<<(S_PROJ + 7) / 8, 256>>>(Xp, Pp, Hp, S_PROJ);

    // 4) ZNCC correlation: out[s, m] = Anorm[s,:] . Bnorm[m,:]
    dim3 gfin(S_CAM / 128, W_PAT / 128);  // (1024, 8)
    tgemm<0><<<gfin, 256>>>(Hc, Hp, nullptr, nullptr, out, S_CAM, W_PAT, FEAT);
}

// round 4
// speedup vs baseline: 3.3576x; 1.1621x over previous
#include <cuda_runtime.h>
#include <cstdint>

// Problem constants
#define FEAT   224
#define NPAT   32
#define H_IMG  256
#define W_IMG  512
#define W_PAT  1024
#define S_CAM  (H_IMG * W_IMG)   // 131072
#define S_PROJ W_PAT             // 1024

// Scratch (device globals)
__device__ float g_P [S_CAM  * FEAT];
__device__ float g_X [S_CAM  * FEAT];
__device__ float g_Hc[S_CAM  * FEAT];
__device__ float g_Pp[S_PROJ * FEAT];
__device__ float g_Xp[S_PROJ * FEAT];
__device__ float g_Hp[S_PROJ * FEAT];

// ---------------------------------------------------------------------------
// Helpers
// ---------------------------------------------------------------------------
__device__ __forceinline__ uint32_t smem_u32(const void* p) {
    uint32_t a;
    asm("{ .reg .u64 t; cvta.to.shared.u64 t, %1; cvt.u32.u64 %0, t; }"
        : "=r"(a) : "l"(p));
    return a;
}

__device__ __forceinline__ void cp16(uint32_t dst, const float* src) {
    asm volatile("cp.async.cg.shared.global [%0], [%1], 16;"
                 :: "r"(dst), "l"(src) : "memory");
}
__device__ __forceinline__ void cp_commit() {
    asm volatile("cp.async.commit_group;" ::: "memory");
}
__device__ __forceinline__ void cp_wait1() {
    asm volatile("cp.async.wait_group 1;" ::: "memory");
}

__device__ __forceinline__ uint32_t cvt_tf32(float v) {
    uint32_t u;
    asm("cvt.rna.tf32.f32 %0, %1;" : "=r"(u) : "f"(v));
    return u;
}

// ---------------------------------------------------------------------------
// Neighbor expansion
// ---------------------------------------------------------------------------
__global__ void build_pcam(const float* __restrict__ cam,
                           float* __restrict__ P, float* __restrict__ X) {
    int idx = blockIdx.x * blockDim.x + threadIdx.x;
    if (idx >= S_CAM * FEAT) return;
    int s = idx / FEAT;
    int f = idx - s * FEAT;
    int j = f / NPAT;
    int k = f - j * NPAT;
    int w = s & (W_IMG - 1);
    int h = s >> 9;
    int wc = w + j - 3;
    wc = wc < 0 ? 0 : (wc > W_IMG - 1 ? W_IMG - 1 : wc);
    float v = cam[(h * W_IMG + wc) * NPAT + k];
    P[idx] = v;
    X[idx] = v;
}

__global__ void build_pproj(const float* __restrict__ proj,
                            float* __restrict__ P, float* __restrict__ X) {
    int idx = blockIdx.x * blockDim.x + threadIdx.x;
    if (idx >= S_PROJ * FEAT) return;
    int m = idx / FEAT;
    int f = idx - m * FEAT;
    int j = f / NPAT;
    int k = f - j * NPAT;
    int mp = m + j - 3;
    mp = mp < 0 ? 0 : (mp > W_PAT - 1 ? W_PAT - 1 : mp);
    float v = proj[k * W_PAT + mp];
    P[idx] = v;
    X[idx] = v;
}

// ---------------------------------------------------------------------------
// TF32 mma.sync GEMM with cp.async 3-stage pipeline.
// C[M,N] = epilogue(A[M,K] @ W[N,K]^T)
// MODE bit 0: + bias[n];  bit 1: relu;  bit 2: + Res[m,n]
// 128x128 tile, BK=32 (7 chunks for K=224), 256 threads, 8 warps (2m x 4n),
// warp tile 64x32, mma.m16n8k8.tf32. Smem: raw f32 staged by cp.async with
// chunk^row&7 XOR swizzle (conflict-free LDS), cvt.rna applied on fragments.
// ---------------------------------------------------------------------------
#define BK       32
#define ST_WORDS (128 * BK)            // 4096 words / 16KB per operand-stage
#define NSTAGE   3
#define SMEM_BYTES (NSTAGE * 2 * ST_WORDS * 4)   // 98304

template <int MODE>
__global__ void __launch_bounds__(256, 2)
tgemm(const float* __restrict__ A, const float* __restrict__ W,
      const float* __restrict__ bias, const float* __restrict__ Res,
      float* __restrict__ C, int M, int N, int K) {
    extern __shared__ float smf[];
    float* Asm = smf;                        // 3 stages x 4096 words
    float* Bsm = smf + NSTAGE * ST_WORDS;    // 3 stages x 4096 words
    const uint32_t a_u32 = smem_u32(Asm);
    const uint32_t b_u32 = smem_u32(Bsm);

    const int t    = threadIdx.x;
    const int lane = t & 31;
    const int wid  = t >> 5;
    const int wm   = wid & 1;    // 64-row slab
    const int wn   = wid >> 1;   // 32-col slab
    const int n0   = blockIdx.x * 128;
    const int m0   = blockIdx.y * 128;
    const int nch  = K / BK;     // 7

    // --- cp.async loader mapping: 4 granules per operand per stage ---
    // granule g = t + 256*i : row = g>>3 (0..127), chunk = g&7 (16B col)
    const int lrow = t >> 3;
    const int lchk = t & 7;
    const float* Asrc[4];
    const float* Bsrc[4];
    uint32_t Adst[4], Bdst[4];
#pragma unroll
    for (int i = 0; i < 4; i++) {
        int row = lrow + 32 * i;
        Asrc[i] = A + (size_t)(m0 + row) * K + lchk * 4;
        int br = n0 + row; if (br > N - 1) br = N - 1;
        Bsrc[i] = W + (size_t)br * K + lchk * 4;
        uint32_t dw = (uint32_t)row * BK + ((lchk ^ (row & 7)) << 2);
        Adst[i] = a_u32 + dw * 4;
        Bdst[i] = b_u32 + dw * 4;
    }

    const int lq = lane >> 2;   // 0..7
    const int lr = lane & 3;    // 0..3

    float c[4][4][4];
#pragma unroll
    for (int i = 0; i < 4; i++)
#pragma unroll
        for (int j = 0; j < 4; j++)
#pragma unroll
            for (int r = 0; r < 4; r++) c[i][j][r] = 0.0f;

    // --- prologue: stages 0,1 ---
#pragma unroll
    for (int s = 0; s < 2; s++) {
#pragma unroll
        for (int i = 0; i < 4; i++) {
            cp16(Adst[i] + s * ST_WORDS * 4, Asrc[i] + s * BK);
            cp16(Bdst[i] + s * ST_WORDS * 4, Bsrc[i] + s * BK);
        }
        cp_commit();
    }

    for (int ch = 0; ch < nch; ch++) {
        cp_wait1();
        __syncthreads();
        if (ch + 2 < nch) {
            const int sl = (ch + 2) % NSTAGE;
#pragma unroll
            for (int i = 0; i < 4; i++) {
                cp16(Adst[i] + sl * ST_WORDS * 4, Asrc[i] + (ch + 2) * BK);
                cp16(Bdst[i] + sl * ST_WORDS * 4, Bsrc[i] + (ch + 2) * BK);
            }
        }
        cp_commit();

        const float* as = Asm + (ch % NSTAGE) * ST_WORDS;
        const float* bs = Bsm + (ch % NSTAGE) * ST_WORDS;
#pragma unroll
        for (int ks = 0; ks < 4; ks++) {
            // swizzled in-row word offset for k-subchunk: chunk = 2*ks (^1 for +4)
            const int sw0 = (((2 * ks) ^ lq) << 2) + lr;
            const int sw1 = sw0 ^ 4;
            uint32_t af[4][4];
#pragma unroll
            for (int mf = 0; mf < 4; mf++) {
                int r0 = (wm * 64 + mf * 16 + lq) * BK;
                int r1 = r0 + 8 * BK;
                af[mf][0] = cvt_tf32(as[r0 + sw0]);
                af[mf][1] = cvt_tf32(as[r1 + sw0]);
                af[mf][2] = cvt_tf32(as[r0 + sw1]);
                af[mf][3] = cvt_tf32(as[r1 + sw1]);
            }
            uint32_t bf[4][2];
#pragma unroll
            for (int nf = 0; nf < 4; nf++) {
                int rn = (wn * 32 + nf * 8 + lq) * BK;
                bf[nf][0] = cvt_tf32(bs[rn + sw0]);
                bf[nf][1] = cvt_tf32(bs[rn + sw1]);
            }
#pragma unroll
            for (int mf = 0; mf < 4; mf++)
#pragma unroll
                for (int nf = 0; nf < 4; nf++) {
                    asm volatile(
                        "mma.sync.aligned.m16n8k8.row.col.f32.tf32.tf32.f32 "
                        "{%0,%1,%2,%3}, {%4,%5,%6,%7}, {%8,%9}, {%0,%1,%2,%3};"
                        : "+f"(c[mf][nf][0]), "+f"(c[mf][nf][1]),
                          "+f"(c[mf][nf][2]), "+f"(c[mf][nf][3])
                        : "r"(af[mf][0]), "r"(af[mf][1]),
                          "r"(af[mf][2]), "r"(af[mf][3]),
                          "r"(bf[nf][0]), "r"(bf[nf][1]));
                }
        }
        __syncthreads();
    }

    // --- epilogue (32B-sector aligned float2 stores) ---
#pragma unroll
    for (int mf = 0; mf < 4; mf++) {
        int row = m0 + wm * 64 + mf * 16 + lq;
#pragma unroll
        for (int nf = 0; nf < 4; nf++) {
            int col = n0 + wn * 32 + nf * 8 + lr * 2;
            if (col < N) {
                float b0 = 0.f, b1 = 0.f;
                if (MODE & 1) { b0 = bias[col]; b1 = bias[col + 1]; }
#pragma unroll
                for (int half = 0; half < 2; half++) {
                    int r = row + half * 8;
                    float v0 = c[mf][nf][half * 2 + 0];
                    float v1 = c[mf][nf][half * 2 + 1];
                    if (MODE & 1) { v0 += b0; v1 += b1; }
                    if (MODE & 2) { v0 = fmaxf(v0, 0.f); v1 = fmaxf(v1, 0.f); }
                    size_t o = (size_t)r * N + col;
                    if (MODE & 4) {
                        float2 rv = *(const float2*)(Res + o);
                        v0 += rv.x; v1 += rv.y;
                    }
                    *(float2*)(C + o) = make_float2(v0, v1);
                }
            }
        }
    }
}

// ---------------------------------------------------------------------------
// Per-row zero-mean + unit-norm of (X + P), one warp per row.
// ---------------------------------------------------------------------------
__global__ void normalize_rows(const float* __restrict__ X,
                               const float* __restrict__ P,
                               float* __restrict__ Out, int M) {
    int warp = (blockIdx.x * blockDim.x + threadIdx.x) >> 5;
    int lane = threadIdx.x & 31;
    if (warp >= M) return;
    size_t base = (size_t)warp * FEAT;
    float y[7];
    float sum = 0.f;
#pragma unroll
    for (int i = 0; i < 7; i++) {
        int o = lane + i * 32;
        y[i] = X[base + o] + P[base + o];
        sum += y[i];
    }
#pragma unroll
    for (int o = 16; o > 0; o >>= 1) sum += __shfl_xor_sync(0xffffffffu, sum, o);
    float mean = sum * (1.0f / FEAT);
    float sq = 0.f;
#pragma unroll
    for (int i = 0; i < 7; i++) {
        y[i] -= mean;
        sq += y[i] * y[i];
    }
#pragma unroll
    for (int o = 16; o > 0; o >>= 1) sq += __shfl_xor_sync(0xffffffffu, sq, o);
    float inv = rsqrtf(sq);
#pragma unroll
    for (int i = 0; i < 7; i++) Out[base + lane + i * 32] = y[i] * inv;
}

// ---------------------------------------------------------------------------
extern "C" void kernel_launch(void* const* d_in, const int* in_sizes, int n_in,
                              void* d_out, int out_size) {
    const float* cam_code  = (const float*)d_in[0];
    const float* proj_code = (const float*)d_in[1];
    const float* cam_w0 = (const float*)d_in[2];
    const float* cam_b0 = (const float*)d_in[3];
    const float* cam_w1 = (const float*)d_in[4];
    const float* cam_b1 = (const float*)d_in[5];
    const float* proj_w0 = (const float*)d_in[6];
    const float* proj_b0 = (const float*)d_in[7];
    const float* proj_w1 = (const float*)d_in[8];
    const float* proj_b1 = (const float*)d_in[9];
    float* out = (float*)d_out;

    float *P, *X, *Hc, *Pp, *Xp, *Hp;
    cudaGetSymbolAddress((void**)&P,  g_P);
    cudaGetSymbolAddress((void**)&X,  g_X);
    cudaGetSymbolAddress((void**)&Hc, g_Hc);
    cudaGetSymbolAddress((void**)&Pp, g_Pp);
    cudaGetSymbolAddress((void**)&Xp, g_Xp);
    cudaGetSymbolAddress((void**)&Hp, g_Hp);

    cudaFuncSetAttribute(tgemm<0>, cudaFuncAttributeMaxDynamicSharedMemorySize, SMEM_BYTES);
    cudaFuncSetAttribute(tgemm<3>, cudaFuncAttributeMaxDynamicSharedMemorySize, SMEM_BYTES);
    cudaFuncSetAttribute(tgemm<5>, cudaFuncAttributeMaxDynamicSharedMemorySize, SMEM_BYTES);

    // 1) Neighbor expansion
    build_pcam <<<(S_CAM  * FEAT + 255) / 256, 256>>>(cam_code,  P,  X);
    build_pproj<<<(S_PROJ * FEAT + 255) / 256, 256>>>(proj_code, Pp, Xp);

    // 2) Residual MLP blocks
    dim3 gcam((FEAT + 127) / 128, S_CAM / 128);   // (2, 1024)
    dim3 gprj((FEAT + 127) / 128, S_PROJ / 128);  // (2, 8)
    for (int l = 0; l < 2; l++) {
        const float* w0c = cam_w0 + (size_t)l * FEAT * FEAT;
        const float* b0c = cam_b0 + (size_t)l * FEAT;
        const float* w1c = cam_w1 + (size_t)l * FEAT * FEAT;
        const float* b1c = cam_b1 + (size_t)l * FEAT;
        tgemm<3><<<gcam, 256, SMEM_BYTES>>>(X,  w0c, b0c, nullptr, Hc, S_CAM, FEAT, FEAT);
        tgemm<5><<<gcam, 256, SMEM_BYTES>>>(Hc, w1c, b1c, X,       X,  S_CAM, FEAT, FEAT);

        const float* w0p = proj_w0 + (size_t)l * FEAT * FEAT;
        const float* b0p = proj_b0 + (size_t)l * FEAT;
        const float* w1p = proj_w1 + (size_t)l * FEAT * FEAT;
        const float* b1p = proj_b1 + (size_t)l * FEAT;
        tgemm<3><<<gprj, 256, SMEM_BYTES>>>(Xp, w0p, b0p, nullptr, Hp, S_PROJ, FEAT, FEAT);
        tgemm<5><<<gprj, 256, SMEM_BYTES>>>(Hp, w1p, b1p, Xp,      Xp, S_PROJ, FEAT, FEAT);
    }

    // 3) y = f + p, zero-mean + unit-norm  (Anorm -> Hc, Bnorm -> Hp)
    normalize_rows<<<(S_CAM  + 7) / 8, 256>>>(X,  P,  Hc, S_CAM);
    normalize_rows<<<(S_PROJ + 7) / 8, 256>>>(Xp, Pp, Hp, S_PROJ);

    // 4) ZNCC correlation
    dim3 gfin(W_PAT / 128, S_CAM / 128);  // (8, 1024)
    tgemm<0><<<gfin, 256, SMEM_BYTES>>>(Hc, Hp, nullptr, nullptr, out, S_CAM, W_PAT, FEAT);
}

// round 5
// speedup vs baseline: 3.5769x; 1.0653x over previous
#include <cuda_runtime.h>
#include <cstdint>

// Problem constants
#define FEAT   224
#define NPAT   32
#define H_IMG  256
#define W_IMG  512
#define W_PAT  1024
#define S_CAM  (H_IMG * W_IMG)   // 131072
#define S_PROJ W_PAT             // 1024

// Scratch (device globals)
__device__ float g_P  [S_CAM * FEAT];
__device__ float g_X  [S_CAM * FEAT];
__device__ float g_Hc [S_CAM * FEAT];
__device__ float g_Hp [S_PROJ * FEAT];
__device__ float g_W0c[2 * FEAT * FEAT];
__device__ float g_W1c[2 * FEAT * FEAT];

// ---------------------------------------------------------------------------
// Helpers
// ---------------------------------------------------------------------------
__device__ __forceinline__ uint32_t smem_u32(const void* p) {
    uint32_t a;
    asm("{ .reg .u64 t; cvta.to.shared.u64 t, %1; cvt.u32.u64 %0, t; }"
        : "=r"(a) : "l"(p));
    return a;
}

__device__ __forceinline__ void cp16(uint32_t dst, const float* src) {
    asm volatile("cp.async.cg.shared.global [%0], [%1], 16;"
                 :: "r"(dst), "l"(src) : "memory");
}
__device__ __forceinline__ void cp_commit() {
    asm volatile("cp.async.commit_group;" ::: "memory");
}
__device__ __forceinline__ void cp_wait1() {
    asm volatile("cp.async.wait_group 1;" ::: "memory");
}

// Round fp32 to tf32 precision (RNA), keep as fp32 bit pattern (low 13 bits 0).
__device__ __forceinline__ float rndtf(float v) {
    uint32_t u;
    asm("cvt.rna.tf32.f32 %0, %1;" : "=r"(u) : "f"(v));
    return __uint_as_float(u);
}

// ---------------------------------------------------------------------------
// Cam neighbor expansion (writes rounded P only; layer-0 GEMM reads P)
// ---------------------------------------------------------------------------
__global__ void build_pcam(const float* __restrict__ cam, float* __restrict__ P) {
    int idx = blockIdx.x * blockDim.x + threadIdx.x;
    if (idx >= S_CAM * FEAT) return;
    int s = idx / FEAT;
    int f = idx - s * FEAT;
    int j = f / NPAT;
    int k = f - j * NPAT;
    int w = s & (W_IMG - 1);
    int h = s >> 9;
    int wc = w + j - 3;
    wc = wc < 0 ? 0 : (wc > W_IMG - 1 ? W_IMG - 1 : wc);
    P[idx] = rndtf(cam[(h * W_IMG + wc) * NPAT + k]);
}

// Round-copy weights into scratch (tf32-representable values)
__global__ void round_copy(const float* __restrict__ src, float* __restrict__ dst,
                           int n) {
    int i = blockIdx.x * blockDim.x + threadIdx.x;
    if (i < n) dst[i] = rndtf(src[i]);
}

// ---------------------------------------------------------------------------
// TF32 mma.sync GEMM, cp.async 3-stage pipeline + ldmatrix fragment loads.
// C[M,N] = epilogue(A[M,K] @ W[N,K]^T)
// MODE bit0: +bias; bit1: relu; bit2: +Res; bit3: round store to tf32.
// A, W contents must already be tf32-rounded (low mantissa bits zero).
// 128x128 tile, BK=32, 256 threads, 8 warps (2m x 4n), warp tile 64x32.
// ---------------------------------------------------------------------------
#define BK       32
#define ST_WORDS (128 * BK)
#define NSTAGE   3
#define SMEM_BYTES (NSTAGE * 2 * ST_WORDS * 4)   // 98304

template <int MODE>
__global__ void __launch_bounds__(256, 2)
tgemm(const float* __restrict__ A, const float* __restrict__ W,
      const float* __restrict__ bias, const float* __restrict__ Res,
      float* __restrict__ C, int M, int N, int K) {
    extern __shared__ float smf[];
    const uint32_t a_u32 = smem_u32(smf);
    const uint32_t b_u32 = a_u32 + NSTAGE * ST_WORDS * 4;

    const int t    = threadIdx.x;
    const int lane = t & 31;
    const int wid  = t >> 5;
    const int wm   = wid & 1;    // 64-row slab
    const int wn   = wid >> 1;   // 32-col slab
    const int n0   = blockIdx.x * 128;
    const int m0   = blockIdx.y * 128;
    const int nch  = K / BK;     // 7

    // --- cp.async loader mapping ---
    const int lrow = t >> 3;
    const int lchk = t & 7;
    const float* Asrc[4];
    const float* Bsrc[4];
    uint32_t Adst[4], Bdst[4];
#pragma unroll
    for (int i = 0; i < 4; i++) {
        int row = lrow + 32 * i;
        Asrc[i] = A + (size_t)(m0 + row) * K + lchk * 4;
        int br = n0 + row; if (br > N - 1) br = N - 1;
        Bsrc[i] = W + (size_t)br * K + lchk * 4;
        uint32_t dw = (uint32_t)row * BK + ((lchk ^ (row & 7)) << 2);
        Adst[i] = a_u32 + dw * 4;
        Bdst[i] = b_u32 + dw * 4;
    }

    // --- ldmatrix lane mapping ---
    // A (x4): lane L: matrix j=L>>3; row-in-tile = ((j&1)<<3) + (L&7); k-block bit = j>>1
    const int a_roff = (((lane >> 3) & 1) << 3) + (lane & 7);
    const int a_kb   = lane >> 4;           // 0/1
    // B (x2): lane L: row = L&7; k-block bit = (L>>3)&1
    const int b_roff = lane & 7;
    const int b_kb   = (lane >> 3) & 1;

    float c[4][4][4];
#pragma unroll
    for (int i = 0; i < 4; i++)
#pragma unroll
        for (int j = 0; j < 4; j++)
#pragma unroll
            for (int r = 0; r < 4; r++) c[i][j][r] = 0.0f;

    // --- prologue: stages 0,1 ---
#pragma unroll
    for (int s = 0; s < 2; s++) {
#pragma unroll
        for (int i = 0; i < 4; i++) {
            cp16(Adst[i] + s * ST_WORDS * 4, Asrc[i] + s * BK);
            cp16(Bdst[i] + s * ST_WORDS * 4, Bsrc[i] + s * BK);
        }
        cp_commit();
    }

    for (int ch = 0; ch < nch; ch++) {
        cp_wait1();
        __syncthreads();
        if (ch + 2 < nch) {
            const int sl = (ch + 2) % NSTAGE;
#pragma unroll
            for (int i = 0; i < 4; i++) {
                cp16(Adst[i] + sl * ST_WORDS * 4, Asrc[i] + (ch + 2) * BK);
                cp16(Bdst[i] + sl * ST_WORDS * 4, Bsrc[i] + (ch + 2) * BK);
            }
        }
        cp_commit();

        const uint32_t as_b = a_u32 + (ch % NSTAGE) * ST_WORDS * 4;
        const uint32_t bs_b = b_u32 + (ch % NSTAGE) * ST_WORDS * 4;

#pragma unroll
        for (int ks = 0; ks < 4; ks++) {
            uint32_t af[4][4];
#pragma unroll
            for (int mf = 0; mf < 4; mf++) {
                int row  = wm * 64 + mf * 16 + a_roff;
                int kblk = 2 * ks + a_kb;
                uint32_t addr = as_b + ((uint32_t)row * BK +
                                        (uint32_t)((kblk ^ (row & 7)) << 2)) * 4;
                asm volatile(
                    "ldmatrix.sync.aligned.m8n8.x4.shared.b16 {%0,%1,%2,%3}, [%4];"
                    : "=r"(af[mf][0]), "=r"(af[mf][1]),
                      "=r"(af[mf][2]), "=r"(af[mf][3])
                    : "r"(addr));
            }
            uint32_t bf[4][2];
#pragma unroll
            for (int nf = 0; nf < 4; nf++) {
                int row  = wn * 32 + nf * 8 + b_roff;
                int kblk = 2 * ks + b_kb;
                uint32_t addr = bs_b + ((uint32_t)row * BK +
                                        (uint32_t)((kblk ^ (row & 7)) << 2)) * 4;
                asm volatile(
                    "ldmatrix.sync.aligned.m8n8.x2.shared.b16 {%0,%1}, [%2];"
                    : "=r"(bf[nf][0]), "=r"(bf[nf][1])
                    : "r"(addr));
            }
#pragma unroll
            for (int mf = 0; mf < 4; mf++)
#pragma unroll
                for (int nf = 0; nf < 4; nf++) {
                    asm volatile(
                        "mma.sync.aligned.m16n8k8.row.col.f32.tf32.tf32.f32 "
                        "{%0,%1,%2,%3}, {%4,%5,%6,%7}, {%8,%9}, {%0,%1,%2,%3};"
                        : "+f"(c[mf][nf][0]), "+f"(c[mf][nf][1]),
                          "+f"(c[mf][nf][2]), "+f"(c[mf][nf][3])
                        : "r"(af[mf][0]), "r"(af[mf][1]),
                          "r"(af[mf][2]), "r"(af[mf][3]),
                          "r"(bf[nf][0]), "r"(bf[nf][1]));
                }
        }
        __syncthreads();
    }

    const int lq = lane >> 2;
    const int lr = lane & 3;
    // --- epilogue ---
#pragma unroll
    for (int mf = 0; mf < 4; mf++) {
        int row = m0 + wm * 64 + mf * 16 + lq;
#pragma unroll
        for (int nf = 0; nf < 4; nf++) {
            int col = n0 + wn * 32 + nf * 8 + lr * 2;
            if (col < N) {
                float b0 = 0.f, b1 = 0.f;
                if (MODE & 1) { b0 = bias[col]; b1 = bias[col + 1]; }
#pragma unroll
                for (int half = 0; half < 2; half++) {
                    int r = row + half * 8;
                    float v0 = c[mf][nf][half * 2 + 0];
                    float v1 = c[mf][nf][half * 2 + 1];
                    if (MODE & 1) { v0 += b0; v1 += b1; }
                    if (MODE & 2) { v0 = fmaxf(v0, 0.f); v1 = fmaxf(v1, 0.f); }
                    size_t o = (size_t)r * N + col;
                    if (MODE & 4) {
                        float2 rv = *(const float2*)(Res + o);
                        v0 += rv.x; v1 += rv.y;
                    }
                    if (MODE & 8) { v0 = rndtf(v0); v1 = rndtf(v1); }
                    *(float2*)(C + o) = make_float2(v0, v1);
                }
            }
        }
    }
}

// ---------------------------------------------------------------------------
// Fused projector pipeline: build + 2 residual MLP layers + normalize.
// 64 CTAs x 16 rows, fp32, all intermediates in smem.
// Smem (words, stride 225 per row): Xs@0, Ps@3600, Hs@7200, Wt@10800 (32x225)
// ---------------------------------------------------------------------------
#define PR_ROWS  16
#define XS_S     225
#define PROJ_SMEM ((3 * PR_ROWS * XS_S + 32 * XS_S) * 4)   // 72000 B

__global__ void __launch_bounds__(256)
proj_fused(const float* __restrict__ proj,
           const float* __restrict__ w0g, const float* __restrict__ b0g,
           const float* __restrict__ w1g, const float* __restrict__ b1g,
           float* __restrict__ Bnorm) {
    extern __shared__ float smf[];
    float* Xs = smf;
    float* Ps = smf + PR_ROWS * XS_S;
    float* Hs = smf + 2 * PR_ROWS * XS_S;
    float* Wt = smf + 3 * PR_ROWS * XS_S;

    const int t  = threadIdx.x;
    const int m0 = blockIdx.x * PR_ROWS;

    // Build p_proj^T slice
    for (int i = t; i < PR_ROWS * FEAT; i += 256) {
        int r = i / FEAT, f = i - r * FEAT;
        int j = f >> 5, k = f & 31;
        int mp = m0 + r + j - 3;
        mp = mp < 0 ? 0 : (mp > W_PAT - 1 ? W_PAT - 1 : mp);
        float v = proj[k * W_PAT + mp];
        Xs[r * XS_S + f] = v;
        Ps[r * XS_S + f] = v;
    }
    __syncthreads();

    const int r  = t >> 4;   // 0..15
    const int nl = t & 15;   // 0..15

    for (int l = 0; l < 2; l++) {
        const float* w0 = w0g + (size_t)l * FEAT * FEAT;
        const float* b0 = b0g + (size_t)l * FEAT;
        const float* w1 = w1g + (size_t)l * FEAT * FEAT;
        const float* b1 = b1g + (size_t)l * FEAT;

        // H = relu(X @ W0^T + b0)
        for (int nb = 0; nb < 7; nb++) {
            for (int i = t; i < 32 * FEAT; i += 256) {
                int n = i / FEAT, k = i - n * FEAT;
                Wt[n * XS_S + k] = w0[(size_t)(nb * 32 + n) * FEAT + k];
            }
            __syncthreads();
            float a0 = 0.f, a1 = 0.f;
            const float* xr = Xs + r * XS_S;
#pragma unroll 8
            for (int k = 0; k < FEAT; k++) {
                float xv = xr[k];
                a0 += xv * Wt[nl * XS_S + k];
                a1 += xv * Wt[(nl + 16) * XS_S + k];
            }
            int ng = nb * 32;
            Hs[r * XS_S + ng + nl]      = fmaxf(a0 + b0[ng + nl], 0.f);
            Hs[r * XS_S + ng + nl + 16] = fmaxf(a1 + b0[ng + nl + 16], 0.f);
            __syncthreads();
        }
        // X += H @ W1^T + b1
        for (int nb = 0; nb < 7; nb++) {
            for (int i = t; i < 32 * FEAT; i += 256) {
                int n = i / FEAT, k = i - n * FEAT;
                Wt[n * XS_S + k] = w1[(size_t)(nb * 32 + n) * FEAT + k];
            }
            __syncthreads();
            float a0 = 0.f, a1 = 0.f;
            const float* hr = Hs + r * XS_S;
#pragma unroll 8
            for (int k = 0; k < FEAT; k++) {
                float hv = hr[k];
                a0 += hv * Wt[nl * XS_S + k];
                a1 += hv * Wt[(nl + 16) * XS_S + k];
            }
            int ng = nb * 32;
            Xs[r * XS_S + ng + nl]      += a0 + b1[ng + nl];
            Xs[r * XS_S + ng + nl + 16] += a1 + b1[ng + nl + 16];
            __syncthreads();
        }
    }

    // Normalize rows of (X + P): 8 warps x 2 rows
    const int wrp  = t >> 5;
    const int lane = t & 31;
    for (int rr = wrp * 2; rr < wrp * 2 + 2; rr++) {
        float sum = 0.f;
        for (int i = lane; i < FEAT; i += 32) {
            float y = Xs[rr * XS_S + i] + Ps[rr * XS_S + i];
            Hs[rr * XS_S + i] = y;
            sum += y;
        }
#pragma unroll
        for (int o = 16; o > 0; o >>= 1) sum += __shfl_xor_sync(0xffffffffu, sum, o);
        float mean = sum * (1.0f / FEAT);
        float sq = 0.f;
        for (int i = lane; i < FEAT; i += 32) {
            float y = Hs[rr * XS_S + i] - mean;
            sq += y * y;
        }
#pragma unroll
        for (int o = 16; o > 0; o >>= 1) sq += __shfl_xor_sync(0xffffffffu, sq, o);
        float inv = rsqrtf(sq);
        for (int i = lane; i < FEAT; i += 32)
            Bnorm[(size_t)(m0 + rr) * FEAT + i] =
                rndtf((Hs[rr * XS_S + i] - mean) * inv);
    }
}

// ---------------------------------------------------------------------------
// Per-row zero-mean + unit-norm of (X + P), one warp per row (cam side).
// ---------------------------------------------------------------------------
__global__ void normalize_rows(const float* __restrict__ X,
                               const float* __restrict__ P,
                               float* __restrict__ Out, int M) {
    int warp = (blockIdx.x * blockDim.x + threadIdx.x) >> 5;
    int lane = threadIdx.x & 31;
    if (warp >= M) return;
    size_t base = (size_t)warp * FEAT;
    float y[7];
    float sum = 0.f;
#pragma unroll
    for (int i = 0; i < 7; i++) {
        int o = lane + i * 32;
        y[i] = X[base + o] + P[base + o];
        sum += y[i];
    }
#pragma unroll
    for (int o = 16; o > 0; o >>= 1) sum += __shfl_xor_sync(0xffffffffu, sum, o);
    float mean = sum * (1.0f / FEAT);
    float sq = 0.f;
#pragma unroll
    for (int i = 0; i < 7; i++) {
        y[i] -= mean;
        sq += y[i] * y[i];
    }
#pragma unroll
    for (int o = 16; o > 0; o >>= 1) sq += __shfl_xor_sync(0xffffffffu, sq, o);
    float inv = rsqrtf(sq);
#pragma unroll
    for (int i = 0; i < 7; i++) Out[base + lane + i * 32] = rndtf(y[i] * inv);
}

// ---------------------------------------------------------------------------
extern "C" void kernel_launch(void* const* d_in, const int* in_sizes, int n_in,
                              void* d_out, int out_size) {
    const float* cam_code  = (const float*)d_in[0];
    const float* proj_code = (const float*)d_in[1];
    const float* cam_w0 = (const float*)d_in[2];
    const float* cam_b0 = (const float*)d_in[3];
    const float* cam_w1 = (const float*)d_in[4];
    const float* cam_b1 = (const float*)d_in[5];
    const float* proj_w0 = (const float*)d_in[6];
    const float* proj_b0 = (const float*)d_in[7];
    const float* proj_w1 = (const float*)d_in[8];
    const float* proj_b1 = (const float*)d_in[9];
    float* out = (float*)d_out;

    float *P, *X, *Hc, *Hp, *W0c, *W1c;
    cudaGetSymbolAddress((void**)&P,   g_P);
    cudaGetSymbolAddress((void**)&X,   g_X);
    cudaGetSymbolAddress((void**)&Hc,  g_Hc);
    cudaGetSymbolAddress((void**)&Hp,  g_Hp);
    cudaGetSymbolAddress((void**)&W0c, g_W0c);
    cudaGetSymbolAddress((void**)&W1c, g_W1c);

    cudaFuncSetAttribute(tgemm<11>, cudaFuncAttributeMaxDynamicSharedMemorySize, SMEM_BYTES);
    cudaFuncSetAttribute(tgemm<13>, cudaFuncAttributeMaxDynamicSharedMemorySize, SMEM_BYTES);
    cudaFuncSetAttribute(tgemm<0>,  cudaFuncAttributeMaxDynamicSharedMemorySize, SMEM_BYTES);
    cudaFuncSetAttribute(proj_fused, cudaFuncAttributeMaxDynamicSharedMemorySize, PROJ_SMEM);

    const int NW = 2 * FEAT * FEAT;

    // 1) Preprocessing: rounded weights, cam expansion, full proj pipeline
    round_copy<<<(NW + 255) / 256, 256>>>(cam_w0, W0c, NW);
    round_copy<<<(NW + 255) / 256, 256>>>(cam_w1, W1c, NW);
    build_pcam<<<(S_CAM * FEAT + 255) / 256, 256>>>(cam_code, P);
    proj_fused<<<S_PROJ / PR_ROWS, 256, PROJ_SMEM>>>(
        proj_code, proj_w0, proj_b0, proj_w1, proj_b1, Hp);

    // 2) Cam residual MLP blocks
    dim3 gcam((FEAT + 127) / 128, S_CAM / 128);   // (2, 1024)
    {
        // layer 0 (A = P)
        tgemm<11><<<gcam, 256, SMEM_BYTES>>>(P,  W0c, cam_b0, nullptr, Hc, S_CAM, FEAT, FEAT);
        tgemm<13><<<gcam, 256, SMEM_BYTES>>>(Hc, W1c, cam_b1, P,       X,  S_CAM, FEAT, FEAT);
        // layer 1
        const float* w0 = W0c + (size_t)FEAT * FEAT;
        const float* w1 = W1c + (size_t)FEAT * FEAT;
        const float* b0 = cam_b0 + FEAT;
        const float* b1 = cam_b1 + FEAT;
        tgemm<11><<<gcam, 256, SMEM_BYTES>>>(X,  w0, b0, nullptr, Hc, S_CAM, FEAT, FEAT);
        tgemm<13><<<gcam, 256, SMEM_BYTES>>>(Hc, w1, b1, X,       X,  S_CAM, FEAT, FEAT);
    }

    // 3) Cam normalize (Anorm -> Hc)
    normalize_rows<<<(S_CAM + 7) / 8, 256>>>(X, P, Hc, S_CAM);

    // 4) ZNCC correlation
    dim3 gfin(W_PAT / 128, S_CAM / 128);  // (8, 1024)
    tgemm<0><<<gfin, 256, SMEM_BYTES>>>(Hc, Hp, nullptr, nullptr, out, S_CAM, W_PAT, FEAT);
}

// round 6
// speedup vs baseline: 4.1969x; 1.1733x over previous
#include <cuda_runtime.h>
#include <cstdint>

// Problem constants
#define FEAT   224
#define NPAT   32
#define H_IMG  256
#define W_IMG  512
#define W_PAT  1024
#define S_CAM  (H_IMG * W_IMG)   // 131072
#define S_PROJ W_PAT             // 1024
#define F2     (FEAT * FEAT)

// Scratch (device globals)
__device__ float g_P  [S_CAM * FEAT];   // cam p (tf32-rounded)
__device__ float g_X  [S_CAM * FEAT];   // cam running x / final Y
__device__ float g_Hc [S_CAM * FEAT];   // cam hidden
__device__ float g_inv[S_CAM];          // cam row scale
__device__ float g_Pp [S_PROJ * FEAT];  // proj p
__device__ float g_Xp [S_PROJ * FEAT];  // proj running x / Yp
__device__ float g_Hp [S_PROJ * FEAT];  // proj hidden / Bnorm
__device__ float g_W0c[2 * F2];
__device__ float g_W1c[2 * F2];
__device__ float g_W0p[2 * F2];
__device__ float g_W1p[2 * F2];

// ---------------------------------------------------------------------------
// Helpers
// ---------------------------------------------------------------------------
__device__ __forceinline__ uint32_t smem_u32(const void* p) {
    uint32_t a;
    asm("{ .reg .u64 t; cvta.to.shared.u64 t, %1; cvt.u32.u64 %0, t; }"
        : "=r"(a) : "l"(p));
    return a;
}
__device__ __forceinline__ void cp16(uint32_t dst, const float* src) {
    asm volatile("cp.async.cg.shared.global [%0], [%1], 16;"
                 :: "r"(dst), "l"(src) : "memory");
}
__device__ __forceinline__ void cp_commit() {
    asm volatile("cp.async.commit_group;" ::: "memory");
}
__device__ __forceinline__ void cp_wait1() {
    asm volatile("cp.async.wait_group 1;" ::: "memory");
}
__device__ __forceinline__ float rndtf(float v) {
    uint32_t u;
    asm("cvt.rna.tf32.f32 %0, %1;" : "=r"(u) : "f"(v));
    return __uint_as_float(u);
}

// ---------------------------------------------------------------------------
// Preprocessing kernels
// ---------------------------------------------------------------------------
__global__ void build_pcam(const float* __restrict__ cam, float* __restrict__ P) {
    int idx = blockIdx.x * blockDim.x + threadIdx.x;
    if (idx >= S_CAM * FEAT) return;
    int s = idx / FEAT;
    int f = idx - s * FEAT;
    int j = f / NPAT;
    int k = f - j * NPAT;
    int w = s & (W_IMG - 1);
    int h = s >> 9;
    int wc = w + j - 3;
    wc = wc < 0 ? 0 : (wc > W_IMG - 1 ? W_IMG - 1 : wc);
    P[idx] = rndtf(cam[(h * W_IMG + wc) * NPAT + k]);
}

__global__ void build_pproj(const float* __restrict__ proj, float* __restrict__ P) {
    int idx = blockIdx.x * blockDim.x + threadIdx.x;
    if (idx >= S_PROJ * FEAT) return;
    int m = idx / FEAT;
    int f = idx - m * FEAT;
    int j = f / NPAT;
    int k = f - j * NPAT;
    int mp = m + j - 3;
    mp = mp < 0 ? 0 : (mp > W_PAT - 1 ? W_PAT - 1 : mp);
    P[idx] = rndtf(proj[k * W_PAT + mp]);
}

// Round-copy all four weight tensors in one launch (each 2*F2 elements).
__global__ void round_weights(const float* __restrict__ s0, float* __restrict__ d0,
                              const float* __restrict__ s1, float* __restrict__ d1,
                              const float* __restrict__ s2, float* __restrict__ d2,
                              const float* __restrict__ s3, float* __restrict__ d3) {
    int i = blockIdx.x * blockDim.x + threadIdx.x;
    if (i >= 2 * F2) return;
    d0[i] = rndtf(s0[i]);
    d1[i] = rndtf(s1[i]);
    d2[i] = rndtf(s2[i]);
    d3[i] = rndtf(s3[i]);
}

// ---------------------------------------------------------------------------
// TF32 mma.sync GEMM, cp.async 3-stage pipeline + ldmatrix.
// Two independent argument sets (cam region + proj region) share one grid:
// blockIdx.y < a0.M/128 -> a0, else a1. C = epilogue(A @ W^T).
// MODE bits: 1 +bias, 2 relu, 4 +Res, 8 tf32-round store, 16 +Res2,
//            32 *rowscale[row].
// ---------------------------------------------------------------------------
#define BK       32
#define ST_WORDS (128 * BK)
#define NSTAGE   3
#define SMEM_BYTES (NSTAGE * 2 * ST_WORDS * 4)   // 98304

struct GArg {
    const float *A, *W, *bias, *Res, *Res2;
    float *C;
    int M, N;
};

template <int MODE>
__global__ void __launch_bounds__(256, 2)
tgemm(GArg a0, GArg a1, const float* __restrict__ rowscale, int K) {
    extern __shared__ float smf[];
    const uint32_t a_u32 = smem_u32(smf);
    const uint32_t b_u32 = a_u32 + NSTAGE * ST_WORDS * 4;

    const int t    = threadIdx.x;
    const int lane = t & 31;
    const int wid  = t >> 5;
    const int wm   = wid & 1;    // 64-row slab
    const int wn   = wid >> 1;   // 32-col slab
    const int n0   = blockIdx.x * 128;
    const int nch  = K / BK;     // 7

    const int tiles0 = a0.M >> 7;
    GArg g;
    int m0;
    if ((int)blockIdx.y < tiles0) { g = a0; m0 = blockIdx.y * 128; }
    else                          { g = a1; m0 = (blockIdx.y - tiles0) * 128; }
    const int N = g.N;

    // --- cp.async loader mapping ---
    const int lrow = t >> 3;
    const int lchk = t & 7;
    const float* Asrc[4];
    const float* Bsrc[4];
    uint32_t Adst[4], Bdst[4];
#pragma unroll
    for (int i = 0; i < 4; i++) {
        int row = lrow + 32 * i;
        Asrc[i] = g.A + (size_t)(m0 + row) * K + lchk * 4;
        int br = n0 + row; if (br > N - 1) br = N - 1;
        Bsrc[i] = g.W + (size_t)br * K + lchk * 4;
        uint32_t dw = (uint32_t)row * BK + ((lchk ^ (row & 7)) << 2);
        Adst[i] = a_u32 + dw * 4;
        Bdst[i] = b_u32 + dw * 4;
    }

    // --- ldmatrix lane mappings ---
    const int a_roff = (((lane >> 3) & 1) << 3) + (lane & 7);
    const int a_kb   = lane >> 4;                       // 0/1
    const int b_roff = ((lane >> 4) << 3) + (lane & 7); // x4-packed B
    const int b_kb   = (lane >> 3) & 1;

    float c[4][4][4];
#pragma unroll
    for (int i = 0; i < 4; i++)
#pragma unroll
        for (int j = 0; j < 4; j++)
#pragma unroll
            for (int r = 0; r < 4; r++) c[i][j][r] = 0.0f;

    // --- prologue: stages 0,1 ---
#pragma unroll
    for (int s = 0; s < 2; s++) {
#pragma unroll
        for (int i = 0; i < 4; i++) {
            cp16(Adst[i] + s * ST_WORDS * 4, Asrc[i] + s * BK);
            cp16(Bdst[i] + s * ST_WORDS * 4, Bsrc[i] + s * BK);
        }
        cp_commit();
    }

    for (int ch = 0; ch < nch; ch++) {
        cp_wait1();
        __syncthreads();
        if (ch + 2 < nch) {
            const int sl = (ch + 2) % NSTAGE;
#pragma unroll
            for (int i = 0; i < 4; i++) {
                cp16(Adst[i] + sl * ST_WORDS * 4, Asrc[i] + (ch + 2) * BK);
                cp16(Bdst[i] + sl * ST_WORDS * 4, Bsrc[i] + (ch + 2) * BK);
            }
        }
        cp_commit();

        const uint32_t as_b = a_u32 + (ch % NSTAGE) * ST_WORDS * 4;
        const uint32_t bs_b = b_u32 + (ch % NSTAGE) * ST_WORDS * 4;

#pragma unroll
        for (int ks = 0; ks < 4; ks++) {
            uint32_t af[4][4];
#pragma unroll
            for (int mf = 0; mf < 4; mf++) {
                int row  = wm * 64 + mf * 16 + a_roff;
                int kblk = 2 * ks + a_kb;
                uint32_t addr = as_b + ((uint32_t)row * BK +
                                        (uint32_t)((kblk ^ (row & 7)) << 2)) * 4;
                asm volatile(
                    "ldmatrix.sync.aligned.m8n8.x4.shared.b16 {%0,%1,%2,%3}, [%4];"
                    : "=r"(af[mf][0]), "=r"(af[mf][1]),
                      "=r"(af[mf][2]), "=r"(af[mf][3])
                    : "r"(addr));
            }
            uint32_t bf[4][2];
#pragma unroll
            for (int p = 0; p < 2; p++) {
                int row  = wn * 32 + p * 16 + b_roff;
                int kblk = 2 * ks + b_kb;
                uint32_t addr = bs_b + ((uint32_t)row * BK +
                                        (uint32_t)((kblk ^ (row & 7)) << 2)) * 4;
                asm volatile(
                    "ldmatrix.sync.aligned.m8n8.x4.shared.b16 {%0,%1,%2,%3}, [%4];"
                    : "=r"(bf[2 * p][0]), "=r"(bf[2 * p][1]),
                      "=r"(bf[2 * p + 1][0]), "=r"(bf[2 * p + 1][1])
                    : "r"(addr));
            }
#pragma unroll
            for (int mf = 0; mf < 4; mf++)
#pragma unroll
                for (int nf = 0; nf < 4; nf++) {
                    asm volatile(
                        "mma.sync.aligned.m16n8k8.row.col.f32.tf32.tf32.f32 "
                        "{%0,%1,%2,%3}, {%4,%5,%6,%7}, {%8,%9}, {%0,%1,%2,%3};"
                        : "+f"(c[mf][nf][0]), "+f"(c[mf][nf][1]),
                          "+f"(c[mf][nf][2]), "+f"(c[mf][nf][3])
                        : "r"(af[mf][0]), "r"(af[mf][1]),
                          "r"(af[mf][2]), "r"(af[mf][3]),
                          "r"(bf[nf][0]), "r"(bf[nf][1]));
                }
        }
        __syncthreads();
    }

    const int lq = lane >> 2;
    const int lr = lane & 3;
    // --- epilogue ---
#pragma unroll
    for (int mf = 0; mf < 4; mf++) {
        int row = m0 + wm * 64 + mf * 16 + lq;
        float s0 = 1.f, s1 = 1.f;
        if (MODE & 32) { s0 = rowscale[row]; s1 = rowscale[row + 8]; }
#pragma unroll
        for (int nf = 0; nf < 4; nf++) {
            int col = n0 + wn * 32 + nf * 8 + lr * 2;
            if (col < N) {
                float b0 = 0.f, b1 = 0.f;
                if (MODE & 1) { b0 = g.bias[col]; b1 = g.bias[col + 1]; }
#pragma unroll
                for (int half = 0; half < 2; half++) {
                    int r = row + half * 8;
                    float v0 = c[mf][nf][half * 2 + 0];
                    float v1 = c[mf][nf][half * 2 + 1];
                    if (MODE & 1) { v0 += b0; v1 += b1; }
                    if (MODE & 2) { v0 = fmaxf(v0, 0.f); v1 = fmaxf(v1, 0.f); }
                    size_t o = (size_t)r * N + col;
                    if (MODE & 4) {
                        float2 rv = *(const float2*)(g.Res + o);
                        v0 += rv.x; v1 += rv.y;
                    }
                    if (MODE & 16) {
                        float2 rv = *(const float2*)(g.Res2 + o);
                        v0 += rv.x; v1 += rv.y;
                    }
                    if (MODE & 32) {
                        float s = half ? s1 : s0;
                        v0 *= s; v1 *= s;
                    }
                    if (MODE & 8) { v0 = rndtf(v0); v1 = rndtf(v1); }
                    *(float2*)(g.C + o) = make_float2(v0, v1);
                }
            }
        }
    }
}

// ---------------------------------------------------------------------------
// Cam row statistics: inv[s] = 1 / ||Y[s,:] - mean(Y[s,:])||   (one warp/row)
// ---------------------------------------------------------------------------
__global__ void rowstat(const float* __restrict__ Y, float* __restrict__ inv,
                        int M) {
    int warp = (blockIdx.x * blockDim.x + threadIdx.x) >> 5;
    int lane = threadIdx.x & 31;
    if (warp >= M) return;
    size_t base = (size_t)warp * FEAT;
    float sum = 0.f, sq = 0.f;
#pragma unroll
    for (int i = 0; i < 7; i++) {
        float y = Y[base + lane + i * 32];
        sum += y;
        sq  += y * y;
    }
#pragma unroll
    for (int o = 16; o > 0; o >>= 1) {
        sum += __shfl_xor_sync(0xffffffffu, sum, o);
        sq  += __shfl_xor_sync(0xffffffffu, sq,  o);
    }
    if (lane == 0) inv[warp] = rsqrtf(sq - sum * sum * (1.0f / FEAT));
}

// ---------------------------------------------------------------------------
// Proj normalize: Bnorm[m,:] = (Y[m,:] - mean) / ||Y - mean||  (tf32-rounded)
// ---------------------------------------------------------------------------
__global__ void normalize_proj(const float* __restrict__ Y,
                               float* __restrict__ Out, int M) {
    int warp = (blockIdx.x * blockDim.x + threadIdx.x) >> 5;
    int lane = threadIdx.x & 31;
    if (warp >= M) return;
    size_t base = (size_t)warp * FEAT;
    float y[7];
    float sum = 0.f;
#pragma unroll
    for (int i = 0; i < 7; i++) {
        y[i] = Y[base + lane + i * 32];
        sum += y[i];
    }
#pragma unroll
    for (int o = 16; o > 0; o >>= 1) sum += __shfl_xor_sync(0xffffffffu, sum, o);
    float mean = sum * (1.0f / FEAT);
    float sq = 0.f;
#pragma unroll
    for (int i = 0; i < 7; i++) {
        y[i] -= mean;
        sq += y[i] * y[i];
    }
#pragma unroll
    for (int o = 16; o > 0; o >>= 1) sq += __shfl_xor_sync(0xffffffffu, sq, o);
    float inv = rsqrtf(sq);
#pragma unroll
    for (int i = 0; i < 7; i++)
        Out[base + lane + i * 32] = rndtf(y[i] * inv);
}

// ---------------------------------------------------------------------------
extern "C" void kernel_launch(void* const* d_in, const int* in_sizes, int n_in,
                              void* d_out, int out_size) {
    const float* cam_code  = (const float*)d_in[0];
    const float* proj_code = (const float*)d_in[1];
    const float* cam_w0 = (const float*)d_in[2];
    const float* cam_b0 = (const float*)d_in[3];
    const float* cam_w1 = (const float*)d_in[4];
    const float* cam_b1 = (const float*)d_in[5];
    const float* proj_w0 = (const float*)d_in[6];
    const float* proj_b0 = (const float*)d_in[7];
    const float* proj_w1 = (const float*)d_in[8];
    const float* proj_b1 = (const float*)d_in[9];
    float* out = (float*)d_out;

    float *P, *X, *Hc, *INV, *Pp, *Xp, *Hp, *W0c, *W1c, *W0p, *W1p;
    cudaGetSymbolAddress((void**)&P,   g_P);
    cudaGetSymbolAddress((void**)&X,   g_X);
    cudaGetSymbolAddress((void**)&Hc,  g_Hc);
    cudaGetSymbolAddress((void**)&INV, g_inv);
    cudaGetSymbolAddress((void**)&Pp,  g_Pp);
    cudaGetSymbolAddress((void**)&Xp,  g_Xp);
    cudaGetSymbolAddress((void**)&Hp,  g_Hp);
    cudaGetSymbolAddress((void**)&W0c, g_W0c);
    cudaGetSymbolAddress((void**)&W1c, g_W1c);
    cudaGetSymbolAddress((void**)&W0p, g_W0p);
    cudaGetSymbolAddress((void**)&W1p, g_W1p);

    cudaFuncSetAttribute(tgemm<11>, cudaFuncAttributeMaxDynamicSharedMemorySize, SMEM_BYTES);
    cudaFuncSetAttribute(tgemm<13>, cudaFuncAttributeMaxDynamicSharedMemorySize, SMEM_BYTES);
    cudaFuncSetAttribute(tgemm<29>, cudaFuncAttributeMaxDynamicSharedMemorySize, SMEM_BYTES);
    cudaFuncSetAttribute(tgemm<32>, cudaFuncAttributeMaxDynamicSharedMemorySize, SMEM_BYTES);

    // 1) Preprocessing
    round_weights<<<(2 * F2 + 255) / 256, 256>>>(cam_w0, W0c, cam_w1, W1c,
                                                 proj_w0, W0p, proj_w1, W1p);
    build_pcam <<<(S_CAM  * FEAT + 255) / 256, 256>>>(cam_code,  P);
    build_pproj<<<(S_PROJ * FEAT + 255) / 256, 256>>>(proj_code, Pp);

    // 2) Residual MLP blocks: cam tiles + proj tiles share one grid
    const int TC = S_CAM / 128;   // 1024
    const int TP = S_PROJ / 128;  // 8
    dim3 gmlp((FEAT + 127) / 128, TC + TP);   // (2, 1032)

    GArg c0, p0;
    // layer 0, GEMM 0: H = relu(P @ W0^T + b0)
    c0 = {P,  W0c, cam_b0,  nullptr, nullptr, Hc, S_CAM,  FEAT};
    p0 = {Pp, W0p, proj_b0, nullptr, nullptr, Hp, S_PROJ, FEAT};
    tgemm<11><<<gmlp, 256, SMEM_BYTES>>>(c0, p0, nullptr, FEAT);
    // layer 0, GEMM 1: X = P + H @ W1^T + b1
    c0 = {Hc, W1c, cam_b1,  P,  nullptr, X,  S_CAM,  FEAT};
    p0 = {Hp, W1p, proj_b1, Pp, nullptr, Xp, S_PROJ, FEAT};
    tgemm<13><<<gmlp, 256, SMEM_BYTES>>>(c0, p0, nullptr, FEAT);
    // layer 1, GEMM 0
    c0 = {X,  W0c + F2, cam_b0 + FEAT,  nullptr, nullptr, Hc, S_CAM,  FEAT};
    p0 = {Xp, W0p + F2, proj_b0 + FEAT, nullptr, nullptr, Hp, S_PROJ, FEAT};
    tgemm<11><<<gmlp, 256, SMEM_BYTES>>>(c0, p0, nullptr, FEAT);
    // layer 1, GEMM 1 (+ second residual P -> writes Y directly)
    c0 = {Hc, W1c + F2, cam_b1 + FEAT,  X,  P,  X,  S_CAM,  FEAT};
    p0 = {Hp, W1p + F2, proj_b1 + FEAT, Xp, Pp, Xp, S_PROJ, FEAT};
    tgemm<29><<<gmlp, 256, SMEM_BYTES>>>(c0, p0, nullptr, FEAT);

    // 3) Row stats (cam) + full normalize (proj)
    rowstat       <<<(S_CAM  + 7) / 8, 256>>>(X,  INV, S_CAM);
    normalize_proj<<<(S_PROJ + 7) / 8, 256>>>(Xp, Hp,  S_PROJ);

    // 4) ZNCC correlation: out[s,m] = inv_a[s] * (Y[s,:] . Bnorm[m,:])
    dim3 gfin(W_PAT / 128, TC);  // (8, 1024)
    GArg f0 = {X, Hp, nullptr, nullptr, nullptr, out, S_CAM, W_PAT};
    tgemm<32><<<gfin, 256, SMEM_BYTES>>>(f0, f0, INV, FEAT);
}

// round 7
// speedup vs baseline: 4.5122x; 1.0751x over previous
#include <cuda_runtime.h>
#include <cstdint>

// Problem constants
#define FEAT   224
#define NPAT   32
#define H_IMG  256
#define W_IMG  512
#define W_PAT  1024
#define S_CAM  (H_IMG * W_IMG)   // 131072
#define S_PROJ W_PAT             // 1024
#define F2     (FEAT * FEAT)

// Scratch (device globals)
__device__ float g_X    [S_CAM * FEAT];   // cam running x / final Y
__device__ float g_Hc   [S_CAM * FEAT];   // cam hidden
__device__ float g_stats[S_CAM * 4];      // per-row {s,q} x 2 N-tiles
__device__ float g_Pp   [S_PROJ * FEAT];  // proj p
__device__ float g_Xp   [S_PROJ * FEAT];  // proj running x / Yp
__device__ float g_Hp   [S_PROJ * FEAT];  // proj hidden / Bnorm
__device__ float g_W0c  [2 * F2];
__device__ float g_W1c  [2 * F2];
__device__ float g_W0p  [2 * F2];
__device__ float g_W1p  [2 * F2];

// ---------------------------------------------------------------------------
// Helpers
// ---------------------------------------------------------------------------
__device__ __forceinline__ uint32_t smem_u32(const void* p) {
    uint32_t a;
    asm("{ .reg .u64 t; cvta.to.shared.u64 t, %1; cvt.u32.u64 %0, t; }"
        : "=r"(a) : "l"(p));
    return a;
}
__device__ __forceinline__ void cp16(uint32_t dst, const float* src) {
    asm volatile("cp.async.cg.shared.global [%0], [%1], 16;"
                 :: "r"(dst), "l"(src) : "memory");
}
__device__ __forceinline__ void cp_commit() {
    asm volatile("cp.async.commit_group;" ::: "memory");
}
__device__ __forceinline__ void cp_wait1() {
    asm volatile("cp.async.wait_group 1;" ::: "memory");
}
__device__ __forceinline__ float rndtf(float v) {
    uint32_t u;
    asm("cvt.rna.tf32.f32 %0, %1;" : "=r"(u) : "f"(v));
    return __uint_as_float(u);
}
__device__ __forceinline__ uint32_t rndtf_u(uint32_t v) {
    uint32_t u;
    asm("cvt.rna.tf32.f32 %0, %1;" : "=r"(u) : "f"(__uint_as_float(v)));
    return u;
}

// ---------------------------------------------------------------------------
// Preprocessing kernels
// ---------------------------------------------------------------------------
__global__ void build_pproj(const float* __restrict__ proj, float* __restrict__ P) {
    int idx = blockIdx.x * blockDim.x + threadIdx.x;
    if (idx >= S_PROJ * FEAT) return;
    int m = idx / FEAT;
    int f = idx - m * FEAT;
    int j = f / NPAT;
    int k = f - j * NPAT;
    int mp = m + j - 3;
    mp = mp < 0 ? 0 : (mp > W_PAT - 1 ? W_PAT - 1 : mp);
    P[idx] = rndtf(proj[k * W_PAT + mp]);
}

__global__ void round_weights(const float* __restrict__ s0, float* __restrict__ d0,
                              const float* __restrict__ s1, float* __restrict__ d1,
                              const float* __restrict__ s2, float* __restrict__ d2,
                              const float* __restrict__ s3, float* __restrict__ d3) {
    int i = blockIdx.x * blockDim.x + threadIdx.x;
    if (i >= 2 * F2) return;
    d0[i] = rndtf(s0[i]);
    d1[i] = rndtf(s1[i]);
    d2[i] = rndtf(s2[i]);
    d3[i] = rndtf(s3[i]);
}

// ---------------------------------------------------------------------------
// TF32 mma.sync GEMM, cp.async 3-stage pipeline + ldmatrix.
// Two argument sets (cam region, proj region) share one grid.
// MODE bits: 1 +bias, 2 relu, 4 +Res, 8 tf32-round store, 16 +Res2,
//            32 row-scale from stats (final), 64 cvt.rna on A fragments,
//            128 emit per-row (sum,sq) partial stats.
// Runtime GArg flags: agather / resgather / res2gather = fetch from cam_code
// with neighbor-clamp instead of a materialized tensor (chunk == j group).
// ---------------------------------------------------------------------------
#define BK       32
#define ST_WORDS (128 * BK)
#define NSTAGE   3
#define STAT_OFF (NSTAGE * 2 * ST_WORDS)              // float index of stat buf
#define SMEM_BYTES (STAT_OFF * 4 + 1024)              // 99328

struct GArg {
    const float *A, *W, *bias, *Res, *Res2;
    float *C;
    float *stats;           // per-row partial stats out (nullptr = skip)
    const float *cam;       // gather source
    int M, N;
    int agather, resgather, res2gather;
};

template <int MODE>
__global__ void __launch_bounds__(256, 2)
tgemm(GArg a0, GArg a1, const float* __restrict__ statsin, int K) {
    extern __shared__ float smf[];
    const uint32_t a_u32 = smem_u32(smf);
    const uint32_t b_u32 = a_u32 + NSTAGE * ST_WORDS * 4;

    const int t    = threadIdx.x;
    const int lane = t & 31;
    const int wid  = t >> 5;
    const int wm   = wid & 1;
    const int wn   = wid >> 1;
    const int n0   = blockIdx.x * 128;
    const int nch  = K / BK;     // 7

    const int tiles0 = a0.M >> 7;
    GArg g;
    int m0;
    if ((int)blockIdx.y < tiles0) { g = a0; m0 = blockIdx.y * 128; }
    else                          { g = a1; m0 = (blockIdx.y - tiles0) * 128; }
    const int N = g.N;

    if (MODE & 128) {
        if (t < 256) smf[STAT_OFF + t] = 0.f;   // zero 128x2 stat slots
    }

    // --- loader mapping ---
    const int lrow = t >> 3;
    const int lchk = t & 7;
    const float* AsrcN[4];
    int wbase[4];
    const float* Bsrc[4];
    uint32_t Adst[4], Bdst[4];
#pragma unroll
    for (int i = 0; i < 4; i++) {
        int row = lrow + 32 * i;
        int s   = m0 + row;
        if (g.agather) {
            wbase[i] = s & (W_IMG - 1);
            AsrcN[i] = g.cam + ((size_t)(s & ~(W_IMG - 1)) << 5) + lchk * 4;
        } else {
            wbase[i] = 0;
            AsrcN[i] = g.A + (size_t)s * K + lchk * 4;
        }
        int br = n0 + row; if (br > N - 1) br = N - 1;
        Bsrc[i] = g.W + (size_t)br * K + lchk * 4;
        uint32_t dw = (uint32_t)row * BK + ((lchk ^ (row & 7)) << 2);
        Adst[i] = a_u32 + dw * 4;
        Bdst[i] = b_u32 + dw * 4;
    }

    auto loadAB = [&](int ch, int sl) {
#pragma unroll
        for (int i = 0; i < 4; i++) {
            const float* src;
            if (g.agather) {
                int wc = wbase[i] + ch - 3;
                wc = wc < 0 ? 0 : (wc > W_IMG - 1 ? W_IMG - 1 : wc);
                src = AsrcN[i] + (size_t)wc * NPAT;
            } else {
                src = AsrcN[i] + (size_t)ch * BK;
            }
            cp16(Adst[i] + sl * ST_WORDS * 4, src);
            cp16(Bdst[i] + sl * ST_WORDS * 4, Bsrc[i] + (size_t)ch * BK);
        }
    };

    // --- ldmatrix lane mappings ---
    const int a_roff = (((lane >> 3) & 1) << 3) + (lane & 7);
    const int a_kb   = lane >> 4;
    const int b_roff = ((lane >> 4) << 3) + (lane & 7);
    const int b_kb   = (lane >> 3) & 1;

    float c[4][4][4];
#pragma unroll
    for (int i = 0; i < 4; i++)
#pragma unroll
        for (int j = 0; j < 4; j++)
#pragma unroll
            for (int r = 0; r < 4; r++) c[i][j][r] = 0.0f;

    // --- prologue: stages 0,1 ---
#pragma unroll
    for (int s = 0; s < 2; s++) {
        loadAB(s, s);
        cp_commit();
    }

    for (int ch = 0; ch < nch; ch++) {
        cp_wait1();
        __syncthreads();
        if (ch + 2 < nch) loadAB(ch + 2, (ch + 2) % NSTAGE);
        cp_commit();

        const uint32_t as_b = a_u32 + (ch % NSTAGE) * ST_WORDS * 4;
        const uint32_t bs_b = b_u32 + (ch % NSTAGE) * ST_WORDS * 4;

#pragma unroll
        for (int ks = 0; ks < 4; ks++) {
            uint32_t af[4][4];
#pragma unroll
            for (int mf = 0; mf < 4; mf++) {
                int row  = wm * 64 + mf * 16 + a_roff;
                int kblk = 2 * ks + a_kb;
                uint32_t addr = as_b + ((uint32_t)row * BK +
                                        (uint32_t)((kblk ^ (row & 7)) << 2)) * 4;
                asm volatile(
                    "ldmatrix.sync.aligned.m8n8.x4.shared.b16 {%0,%1,%2,%3}, [%4];"
                    : "=r"(af[mf][0]), "=r"(af[mf][1]),
                      "=r"(af[mf][2]), "=r"(af[mf][3])
                    : "r"(addr));
                if (MODE & 64) {
#pragma unroll
                    for (int x = 0; x < 4; x++) af[mf][x] = rndtf_u(af[mf][x]);
                }
            }
            uint32_t bf[4][2];
#pragma unroll
            for (int p = 0; p < 2; p++) {
                int row  = wn * 32 + p * 16 + b_roff;
                int kblk = 2 * ks + b_kb;
                uint32_t addr = bs_b + ((uint32_t)row * BK +
                                        (uint32_t)((kblk ^ (row & 7)) << 2)) * 4;
                asm volatile(
                    "ldmatrix.sync.aligned.m8n8.x4.shared.b16 {%0,%1,%2,%3}, [%4];"
                    : "=r"(bf[2 * p][0]), "=r"(bf[2 * p][1]),
                      "=r"(bf[2 * p + 1][0]), "=r"(bf[2 * p + 1][1])
                    : "r"(addr));
            }
#pragma unroll
            for (int mf = 0; mf < 4; mf++)
#pragma unroll
                for (int nf = 0; nf < 4; nf++) {
                    asm volatile(
                        "mma.sync.aligned.m16n8k8.row.col.f32.tf32.tf32.f32 "
                        "{%0,%1,%2,%3}, {%4,%5,%6,%7}, {%8,%9}, {%0,%1,%2,%3};"
                        : "+f"(c[mf][nf][0]), "+f"(c[mf][nf][1]),
                          "+f"(c[mf][nf][2]), "+f"(c[mf][nf][3])
                        : "r"(af[mf][0]), "r"(af[mf][1]),
                          "r"(af[mf][2]), "r"(af[mf][3]),
                          "r"(bf[nf][0]), "r"(bf[nf][1]));
                }
        }
        __syncthreads();
    }

    const int lq = lane >> 2;
    const int lr = lane & 3;

    float ss[8], qq[8];
    if (MODE & 128) {
#pragma unroll
        for (int e = 0; e < 8; e++) { ss[e] = 0.f; qq[e] = 0.f; }
    }

    // --- epilogue ---
#pragma unroll
    for (int mf = 0; mf < 4; mf++) {
        int row = m0 + wm * 64 + mf * 16 + lq;
        float inv0 = 1.f, inv1 = 1.f;
        if (MODE & 32) {
            float4 s0v = *(const float4*)(statsin + (size_t)row * 4);
            float4 s1v = *(const float4*)(statsin + (size_t)(row + 8) * 4);
            float sa = s0v.x + s0v.z, qa = s0v.y + s0v.w;
            float sb = s1v.x + s1v.z, qb = s1v.y + s1v.w;
            inv0 = rsqrtf(qa - sa * sa * (1.0f / FEAT));
            inv1 = rsqrtf(qb - sb * sb * (1.0f / FEAT));
        }
#pragma unroll
        for (int nf = 0; nf < 4; nf++) {
            int col = n0 + wn * 32 + nf * 8 + lr * 2;
            if (col < N) {
                float b0 = 0.f, b1 = 0.f;
                if (MODE & 1) { b0 = g.bias[col]; b1 = g.bias[col + 1]; }
#pragma unroll
                for (int half = 0; half < 2; half++) {
                    int r = row + half * 8;
                    float v0 = c[mf][nf][half * 2 + 0];
                    float v1 = c[mf][nf][half * 2 + 1];
                    if (MODE & 1) { v0 += b0; v1 += b1; }
                    if (MODE & 2) { v0 = fmaxf(v0, 0.f); v1 = fmaxf(v1, 0.f); }
                    size_t o = (size_t)r * N + col;
                    if (MODE & 4) {
                        if (g.resgather) {
                            int j = col >> 5, k = col & 31;
                            int wc = (r & (W_IMG - 1)) + j - 3;
                            wc = wc < 0 ? 0 : (wc > W_IMG - 1 ? W_IMG - 1 : wc);
                            const float* p = g.cam +
                                (((size_t)(r & ~(W_IMG - 1)) + wc) << 5) + k;
                            v0 += p[0]; v1 += p[1];
                        } else {
                            float2 rv = *(const float2*)(g.Res + o);
                            v0 += rv.x; v1 += rv.y;
                        }
                    }
                    if (MODE & 16) {
                        if (g.res2gather) {
                            int j = col >> 5, k = col & 31;
                            int wc = (r & (W_IMG - 1)) + j - 3;
                            wc = wc < 0 ? 0 : (wc > W_IMG - 1 ? W_IMG - 1 : wc);
                            const float* p = g.cam +
                                (((size_t)(r & ~(W_IMG - 1)) + wc) << 5) + k;
                            v0 += p[0]; v1 += p[1];
                        } else {
                            float2 rv = *(const float2*)(g.Res2 + o);
                            v0 += rv.x; v1 += rv.y;
                        }
                    }
                    if (MODE & 32) {
                        float sc = half ? inv1 : inv0;
                        v0 *= sc; v1 *= sc;
                    }
                    if (MODE & 8) { v0 = rndtf(v0); v1 = rndtf(v1); }
                    *(float2*)(g.C + o) = make_float2(v0, v1);
                    if (MODE & 128) {
                        int e = mf * 2 + half;
                        ss[e] += v0 + v1;
                        qq[e] += v0 * v0 + v1 * v1;
                    }
                }
            }
        }
    }

    if (MODE & 128) {
        // reduce over lr lanes (lane bits 0,1), then smem atomics, then write
#pragma unroll
        for (int e = 0; e < 8; e++) {
            ss[e] += __shfl_xor_sync(0xffffffffu, ss[e], 1);
            ss[e] += __shfl_xor_sync(0xffffffffu, ss[e], 2);
            qq[e] += __shfl_xor_sync(0xffffffffu, qq[e], 1);
            qq[e] += __shfl_xor_sync(0xffffffffu, qq[e], 2);
        }
        __syncthreads();   // stats buffer zeroed before mainloop; all passed it
        if (lr == 0) {
#pragma unroll
            for (int e = 0; e < 8; e++) {
                int rl = wm * 64 + (e >> 1) * 16 + lq + (e & 1) * 8;
                atomicAdd(&smf[STAT_OFF + rl * 2 + 0], ss[e]);
                atomicAdd(&smf[STAT_OFF + rl * 2 + 1], qq[e]);
            }
        }
        __syncthreads();
        if (t < 128 && g.stats) {
            *(float2*)(g.stats + (size_t)(m0 + t) * 4 + blockIdx.x * 2) =
                make_float2(smf[STAT_OFF + t * 2], smf[STAT_OFF + t * 2 + 1]);
        }
    }
}

// ---------------------------------------------------------------------------
// Proj normalize: Bnorm[m,:] = (Y[m,:] - mean) / ||Y - mean||  (tf32-rounded)
// ---------------------------------------------------------------------------
__global__ void normalize_proj(const float* __restrict__ Y,
                               float* __restrict__ Out, int M) {
    int warp = (blockIdx.x * blockDim.x + threadIdx.x) >> 5;
    int lane = threadIdx.x & 31;
    if (warp >= M) return;
    size_t base = (size_t)warp * FEAT;
    float y[7];
    float sum = 0.f;
#pragma unroll
    for (int i = 0; i < 7; i++) {
        y[i] = Y[base + lane + i * 32];
        sum += y[i];
    }
#pragma unroll
    for (int o = 16; o > 0; o >>= 1) sum += __shfl_xor_sync(0xffffffffu, sum, o);
    float mean = sum * (1.0f / FEAT);
    float sq = 0.f;
#pragma unroll
    for (int i = 0; i < 7; i++) {
        y[i] -= mean;
        sq += y[i] * y[i];
    }
#pragma unroll
    for (int o = 16; o > 0; o >>= 1) sq += __shfl_xor_sync(0xffffffffu, sq, o);
    float inv = rsqrtf(sq);
#pragma unroll
    for (int i = 0; i < 7; i++)
        Out[base + lane + i * 32] = rndtf(y[i] * inv);
}

// ---------------------------------------------------------------------------
extern "C" void kernel_launch(void* const* d_in, const int* in_sizes, int n_in,
                              void* d_out, int out_size) {
    const float* cam_code  = (const float*)d_in[0];
    const float* proj_code = (const float*)d_in[1];
    const float* cam_w0 = (const float*)d_in[2];
    const float* cam_b0 = (const float*)d_in[3];
    const float* cam_w1 = (const float*)d_in[4];
    const float* cam_b1 = (const float*)d_in[5];
    const float* proj_w0 = (const float*)d_in[6];
    const float* proj_b0 = (const float*)d_in[7];
    const float* proj_w1 = (const float*)d_in[8];
    const float* proj_b1 = (const float*)d_in[9];
    float* out = (float*)d_out;

    float *X, *Hc, *ST, *Pp, *Xp, *Hp, *W0c, *W1c, *W0p, *W1p;
    cudaGetSymbolAddress((void**)&X,   g_X);
    cudaGetSymbolAddress((void**)&Hc,  g_Hc);
    cudaGetSymbolAddress((void**)&ST,  g_stats);
    cudaGetSymbolAddress((void**)&Pp,  g_Pp);
    cudaGetSymbolAddress((void**)&Xp,  g_Xp);
    cudaGetSymbolAddress((void**)&Hp,  g_Hp);
    cudaGetSymbolAddress((void**)&W0c, g_W0c);
    cudaGetSymbolAddress((void**)&W1c, g_W1c);
    cudaGetSymbolAddress((void**)&W0p, g_W0p);
    cudaGetSymbolAddress((void**)&W1p, g_W1p);

    cudaFuncSetAttribute(tgemm<75>,  cudaFuncAttributeMaxDynamicSharedMemorySize, SMEM_BYTES);
    cudaFuncSetAttribute(tgemm<13>,  cudaFuncAttributeMaxDynamicSharedMemorySize, SMEM_BYTES);
    cudaFuncSetAttribute(tgemm<11>,  cudaFuncAttributeMaxDynamicSharedMemorySize, SMEM_BYTES);
    cudaFuncSetAttribute(tgemm<157>, cudaFuncAttributeMaxDynamicSharedMemorySize, SMEM_BYTES);
    cudaFuncSetAttribute(tgemm<32>,  cudaFuncAttributeMaxDynamicSharedMemorySize, SMEM_BYTES);

    // 1) Preprocessing (proj expansion + weight rounding only; no g_P pass)
    round_weights<<<(2 * F2 + 255) / 256, 256>>>(cam_w0, W0c, cam_w1, W1c,
                                                 proj_w0, W0p, proj_w1, W1p);
    build_pproj<<<(S_PROJ * FEAT + 255) / 256, 256>>>(proj_code, Pp);

    const int TC = S_CAM / 128;   // 1024
    const int TP = S_PROJ / 128;  // 8
    dim3 gmlp((FEAT + 127) / 128, TC + TP);

    GArg c0, p0;
    // layer 0, GEMM 0: H = relu(P @ W0^T + b0); cam P gathered from cam_code
    c0 = {cam_code, W0c, cam_b0,  nullptr, nullptr, Hc, nullptr, cam_code,
          S_CAM,  FEAT, 1, 0, 0};
    p0 = {Pp,       W0p, proj_b0, nullptr, nullptr, Hp, nullptr, nullptr,
          S_PROJ, FEAT, 0, 0, 0};
    tgemm<75><<<gmlp, 256, SMEM_BYTES>>>(c0, p0, nullptr, FEAT);   // 64|11

    // layer 0, GEMM 1: X = P + H @ W1^T + b1  (cam residual gathered)
    c0 = {Hc, W1c, cam_b1,  nullptr, nullptr, X,  nullptr, cam_code,
          S_CAM,  FEAT, 0, 1, 0};
    p0 = {Hp, W1p, proj_b1, Pp,      nullptr, Xp, nullptr, nullptr,
          S_PROJ, FEAT, 0, 0, 0};
    tgemm<13><<<gmlp, 256, SMEM_BYTES>>>(c0, p0, nullptr, FEAT);

    // layer 1, GEMM 0: H = relu(X @ W0^T + b0)
    c0 = {X,  W0c + F2, cam_b0 + FEAT,  nullptr, nullptr, Hc, nullptr, nullptr,
          S_CAM,  FEAT, 0, 0, 0};
    p0 = {Xp, W0p + F2, proj_b0 + FEAT, nullptr, nullptr, Hp, nullptr, nullptr,
          S_PROJ, FEAT, 0, 0, 0};
    tgemm<11><<<gmlp, 256, SMEM_BYTES>>>(c0, p0, nullptr, FEAT);

    // layer 1, GEMM 1: Y = X + H @ W1^T + b1 + P  (+ per-row stats, cam)
    c0 = {Hc, W1c + F2, cam_b1 + FEAT,  X,  nullptr, X,  ST,      cam_code,
          S_CAM,  FEAT, 0, 0, 1};
    p0 = {Hp, W1p + F2, proj_b1 + FEAT, Xp, Pp,      Xp, nullptr, nullptr,
          S_PROJ, FEAT, 0, 0, 0};
    tgemm<157><<<gmlp, 256, SMEM_BYTES>>>(c0, p0, nullptr, FEAT);  // 128|29

    // 3) Proj normalize only (cam stats already emitted by tgemm<157>)
    normalize_proj<<<(S_PROJ + 7) / 8, 256>>>(Xp, Hp, S_PROJ);

    // 4) ZNCC correlation: out[s,m] = inv_a[s] * (Y[s,:] . Bnorm[m,:])
    dim3 gfin(W_PAT / 128, TC);
    GArg f0 = {X, Hp, nullptr, nullptr, nullptr, out, nullptr, nullptr,
               S_CAM, W_PAT, 0, 0, 0};
    tgemm<32><<<gfin, 256, SMEM_BYTES>>>(f0, f0, ST, FEAT);
}

// round 8
// speedup vs baseline: 4.6437x; 1.0292x over previous
#include <cuda_runtime.h>
#include <cstdint>

// Problem constants
#define FEAT   224
#define NPAT   32
#define H_IMG  256
#define W_IMG  512
#define W_PAT  1024
#define S_CAM  (H_IMG * W_IMG)   // 131072
#define S_PROJ W_PAT             // 1024
#define F2     (FEAT * FEAT)
#define NCAM   (H_IMG * W_IMG * NPAT)   // 4194304

// Scratch (device globals)
__device__ float g_X    [S_CAM * FEAT];   // cam running x / final Y
__device__ float g_Hc   [S_CAM * FEAT];   // cam hidden
__device__ float g_stats[S_CAM * 4];      // per-row {s,q} x 2 N-tiles
__device__ float g_camr [NCAM];           // tf32-rounded cam_code
__device__ float g_Pp   [S_PROJ * FEAT];  // proj p
__device__ float g_Xp   [S_PROJ * FEAT];  // proj running x / Yp
__device__ float g_Hp   [S_PROJ * FEAT];  // proj hidden / Bnorm
__device__ float g_W0c  [2 * F2];
__device__ float g_W1c  [2 * F2];
__device__ float g_W0p  [2 * F2];
__device__ float g_W1p  [2 * F2];

// ---------------------------------------------------------------------------
// Helpers
// ---------------------------------------------------------------------------
__device__ __forceinline__ uint32_t smem_u32(const void* p) {
    uint32_t a;
    asm("{ .reg .u64 t; cvta.to.shared.u64 t, %1; cvt.u32.u64 %0, t; }"
        : "=r"(a) : "l"(p));
    return a;
}
__device__ __forceinline__ void cp16(uint32_t dst, const float* src) {
    asm volatile("cp.async.cg.shared.global [%0], [%1], 16;"
                 :: "r"(dst), "l"(src) : "memory");
}
__device__ __forceinline__ void cp_commit() {
    asm volatile("cp.async.commit_group;" ::: "memory");
}
__device__ __forceinline__ void cp_wait1() {
    asm volatile("cp.async.wait_group 1;" ::: "memory");
}
__device__ __forceinline__ void cp_wait0() {
    asm volatile("cp.async.wait_group 0;" ::: "memory");
}
__device__ __forceinline__ float rndtf(float v) {
    uint32_t u;
    asm("cvt.rna.tf32.f32 %0, %1;" : "=r"(u) : "f"(v));
    return __uint_as_float(u);
}

// ---------------------------------------------------------------------------
// Preprocessing kernels
// ---------------------------------------------------------------------------
__global__ void build_pproj(const float* __restrict__ proj, float* __restrict__ P) {
    int idx = blockIdx.x * blockDim.x + threadIdx.x;
    if (idx >= S_PROJ * FEAT) return;
    int m = idx / FEAT;
    int f = idx - m * FEAT;
    int j = f / NPAT;
    int k = f - j * NPAT;
    int mp = m + j - 3;
    mp = mp < 0 ? 0 : (mp > W_PAT - 1 ? W_PAT - 1 : mp);
    P[idx] = rndtf(proj[k * W_PAT + mp]);
}

__global__ void round_weights(const float* __restrict__ s0, float* __restrict__ d0,
                              const float* __restrict__ s1, float* __restrict__ d1,
                              const float* __restrict__ s2, float* __restrict__ d2,
                              const float* __restrict__ s3, float* __restrict__ d3) {
    int i = blockIdx.x * blockDim.x + threadIdx.x;
    if (i >= 2 * F2) return;
    d0[i] = rndtf(s0[i]);
    d1[i] = rndtf(s1[i]);
    d2[i] = rndtf(s2[i]);
    d3[i] = rndtf(s3[i]);
}

__global__ void round_cam(const float* __restrict__ src, float* __restrict__ dst) {
    int i = blockIdx.x * blockDim.x + threadIdx.x;
    if (i < NCAM) dst[i] = rndtf(src[i]);
}

// ---------------------------------------------------------------------------
// TF32 mma.sync GEMM, cp.async 3-stage pipeline + ldmatrix.
// Two argument sets (cam region, proj region) share one grid.
// MODE bits: 1 +bias, 2 relu, 4 +Res, 8 tf32-round store, 16 +Res2,
//            32 row-scale from stats (final), 128 emit per-row stats.
// GArg flags: agather = A fetched from camA (rounded cam_code) with
// neighbor-clamp (BK chunk == neighbor group j); resgather/res2gather =
// that residual is the virtual P tile, staged via smem from camR (raw).
// ---------------------------------------------------------------------------
#define BK       32
#define ST_WORDS (128 * BK)
#define NSTAGE   3
#define STAT_OFF (NSTAGE * 2 * ST_WORDS)              // float index of stat buf
#define SMEM_BYTES (STAT_OFF * 4 + 1024)              // 99328
#define GS       132                                  // staged-gather row stride

struct GArg {
    const float *A, *W, *bias, *Res, *Res2;
    float *C;
    float *stats;           // per-row partial stats out (nullptr = skip)
    const float *camA;      // A-gather source (rounded)
    const float *camR;      // residual-gather source (raw)
    int M, N;
    int agather, resgather, res2gather;
};

template <int MODE>
__global__ void __launch_bounds__(256, 2)
tgemm(GArg a0, GArg a1, const float* __restrict__ statsin, int K) {
    extern __shared__ float smf[];
    const uint32_t a_u32 = smem_u32(smf);
    const uint32_t b_u32 = a_u32 + NSTAGE * ST_WORDS * 4;

    const int t    = threadIdx.x;
    const int lane = t & 31;
    const int wid  = t >> 5;
    const int wm   = wid & 1;
    const int wn   = wid >> 1;
    const int n0   = blockIdx.x * 128;
    const int nch  = K / BK;     // 7

    const int tiles0 = a0.M >> 7;
    GArg g;
    int m0;
    if ((int)blockIdx.y < tiles0) { g = a0; m0 = blockIdx.y * 128; }
    else                          { g = a1; m0 = (blockIdx.y - tiles0) * 128; }
    const int N = g.N;

    if (MODE & 128) {
        if (t < 256) smf[STAT_OFF + t] = 0.f;   // zero 128x2 stat slots
    }

    // --- loader mapping ---
    const int lrow = t >> 3;
    const int lchk = t & 7;
    const float* AsrcN[4];
    int wbase[4];
    const float* Bsrc[4];
    uint32_t Adst[4], Bdst[4];
#pragma unroll
    for (int i = 0; i < 4; i++) {
        int row = lrow + 32 * i;
        int s   = m0 + row;
        if (g.agather) {
            wbase[i] = s & (W_IMG - 1);
            AsrcN[i] = g.camA + ((size_t)(s & ~(W_IMG - 1)) << 5) + lchk * 4;
        } else {
            wbase[i] = 0;
            AsrcN[i] = g.A + (size_t)s * K + lchk * 4;
        }
        int br = n0 + row; if (br > N - 1) br = N - 1;
        Bsrc[i] = g.W + (size_t)br * K + lchk * 4;
        uint32_t dw = (uint32_t)row * BK + ((lchk ^ (row & 7)) << 2);
        Adst[i] = a_u32 + dw * 4;
        Bdst[i] = b_u32 + dw * 4;
    }

    auto loadAB = [&](int ch, int sl) {
#pragma unroll
        for (int i = 0; i < 4; i++) {
            const float* src;
            if (g.agather) {
                int wc = wbase[i] + ch - 3;
                wc = wc < 0 ? 0 : (wc > W_IMG - 1 ? W_IMG - 1 : wc);
                src = AsrcN[i] + (size_t)wc * NPAT;
            } else {
                src = AsrcN[i] + (size_t)ch * BK;
            }
            cp16(Adst[i] + sl * ST_WORDS * 4, src);
            cp16(Bdst[i] + sl * ST_WORDS * 4, Bsrc[i] + (size_t)ch * BK);
        }
    };

    // --- ldmatrix lane mappings ---
    const int a_roff = (((lane >> 3) & 1) << 3) + (lane & 7);
    const int a_kb   = lane >> 4;
    const int b_roff = ((lane >> 4) << 3) + (lane & 7);
    const int b_kb   = (lane >> 3) & 1;

    float c[4][4][4];
#pragma unroll
    for (int i = 0; i < 4; i++)
#pragma unroll
        for (int j = 0; j < 4; j++)
#pragma unroll
            for (int r = 0; r < 4; r++) c[i][j][r] = 0.0f;

    // --- prologue: stages 0,1 ---
#pragma unroll
    for (int s = 0; s < 2; s++) {
        loadAB(s, s);
        cp_commit();
    }

    for (int ch = 0; ch < nch; ch++) {
        cp_wait1();
        __syncthreads();   // sole barrier: also orders slot reuse (3 stages)
        if (ch + 2 < nch) loadAB(ch + 2, (ch + 2) % NSTAGE);
        cp_commit();

        const uint32_t as_b = a_u32 + (ch % NSTAGE) * ST_WORDS * 4;
        const uint32_t bs_b = b_u32 + (ch % NSTAGE) * ST_WORDS * 4;

#pragma unroll
        for (int ks = 0; ks < 4; ks++) {
            uint32_t af[4][4];
#pragma unroll
            for (int mf = 0; mf < 4; mf++) {
                int row  = wm * 64 + mf * 16 + a_roff;
                int kblk = 2 * ks + a_kb;
                uint32_t addr = as_b + ((uint32_t)row * BK +
                                        (uint32_t)((kblk ^ (row & 7)) << 2)) * 4;
                asm volatile(
                    "ldmatrix.sync.aligned.m8n8.x4.shared.b16 {%0,%1,%2,%3}, [%4];"
                    : "=r"(af[mf][0]), "=r"(af[mf][1]),
                      "=r"(af[mf][2]), "=r"(af[mf][3])
                    : "r"(addr));
            }
            uint32_t bf[4][2];
#pragma unroll
            for (int p = 0; p < 2; p++) {
                int row  = wn * 32 + p * 16 + b_roff;
                int kblk = 2 * ks + b_kb;
                uint32_t addr = bs_b + ((uint32_t)row * BK +
                                        (uint32_t)((kblk ^ (row & 7)) << 2)) * 4;
                asm volatile(
                    "ldmatrix.sync.aligned.m8n8.x4.shared.b16 {%0,%1,%2,%3}, [%4];"
                    : "=r"(bf[2 * p][0]), "=r"(bf[2 * p][1]),
                      "=r"(bf[2 * p + 1][0]), "=r"(bf[2 * p + 1][1])
                    : "r"(addr));
            }
#pragma unroll
            for (int mf = 0; mf < 4; mf++)
#pragma unroll
                for (int nf = 0; nf < 4; nf++) {
                    asm volatile(
                        "mma.sync.aligned.m16n8k8.row.col.f32.tf32.tf32.f32 "
                        "{%0,%1,%2,%3}, {%4,%5,%6,%7}, {%8,%9}, {%0,%1,%2,%3};"
                        : "+f"(c[mf][nf][0]), "+f"(c[mf][nf][1]),
                          "+f"(c[mf][nf][2]), "+f"(c[mf][nf][3])
                        : "r"(af[mf][0]), "r"(af[mf][1]),
                          "r"(af[mf][2]), "r"(af[mf][3]),
                          "r"(bf[nf][0]), "r"(bf[nf][1]));
                }
        }
    }

    // --- optional: stage residual P-tile gather into (now free) pipe smem ---
    const int dogather = ((MODE & 4) && g.resgather) ||
                         ((MODE & 16) && g.res2gather);
    if (dogather) {
        __syncthreads();   // all warps done reading pipeline slots
#pragma unroll
        for (int i = 0; i < 16; i++) {
            int idx = t + 256 * i;          // 4096 granules (128 x 32)
            int r   = idx >> 5;
            int q   = idx & 31;             // 16B granule within 512B row
            int s   = m0 + r;
            int j   = (n0 >> 5) + (q >> 3);
            int wc  = (s & (W_IMG - 1)) + j - 3;
            wc = wc < 0 ? 0 : (wc > W_IMG - 1 ? W_IMG - 1 : wc);
            const float* src = g.camR +
                (((size_t)(s & ~(W_IMG - 1)) + wc) << 5) + (q & 7) * 4;
            cp16(a_u32 + ((uint32_t)r * GS + q * 4) * 4, src);
        }
        cp_commit();
        cp_wait0();
        __syncthreads();
    }

    const int lq = lane >> 2;
    const int lr = lane & 3;

    float ss[8], qq[8];
    if (MODE & 128) {
#pragma unroll
        for (int e = 0; e < 8; e++) { ss[e] = 0.f; qq[e] = 0.f; }
    }

    // --- epilogue ---
#pragma unroll
    for (int mf = 0; mf < 4; mf++) {
        int row = m0 + wm * 64 + mf * 16 + lq;
        float inv0 = 1.f, inv1 = 1.f;
        if (MODE & 32) {
            float4 s0v = *(const float4*)(statsin + (size_t)row * 4);
            float4 s1v = *(const float4*)(statsin + (size_t)(row + 8) * 4);
            float sa = s0v.x + s0v.z, qa = s0v.y + s0v.w;
            float sb = s1v.x + s1v.z, qb = s1v.y + s1v.w;
            inv0 = rsqrtf(qa - sa * sa * (1.0f / FEAT));
            inv1 = rsqrtf(qb - sb * sb * (1.0f / FEAT));
        }
#pragma unroll
        for (int nf = 0; nf < 4; nf++) {
            int col = n0 + wn * 32 + nf * 8 + lr * 2;
            if (col < N) {
                float b0 = 0.f, b1 = 0.f;
                if (MODE & 1) { b0 = g.bias[col]; b1 = g.bias[col + 1]; }
#pragma unroll
                for (int half = 0; half < 2; half++) {
                    int r = row + half * 8;
                    float v0 = c[mf][nf][half * 2 + 0];
                    float v1 = c[mf][nf][half * 2 + 1];
                    if (MODE & 1) { v0 += b0; v1 += b1; }
                    if (MODE & 2) { v0 = fmaxf(v0, 0.f); v1 = fmaxf(v1, 0.f); }
                    size_t o = (size_t)r * N + col;
                    if (MODE & 4) {
                        if (g.resgather) {
                            float2 rv = *(const float2*)
                                (&smf[(r - m0) * GS + (col - n0)]);
                            v0 += rv.x; v1 += rv.y;
                        } else {
                            float2 rv = *(const float2*)(g.Res + o);
                            v0 += rv.x; v1 += rv.y;
                        }
                    }
                    if (MODE & 16) {
                        if (g.res2gather) {
                            float2 rv = *(const float2*)
                                (&smf[(r - m0) * GS + (col - n0)]);
                            v0 += rv.x; v1 += rv.y;
                        } else {
                            float2 rv = *(const float2*)(g.Res2 + o);
                            v0 += rv.x; v1 += rv.y;
                        }
                    }
                    if (MODE & 32) {
                        float sc = half ? inv1 : inv0;
                        v0 *= sc; v1 *= sc;
                    }
                    if (MODE & 8) { v0 = rndtf(v0); v1 = rndtf(v1); }
                    *(float2*)(g.C + o) = make_float2(v0, v1);
                    if (MODE & 128) {
                        int e = mf * 2 + half;
                        ss[e] += v0 + v1;
                        qq[e] += v0 * v0 + v1 * v1;
                    }
                }
            }
        }
    }

    if (MODE & 128) {
#pragma unroll
        for (int e = 0; e < 8; e++) {
            ss[e] += __shfl_xor_sync(0xffffffffu, ss[e], 1);
            ss[e] += __shfl_xor_sync(0xffffffffu, ss[e], 2);
            qq[e] += __shfl_xor_sync(0xffffffffu, qq[e], 1);
            qq[e] += __shfl_xor_sync(0xffffffffu, qq[e], 2);
        }
        __syncthreads();
        if (lr == 0) {
#pragma unroll
            for (int e = 0; e < 8; e++) {
                int rl = wm * 64 + (e >> 1) * 16 + lq + (e & 1) * 8;
                atomicAdd(&smf[STAT_OFF + rl * 2 + 0], ss[e]);
                atomicAdd(&smf[STAT_OFF + rl * 2 + 1], qq[e]);
            }
        }
        __syncthreads();
        if (t < 128 && g.stats) {
            *(float2*)(g.stats + (size_t)(m0 + t) * 4 + blockIdx.x * 2) =
                make_float2(smf[STAT_OFF + t * 2], smf[STAT_OFF + t * 2 + 1]);
        }
    }
}

// ---------------------------------------------------------------------------
// Proj normalize: Bnorm[m,:] = (Y[m,:] - mean) / ||Y - mean||  (tf32-rounded)
// ---------------------------------------------------------------------------
__global__ void normalize_proj(const float* __restrict__ Y,
                               float* __restrict__ Out, int M) {
    int warp = (blockIdx.x * blockDim.x + threadIdx.x) >> 5;
    int lane = threadIdx.x & 31;
    if (warp >= M) return;
    size_t base = (size_t)warp * FEAT;
    float y[7];
    float sum = 0.f;
#pragma unroll
    for (int i = 0; i < 7; i++) {
        y[i] = Y[base + lane + i * 32];
        sum += y[i];
    }
#pragma unroll
    for (int o = 16; o > 0; o >>= 1) sum += __shfl_xor_sync(0xffffffffu, sum, o);
    float mean = sum * (1.0f / FEAT);
    float sq = 0.f;
#pragma unroll
    for (int i = 0; i < 7; i++) {
        y[i] -= mean;
        sq += y[i] * y[i];
    }
#pragma unroll
    for (int o = 16; o > 0; o >>= 1) sq += __shfl_xor_sync(0xffffffffu, sq, o);
    float inv = rsqrtf(sq);
#pragma unroll
    for (int i = 0; i < 7; i++)
        Out[base + lane + i * 32] = rndtf(y[i] * inv);
}

// ---------------------------------------------------------------------------
extern "C" void kernel_launch(void* const* d_in, const int* in_sizes, int n_in,
                              void* d_out, int out_size) {
    const float* cam_code  = (const float*)d_in[0];
    const float* proj_code = (const float*)d_in[1];
    const float* cam_w0 = (const float*)d_in[2];
    const float* cam_b0 = (const float*)d_in[3];
    const float* cam_w1 = (const float*)d_in[4];
    const float* cam_b1 = (const float*)d_in[5];
    const float* proj_w0 = (const float*)d_in[6];
    const float* proj_b0 = (const float*)d_in[7];
    const float* proj_w1 = (const float*)d_in[8];
    const float* proj_b1 = (const float*)d_in[9];
    float* out = (float*)d_out;

    float *X, *Hc, *ST, *CR, *Pp, *Xp, *Hp, *W0c, *W1c, *W0p, *W1p;
    cudaGetSymbolAddress((void**)&X,   g_X);
    cudaGetSymbolAddress((void**)&Hc,  g_Hc);
    cudaGetSymbolAddress((void**)&ST,  g_stats);
    cudaGetSymbolAddress((void**)&CR,  g_camr);
    cudaGetSymbolAddress((void**)&Pp,  g_Pp);
    cudaGetSymbolAddress((void**)&Xp,  g_Xp);
    cudaGetSymbolAddress((void**)&Hp,  g_Hp);
    cudaGetSymbolAddress((void**)&W0c, g_W0c);
    cudaGetSymbolAddress((void**)&W1c, g_W1c);
    cudaGetSymbolAddress((void**)&W0p, g_W0p);
    cudaGetSymbolAddress((void**)&W1p, g_W1p);

    cudaFuncSetAttribute(tgemm<11>,  cudaFuncAttributeMaxDynamicSharedMemorySize, SMEM_BYTES);
    cudaFuncSetAttribute(tgemm<13>,  cudaFuncAttributeMaxDynamicSharedMemorySize, SMEM_BYTES);
    cudaFuncSetAttribute(tgemm<157>, cudaFuncAttributeMaxDynamicSharedMemorySize, SMEM_BYTES);
    cudaFuncSetAttribute(tgemm<32>,  cudaFuncAttributeMaxDynamicSharedMemorySize, SMEM_BYTES);

    // 1) Preprocessing
    round_weights<<<(2 * F2 + 255) / 256, 256>>>(cam_w0, W0c, cam_w1, W1c,
                                                 proj_w0, W0p, proj_w1, W1p);
    round_cam<<<(NCAM + 255) / 256, 256>>>(cam_code, CR);
    build_pproj<<<(S_PROJ * FEAT + 255) / 256, 256>>>(proj_code, Pp);

    const int TC = S_CAM / 128;   // 1024
    const int TP = S_PROJ / 128;  // 8
    dim3 gmlp((FEAT + 127) / 128, TC + TP);

    GArg c0, p0;
    // layer 0, GEMM 0: H = relu(P @ W0^T + b0); cam P gathered from g_camr
    c0 = {nullptr, W0c, cam_b0,  nullptr, nullptr, Hc, nullptr, CR, cam_code,
          S_CAM,  FEAT, 1, 0, 0};
    p0 = {Pp,      W0p, proj_b0, nullptr, nullptr, Hp, nullptr, nullptr, nullptr,
          S_PROJ, FEAT, 0, 0, 0};
    tgemm<11><<<gmlp, 256, SMEM_BYTES>>>(c0, p0, nullptr, FEAT);

    // layer 0, GEMM 1: X = P + H @ W1^T + b1  (cam residual staged gather)
    c0 = {Hc, W1c, cam_b1,  nullptr, nullptr, X,  nullptr, CR, cam_code,
          S_CAM,  FEAT, 0, 1, 0};
    p0 = {Hp, W1p, proj_b1, Pp,      nullptr, Xp, nullptr, nullptr, nullptr,
          S_PROJ, FEAT, 0, 0, 0};
    tgemm<13><<<gmlp, 256, SMEM_BYTES>>>(c0, p0, nullptr, FEAT);

    // layer 1, GEMM 0: H = relu(X @ W0^T + b0)
    c0 = {X,  W0c + F2, cam_b0 + FEAT,  nullptr, nullptr, Hc, nullptr, nullptr,
          nullptr, S_CAM,  FEAT, 0, 0, 0};
    p0 = {Xp, W0p + F2, proj_b0 + FEAT, nullptr, nullptr, Hp, nullptr, nullptr,
          nullptr, S_PROJ, FEAT, 0, 0, 0};
    tgemm<11><<<gmlp, 256, SMEM_BYTES>>>(c0, p0, nullptr, FEAT);

    // layer 1, GEMM 1: Y = X + H @ W1^T + b1 + P  (+ per-row stats, cam)
    c0 = {Hc, W1c + F2, cam_b1 + FEAT,  X,  nullptr, X,  ST, CR, cam_code,
          S_CAM,  FEAT, 0, 0, 1};
    p0 = {Hp, W1p + F2, proj_b1 + FEAT, Xp, Pp,      Xp, nullptr, nullptr, nullptr,
          S_PROJ, FEAT, 0, 0, 0};
    tgemm<157><<<gmlp, 256, SMEM_BYTES>>>(c0, p0, nullptr, FEAT);

    // 3) Proj normalize (cam stats already emitted by tgemm<157>)
    normalize_proj<<<(S_PROJ + 7) / 8, 256>>>(Xp, Hp, S_PROJ);

    // 4) ZNCC correlation: out[s,m] = inv_a[s] * (Y[s,:] . Bnorm[m,:])
    dim3 gfin(W_PAT / 128, TC);
    GArg f0 = {X, Hp, nullptr, nullptr, nullptr, out, nullptr, nullptr, nullptr,
               S_CAM, W_PAT, 0, 0, 0};
    tgemm<32><<<gfin, 256, SMEM_BYTES>>>(f0, f0, ST, FEAT);
}

// round 9
// speedup vs baseline: 6.0612x; 1.3052x over previous
#include <cuda_runtime.h>
#include <cuda_fp16.h>
#include <cstdint>

// Problem constants
#define FEAT   224
#define NPAT   32
#define H_IMG  256
#define W_IMG  512
#define W_PAT  1024
#define S_CAM  (H_IMG * W_IMG)   // 131072
#define S_PROJ W_PAT             // 1024
#define F2     (FEAT * FEAT)
#define NCAM   (H_IMG * W_IMG * NPAT)   // 4194304

// Scratch (device globals) — all GEMM operands fp16
__device__ __half g_X    [S_CAM * FEAT];   // cam running x / final Y
__device__ __half g_Hc   [S_CAM * FEAT];   // cam hidden
__device__ float  g_stats[S_CAM * 4];      // per-row {s,q} x 2 N-tiles
__device__ __half g_camh [NCAM];           // fp16-rounded cam_code
__device__ __half g_Pp   [S_PROJ * FEAT];  // proj p
__device__ __half g_Xp   [S_PROJ * FEAT];  // proj running x / Yp
__device__ __half g_Hp   [S_PROJ * FEAT];  // proj hidden / Bnorm
__device__ __half g_W0c  [2 * F2];
__device__ __half g_W1c  [2 * F2];
__device__ __half g_W0p  [2 * F2];
__device__ __half g_W1p  [2 * F2];

// ---------------------------------------------------------------------------
// Helpers
// ---------------------------------------------------------------------------
__device__ __forceinline__ uint32_t smem_u32(const void* p) {
    uint32_t a;
    asm("{ .reg .u64 t; cvta.to.shared.u64 t, %1; cvt.u32.u64 %0, t; }"
        : "=r"(a) : "l"(p));
    return a;
}
__device__ __forceinline__ void cp16(uint32_t dst, const void* src) {
    asm volatile("cp.async.cg.shared.global [%0], [%1], 16;"
                 :: "r"(dst), "l"(src) : "memory");
}
__device__ __forceinline__ void cp_commit() {
    asm volatile("cp.async.commit_group;" ::: "memory");
}
__device__ __forceinline__ void cp_wait1() {
    asm volatile("cp.async.wait_group 1;" ::: "memory");
}
__device__ __forceinline__ void cp_wait0() {
    asm volatile("cp.async.wait_group 0;" ::: "memory");
}

// ---------------------------------------------------------------------------
// Preprocessing kernels
// ---------------------------------------------------------------------------
__global__ void build_pproj(const float* __restrict__ proj,
                            __half* __restrict__ P) {
    int idx = blockIdx.x * blockDim.x + threadIdx.x;
    if (idx >= S_PROJ * FEAT) return;
    int m = idx / FEAT;
    int f = idx - m * FEAT;
    int j = f / NPAT;
    int k = f - j * NPAT;
    int mp = m + j - 3;
    mp = mp < 0 ? 0 : (mp > W_PAT - 1 ? W_PAT - 1 : mp);
    P[idx] = __float2half_rn(proj[k * W_PAT + mp]);
}

__global__ void round_weights(const float* __restrict__ s0, __half* __restrict__ d0,
                              const float* __restrict__ s1, __half* __restrict__ d1,
                              const float* __restrict__ s2, __half* __restrict__ d2,
                              const float* __restrict__ s3, __half* __restrict__ d3) {
    int i = blockIdx.x * blockDim.x + threadIdx.x;
    if (i >= 2 * F2) return;
    d0[i] = __float2half_rn(s0[i]);
    d1[i] = __float2half_rn(s1[i]);
    d2[i] = __float2half_rn(s2[i]);
    d3[i] = __float2half_rn(s3[i]);
}

__global__ void round_cam(const float* __restrict__ src, __half* __restrict__ dst) {
    int i = blockIdx.x * blockDim.x + threadIdx.x;
    if (i < NCAM) dst[i] = __float2half_rn(src[i]);
}

// ---------------------------------------------------------------------------
// FP16 mma.sync m16n8k16 GEMM (fp32 accumulate), cp.async 3-stage pipeline
// + ldmatrix. Two argument sets (cam region, proj region) share one grid.
// Stage layout: 128 rows x 128 B; row r = [A chunk 64B | B chunk 64B],
// granule (16B) position = g ^ (r&7)  (g: 0-3 A, 4-7 B) -> LDSM conflict-free.
// MODE bits: 1 +bias, 2 relu, 4 +Res, 8 store half (else fp32),
//            16 +Res2, 32 row-scale from stats, 128 emit per-row stats.
// GArg flags: agather = A rows gathered from camA (neighbor-clamp, chunk==j);
// resgather/res2gather = residual is the virtual P tile, staged from camA.
// ---------------------------------------------------------------------------
#define BK        32                       // K elements (halves) per chunk
#define ST_BYTES  16384                    // 128 rows x 128 B
#define NSTAGE    3
#define STAT_BYTE (NSTAGE * ST_BYTES)      // 49152
#define SMEM_BYTES (STAT_BYTE + 1024)      // 50176
#define GS        136                      // staged residual row stride (halves)

struct GArg {
    const __half *A, *W, *Res, *Res2, *camA;
    const float *bias;
    void *C;                // __half* (MODE&8) or float*
    float *stats;
    int M, N;
    int agather, resgather, res2gather;
};

template <int MODE>
__global__ void __launch_bounds__(256, 2)
tgemm(GArg a0, GArg a1, const float* __restrict__ statsin, int K) {
    extern __shared__ char smc[];
    __half* smh = (__half*)smc;
    float* smstat = (float*)(smc + STAT_BYTE);
    const uint32_t sb = smem_u32(smc);

    const int t    = threadIdx.x;
    const int lane = t & 31;
    const int wid  = t >> 5;
    const int wm   = wid & 1;
    const int wn   = wid >> 1;
    const int n0   = blockIdx.x * 128;
    const int nch  = K / BK;     // 7

    const int tiles0 = a0.M >> 7;
    GArg g;
    int m0;
    if ((int)blockIdx.y < tiles0) { g = a0; m0 = blockIdx.y * 128; }
    else                          { g = a1; m0 = (blockIdx.y - tiles0) * 128; }
    const int N = g.N;

    if (MODE & 128) {
        if (t < 256) smstat[t] = 0.f;
    }

    // --- loader mapping: 2 A granules + 2 B granules per thread per chunk ---
    const __half* AsrcB[2];
    const __half* BsrcB[2];
    int wbA[2];
    uint32_t AdstB[2], BdstB[2];
#pragma unroll
    for (int i = 0; i < 2; i++) {
        int idx = t + 256 * i;      // 0..511
        int r = idx >> 2;           // 0..127
        int gq = idx & 3;           // granule within 64B
        int s = m0 + r;
        if (g.agather) {
            wbA[i]   = s & (W_IMG - 1);
            AsrcB[i] = g.camA + ((size_t)(s & ~(W_IMG - 1)) << 5) + gq * 8;
        } else {
            wbA[i]   = 0;
            AsrcB[i] = g.A + (size_t)s * K + gq * 8;
        }
        int br = n0 + r; if (br > N - 1) br = N - 1;
        BsrcB[i] = g.W + (size_t)br * K + gq * 8;
        AdstB[i] = sb + (uint32_t)r * 128 + (((uint32_t)gq       ^ (r & 7)) << 4);
        BdstB[i] = sb + (uint32_t)r * 128 + (((uint32_t)(gq + 4) ^ (r & 7)) << 4);
    }

    auto loadAB = [&](int ch, int sl) {
        uint32_t so = (uint32_t)sl * ST_BYTES;
#pragma unroll
        for (int i = 0; i < 2; i++) {
            const __half* src;
            if (g.agather) {
                int wc = wbA[i] + ch - 3;
                wc = wc < 0 ? 0 : (wc > W_IMG - 1 ? W_IMG - 1 : wc);
                src = AsrcB[i] + (size_t)wc * NPAT;
            } else {
                src = AsrcB[i] + (size_t)ch * BK;
            }
            cp16(AdstB[i] + so, src);
            cp16(BdstB[i] + so, BsrcB[i] + (size_t)ch * BK);
        }
    };

    // --- ldmatrix lane mappings ---
    const int a_roff = (((lane >> 3) & 1) << 3) + (lane & 7);
    const int a_kb   = lane >> 4;            // k granule +0/+1
    const int b_roff = (((lane >> 4) & 1) << 3) + (lane & 7);
    const int b_kb   = (lane >> 3) & 1;

    float c[4][4][4];
#pragma unroll
    for (int i = 0; i < 4; i++)
#pragma unroll
        for (int j = 0; j < 4; j++)
#pragma unroll
            for (int r = 0; r < 4; r++) c[i][j][r] = 0.0f;

#pragma unroll
    for (int s = 0; s < 2; s++) {
        loadAB(s, s);
        cp_commit();
    }

    for (int ch = 0; ch < nch; ch++) {
        cp_wait1();
        __syncthreads();
        if (ch + 2 < nch) loadAB(ch + 2, (ch + 2) % NSTAGE);
        cp_commit();

        const uint32_t st_b = sb + (uint32_t)(ch % NSTAGE) * ST_BYTES;

#pragma unroll
        for (int ks = 0; ks < 2; ks++) {      // two k16 steps per 32-chunk
            uint32_t af[4][4];
#pragma unroll
            for (int mf = 0; mf < 4; mf++) {
                int row = wm * 64 + mf * 16 + a_roff;
                int gk  = 2 * ks + a_kb;      // A granule 0..3
                uint32_t addr = st_b + (uint32_t)row * 128 +
                                (((uint32_t)gk ^ (row & 7)) << 4);
                asm volatile(
                    "ldmatrix.sync.aligned.m8n8.x4.shared.b16 {%0,%1,%2,%3}, [%4];"
                    : "=r"(af[mf][0]), "=r"(af[mf][1]),
                      "=r"(af[mf][2]), "=r"(af[mf][3])
                    : "r"(addr));
            }
            uint32_t bf[4][2];
#pragma unroll
            for (int p = 0; p < 2; p++) {     // 2 nf per x4
                int row = wn * 32 + p * 16 + b_roff;
                int gk  = 4 + 2 * ks + b_kb;  // B granule 4..7
                uint32_t addr = st_b + (uint32_t)row * 128 +
                                (((uint32_t)gk ^ (row & 7)) << 4);
                asm volatile(
                    "ldmatrix.sync.aligned.m8n8.x4.shared.b16 {%0,%1,%2,%3}, [%4];"
                    : "=r"(bf[2 * p][0]), "=r"(bf[2 * p][1]),
                      "=r"(bf[2 * p + 1][0]), "=r"(bf[2 * p + 1][1])
                    : "r"(addr));
            }
#pragma unroll
            for (int mf = 0; mf < 4; mf++)
#pragma unroll
                for (int nf = 0; nf < 4; nf++) {
                    asm volatile(
                        "mma.sync.aligned.m16n8k16.row.col.f32.f16.f16.f32 "
                        "{%0,%1,%2,%3}, {%4,%5,%6,%7}, {%8,%9}, {%0,%1,%2,%3};"
                        : "+f"(c[mf][nf][0]), "+f"(c[mf][nf][1]),
                          "+f"(c[mf][nf][2]), "+f"(c[mf][nf][3])
                        : "r"(af[mf][0]), "r"(af[mf][1]),
                          "r"(af[mf][2]), "r"(af[mf][3]),
                          "r"(bf[nf][0]), "r"(bf[nf][1]));
                }
        }
    }

    // --- stage residual P-tile (fp16) into now-free pipeline smem ---
    const int dogather = ((MODE & 4) && g.resgather) ||
                         ((MODE & 16) && g.res2gather);
    if (dogather) {
        __syncthreads();
#pragma unroll
        for (int i = 0; i < 8; i++) {
            int idx = t + 256 * i;     // 2048 granules (128 rows x 16)
            int r   = idx >> 4;
            int q   = idx & 15;        // 8-half granule within row
            if (n0 + q * 8 < N) {
                int s  = m0 + r;
                int j  = (n0 >> 5) + (q >> 2);
                int wc = (s & (W_IMG - 1)) + j - 3;
                wc = wc < 0 ? 0 : (wc > W_IMG - 1 ? W_IMG - 1 : wc);
                const __half* src = g.camA +
                    (((size_t)(s & ~(W_IMG - 1)) + wc) << 5) + (q & 3) * 8;
                cp16(sb + (uint32_t)r * (GS * 2) + q * 16, src);
            }
        }
        cp_commit();
        cp_wait0();
        __syncthreads();
    }

    const int lq = lane >> 2;
    const int lr = lane & 3;

    float ss[8], qq[8];
    if (MODE & 128) {
#pragma unroll
        for (int e = 0; e < 8; e++) { ss[e] = 0.f; qq[e] = 0.f; }
    }

    // --- epilogue ---
#pragma unroll
    for (int mf = 0; mf < 4; mf++) {
        int row = m0 + wm * 64 + mf * 16 + lq;
        float inv0 = 1.f, inv1 = 1.f;
        if (MODE & 32) {
            float4 s0v = *(const float4*)(statsin + (size_t)row * 4);
            float4 s1v = *(const float4*)(statsin + (size_t)(row + 8) * 4);
            float sa = s0v.x + s0v.z, qa = s0v.y + s0v.w;
            float sb2 = s1v.x + s1v.z, qb = s1v.y + s1v.w;
            inv0 = rsqrtf(qa - sa * sa * (1.0f / FEAT));
            inv1 = rsqrtf(qb - sb2 * sb2 * (1.0f / FEAT));
        }
#pragma unroll
        for (int nf = 0; nf < 4; nf++) {
            int col = n0 + wn * 32 + nf * 8 + lr * 2;
            if (col < N) {
                float b0 = 0.f, b1 = 0.f;
                if (MODE & 1) { b0 = g.bias[col]; b1 = g.bias[col + 1]; }
#pragma unroll
                for (int half_ = 0; half_ < 2; half_++) {
                    int r = row + half_ * 8;
                    float v0 = c[mf][nf][half_ * 2 + 0];
                    float v1 = c[mf][nf][half_ * 2 + 1];
                    if (MODE & 1) { v0 += b0; v1 += b1; }
                    if (MODE & 2) { v0 = fmaxf(v0, 0.f); v1 = fmaxf(v1, 0.f); }
                    size_t o = (size_t)r * N + col;
                    if (MODE & 4) {
                        float2 rv;
                        if (g.resgather) {
                            rv = __half22float2(
                                *(const __half2*)(smh + (r - m0) * GS + (col - n0)));
                        } else {
                            rv = __half22float2(*(const __half2*)(g.Res + o));
                        }
                        v0 += rv.x; v1 += rv.y;
                    }
                    if (MODE & 16) {
                        float2 rv;
                        if (g.res2gather) {
                            rv = __half22float2(
                                *(const __half2*)(smh + (r - m0) * GS + (col - n0)));
                        } else {
                            rv = __half22float2(*(const __half2*)(g.Res2 + o));
                        }
                        v0 += rv.x; v1 += rv.y;
                    }
                    if (MODE & 32) {
                        float sc = half_ ? inv1 : inv0;
                        v0 *= sc; v1 *= sc;
                    }
                    if (MODE & 8) {
                        __half2 hv = __floats2half2_rn(v0, v1);
                        *((__half2*)((__half*)g.C + o)) = hv;
                        if (MODE & 128) {
                            float2 fr = __half22float2(hv);
                            v0 = fr.x; v1 = fr.y;
                        }
                    } else {
                        *((float2*)((float*)g.C + o)) = make_float2(v0, v1);
                    }
                    if (MODE & 128) {
                        int e = mf * 2 + half_;
                        ss[e] += v0 + v1;
                        qq[e] += v0 * v0 + v1 * v1;
                    }
                }
            }
        }
    }

    if (MODE & 128) {
#pragma unroll
        for (int e = 0; e < 8; e++) {
            ss[e] += __shfl_xor_sync(0xffffffffu, ss[e], 1);
            ss[e] += __shfl_xor_sync(0xffffffffu, ss[e], 2);
            qq[e] += __shfl_xor_sync(0xffffffffu, qq[e], 1);
            qq[e] += __shfl_xor_sync(0xffffffffu, qq[e], 2);
        }
        __syncthreads();
        if (lr == 0) {
#pragma unroll
            for (int e = 0; e < 8; e++) {
                int rl = wm * 64 + (e >> 1) * 16 + lq + (e & 1) * 8;
                atomicAdd(&smstat[rl * 2 + 0], ss[e]);
                atomicAdd(&smstat[rl * 2 + 1], qq[e]);
            }
        }
        __syncthreads();
        if (t < 128 && g.stats) {
            *(float2*)(g.stats + (size_t)(m0 + t) * 4 + blockIdx.x * 2) =
                make_float2(smstat[t * 2], smstat[t * 2 + 1]);
        }
    }
}

// ---------------------------------------------------------------------------
// Proj normalize: Bnorm[m,:] = (Y[m,:] - mean) / ||Y - mean||  (fp16 out)
// ---------------------------------------------------------------------------
__global__ void normalize_proj(const __half* __restrict__ Y,
                               __half* __restrict__ Out, int M) {
    int warp = (blockIdx.x * blockDim.x + threadIdx.x) >> 5;
    int lane = threadIdx.x & 31;
    if (warp >= M) return;
    size_t base = (size_t)warp * FEAT;
    float y[7];
    float sum = 0.f;
#pragma unroll
    for (int i = 0; i < 7; i++) {
        y[i] = __half2float(Y[base + lane + i * 32]);
        sum += y[i];
    }
#pragma unroll
    for (int o = 16; o > 0; o >>= 1) sum += __shfl_xor_sync(0xffffffffu, sum, o);
    float mean = sum * (1.0f / FEAT);
    float sq = 0.f;
#pragma unroll
    for (int i = 0; i < 7; i++) {
        y[i] -= mean;
        sq += y[i] * y[i];
    }
#pragma unroll
    for (int o = 16; o > 0; o >>= 1) sq += __shfl_xor_sync(0xffffffffu, sq, o);
    float inv = rsqrtf(sq);
#pragma unroll
    for (int i = 0; i < 7; i++)
        Out[base + lane + i * 32] = __float2half_rn(y[i] * inv);
}

// ---------------------------------------------------------------------------
extern "C" void kernel_launch(void* const* d_in, const int* in_sizes, int n_in,
                              void* d_out, int out_size) {
    const float* cam_code  = (const float*)d_in[0];
    const float* proj_code = (const float*)d_in[1];
    const float* cam_w0 = (const float*)d_in[2];
    const float* cam_b0 = (const float*)d_in[3];
    const float* cam_w1 = (const float*)d_in[4];
    const float* cam_b1 = (const float*)d_in[5];
    const float* proj_w0 = (const float*)d_in[6];
    const float* proj_b0 = (const float*)d_in[7];
    const float* proj_w1 = (const float*)d_in[8];
    const float* proj_b1 = (const float*)d_in[9];
    float* out = (float*)d_out;

    __half *X, *Hc, *CH, *Pp, *Xp, *Hp, *W0c, *W1c, *W0p, *W1p;
    float *ST;
    cudaGetSymbolAddress((void**)&X,   g_X);
    cudaGetSymbolAddress((void**)&Hc,  g_Hc);
    cudaGetSymbolAddress((void**)&ST,  g_stats);
    cudaGetSymbolAddress((void**)&CH,  g_camh);
    cudaGetSymbolAddress((void**)&Pp,  g_Pp);
    cudaGetSymbolAddress((void**)&Xp,  g_Xp);
    cudaGetSymbolAddress((void**)&Hp,  g_Hp);
    cudaGetSymbolAddress((void**)&W0c, g_W0c);
    cudaGetSymbolAddress((void**)&W1c, g_W1c);
    cudaGetSymbolAddress((void**)&W0p, g_W0p);
    cudaGetSymbolAddress((void**)&W1p, g_W1p);

    cudaFuncSetAttribute(tgemm<11>,  cudaFuncAttributeMaxDynamicSharedMemorySize, SMEM_BYTES);
    cudaFuncSetAttribute(tgemm<13>,  cudaFuncAttributeMaxDynamicSharedMemorySize, SMEM_BYTES);
    cudaFuncSetAttribute(tgemm<157>, cudaFuncAttributeMaxDynamicSharedMemorySize, SMEM_BYTES);
    cudaFuncSetAttribute(tgemm<32>,  cudaFuncAttributeMaxDynamicSharedMemorySize, SMEM_BYTES);

    // 1) Preprocessing
    round_weights<<<(2 * F2 + 255) / 256, 256>>>(cam_w0, W0c, cam_w1, W1c,
                                                 proj_w0, W0p, proj_w1, W1p);
    round_cam<<<(NCAM + 255) / 256, 256>>>(cam_code, CH);
    build_pproj<<<(S_PROJ * FEAT + 255) / 256, 256>>>(proj_code, Pp);

    const int TC = S_CAM / 128;   // 1024
    const int TP = S_PROJ / 128;  // 8
    dim3 gmlp((FEAT + 127) / 128, TC + TP);

    GArg c0, p0;
    // layer 0, GEMM 0: H = relu(P @ W0^T + b0); cam P gathered from g_camh
    c0 = {nullptr, W0c, nullptr, nullptr, CH, cam_b0, Hc, nullptr,
          S_CAM,  FEAT, 1, 0, 0};
    p0 = {Pp,      W0p, nullptr, nullptr, nullptr, proj_b0, Hp, nullptr,
          S_PROJ, FEAT, 0, 0, 0};
    tgemm<11><<<gmlp, 256, SMEM_BYTES>>>(c0, p0, nullptr, FEAT);

    // layer 0, GEMM 1: X = P + H @ W1^T + b1  (cam residual staged gather)
    c0 = {Hc, W1c, nullptr, nullptr, CH, cam_b1, X, nullptr,
          S_CAM,  FEAT, 0, 1, 0};
    p0 = {Hp, W1p, Pp,      nullptr, nullptr, proj_b1, Xp, nullptr,
          S_PROJ, FEAT, 0, 0, 0};
    tgemm<13><<<gmlp, 256, SMEM_BYTES>>>(c0, p0, nullptr, FEAT);

    // layer 1, GEMM 0: H = relu(X @ W0^T + b0)
    c0 = {X,  W0c + F2, nullptr, nullptr, nullptr, cam_b0 + FEAT,  Hc, nullptr,
          S_CAM,  FEAT, 0, 0, 0};
    p0 = {Xp, W0p + F2, nullptr, nullptr, nullptr, proj_b0 + FEAT, Hp, nullptr,
          S_PROJ, FEAT, 0, 0, 0};
    tgemm<11><<<gmlp, 256, SMEM_BYTES>>>(c0, p0, nullptr, FEAT);

    // layer 1, GEMM 1: Y = X + H @ W1^T + b1 + P  (+ per-row stats, cam)
    c0 = {Hc, W1c + F2, X,  nullptr, CH, cam_b1 + FEAT,  X,  ST,
          S_CAM,  FEAT, 0, 0, 1};
    p0 = {Hp, W1p + F2, Xp, Pp,      nullptr, proj_b1 + FEAT, Xp, nullptr,
          S_PROJ, FEAT, 0, 0, 0};
    tgemm<157><<<gmlp, 256, SMEM_BYTES>>>(c0, p0, nullptr, FEAT);

    // 3) Proj normalize (cam stats already emitted by tgemm<157>)
    normalize_proj<<<(S_PROJ + 7) / 8, 256>>>(Xp, Hp, S_PROJ);

    // 4) ZNCC correlation: out[s,m] = inv_a[s] * (Y[s,:] . Bnorm[m,:])
    dim3 gfin(W_PAT / 128, TC);
    GArg f0 = {X, Hp, nullptr, nullptr, nullptr, nullptr, out, nullptr,
               S_CAM, W_PAT, 0, 0, 0};
    tgemm<32><<<gfin, 256, SMEM_BYTES>>>(f0, f0, ST, FEAT);
}

// round 10
// speedup vs baseline: 6.1390x; 1.0128x over previous
#include <cuda_runtime.h>
#include <cuda_fp16.h>
#include <cstdint>

// Problem constants
#define FEAT   224
#define NPAT   32
#define H_IMG  256
#define W_IMG  512
#define W_PAT  1024
#define S_CAM  (H_IMG * W_IMG)   // 131072
#define S_PROJ W_PAT             // 1024
#define F2     (FEAT * FEAT)
#define NCAM   (H_IMG * W_IMG * NPAT)   // 4194304

// Scratch (device globals) — all GEMM operands fp16
__device__ __half g_X    [S_CAM * FEAT];   // cam running x / final Y
__device__ __half g_Hc   [S_CAM * FEAT];   // cam hidden
__device__ float  g_stats[S_CAM * 4];      // per-row {s,q} x 2 N-tiles
__device__ __half g_camh [NCAM];           // fp16-rounded cam_code
__device__ __half g_Pp   [S_PROJ * FEAT];  // proj p
__device__ __half g_Xp   [S_PROJ * FEAT];  // proj running x / Yp
__device__ __half g_Hp   [S_PROJ * FEAT];  // proj hidden / Bnorm
__device__ __half g_W0c  [2 * F2];
__device__ __half g_W1c  [2 * F2];
__device__ __half g_W0p  [2 * F2];
__device__ __half g_W1p  [2 * F2];

// ---------------------------------------------------------------------------
// Helpers
// ---------------------------------------------------------------------------
__device__ __forceinline__ uint32_t smem_u32(const void* p) {
    uint32_t a;
    asm("{ .reg .u64 t; cvta.to.shared.u64 t, %1; cvt.u32.u64 %0, t; }"
        : "=r"(a) : "l"(p));
    return a;
}
__device__ __forceinline__ void cp16(uint32_t dst, const void* src) {
    asm volatile("cp.async.cg.shared.global [%0], [%1], 16;"
                 :: "r"(dst), "l"(src) : "memory");
}
__device__ __forceinline__ void cp_commit() {
    asm volatile("cp.async.commit_group;" ::: "memory");
}
__device__ __forceinline__ void cp_wait3() {
    asm volatile("cp.async.wait_group 3;" ::: "memory");
}
__device__ __forceinline__ void cp_wait0() {
    asm volatile("cp.async.wait_group 0;" ::: "memory");
}

// ---------------------------------------------------------------------------
// Preprocessing kernels
// ---------------------------------------------------------------------------
__global__ void build_pproj(const float* __restrict__ proj,
                            __half* __restrict__ P) {
    int idx = blockIdx.x * blockDim.x + threadIdx.x;
    if (idx >= S_PROJ * FEAT) return;
    int m = idx / FEAT;
    int f = idx - m * FEAT;
    int j = f / NPAT;
    int k = f - j * NPAT;
    int mp = m + j - 3;
    mp = mp < 0 ? 0 : (mp > W_PAT - 1 ? W_PAT - 1 : mp);
    P[idx] = __float2half_rn(proj[k * W_PAT + mp]);
}

__global__ void round_weights(const float* __restrict__ s0, __half* __restrict__ d0,
                              const float* __restrict__ s1, __half* __restrict__ d1,
                              const float* __restrict__ s2, __half* __restrict__ d2,
                              const float* __restrict__ s3, __half* __restrict__ d3) {
    int i = blockIdx.x * blockDim.x + threadIdx.x;
    if (i >= 2 * F2) return;
    d0[i] = __float2half_rn(s0[i]);
    d1[i] = __float2half_rn(s1[i]);
    d2[i] = __float2half_rn(s2[i]);
    d3[i] = __float2half_rn(s3[i]);
}

__global__ void round_cam(const float* __restrict__ src, __half* __restrict__ dst) {
    int i = blockIdx.x * blockDim.x + threadIdx.x;
    if (i < NCAM) dst[i] = __float2half_rn(src[i]);
}

// ---------------------------------------------------------------------------
// FP16 mma.sync m16n8k16 GEMM (fp32 accumulate), cp.async 5-stage pipeline
// (4 chunks in flight -> ~600+ cyc latency cover) + ldmatrix.
// Stage layout: 128 rows x 128 B; row r = [A chunk 64B | B chunk 64B],
// granule (16B) position = g ^ (r&7)  -> LDSM conflict-free.
// MODE bits: 1 +bias, 2 relu, 4 +Res, 8 store half (else fp32),
//            16 +Res2, 32 row-scale from stats, 128 emit per-row stats.
// ---------------------------------------------------------------------------
#define BK        32                       // K elements (halves) per chunk
#define ST_BYTES  16384                    // 128 rows x 128 B
#define NSTAGE    5
#define NPRO      4                        // prologue depth (< nch = 7)
#define STAT_BYTE (NSTAGE * ST_BYTES)      // 81920
#define SMEM_BYTES (STAT_BYTE + 1024)      // 82944
#define GS        136                      // staged residual row stride (halves)

struct GArg {
    const __half *A, *W, *Res, *Res2, *camA;
    const float *bias;
    void *C;                // __half* (MODE&8) or float*
    float *stats;
    int M, N;
    int agather, resgather, res2gather;
};

template <int MODE>
__global__ void __launch_bounds__(256, 2)
tgemm(GArg a0, GArg a1, const float* __restrict__ statsin, int K) {
    extern __shared__ char smc[];
    __half* smh = (__half*)smc;
    float* smstat = (float*)(smc + STAT_BYTE);
    const uint32_t sb = smem_u32(smc);

    const int t    = threadIdx.x;
    const int lane = t & 31;
    const int wid  = t >> 5;
    const int wm   = wid & 1;
    const int wn   = wid >> 1;
    const int n0   = blockIdx.x * 128;
    const int nch  = K / BK;     // 7

    const int tiles0 = a0.M >> 7;
    GArg g;
    int m0;
    if ((int)blockIdx.y < tiles0) { g = a0; m0 = blockIdx.y * 128; }
    else                          { g = a1; m0 = (blockIdx.y - tiles0) * 128; }
    const int N = g.N;

    if (MODE & 128) {
        if (t < 256) smstat[t] = 0.f;
    }

    // --- loader mapping: 2 A granules + 2 B granules per thread per chunk ---
    const __half* AsrcB[2];
    const __half* BsrcB[2];
    int wbA[2];
    uint32_t AdstB[2], BdstB[2];
#pragma unroll
    for (int i = 0; i < 2; i++) {
        int idx = t + 256 * i;      // 0..511
        int r = idx >> 2;           // 0..127
        int gq = idx & 3;           // granule within 64B
        int s = m0 + r;
        if (g.agather) {
            wbA[i]   = s & (W_IMG - 1);
            AsrcB[i] = g.camA + ((size_t)(s & ~(W_IMG - 1)) << 5) + gq * 8;
        } else {
            wbA[i]   = 0;
            AsrcB[i] = g.A + (size_t)s * K + gq * 8;
        }
        int br = n0 + r; if (br > N - 1) br = N - 1;
        BsrcB[i] = g.W + (size_t)br * K + gq * 8;
        AdstB[i] = sb + (uint32_t)r * 128 + (((uint32_t)gq       ^ (r & 7)) << 4);
        BdstB[i] = sb + (uint32_t)r * 128 + (((uint32_t)(gq + 4) ^ (r & 7)) << 4);
    }

    auto loadAB = [&](int ch, int sl) {
        uint32_t so = (uint32_t)sl * ST_BYTES;
#pragma unroll
        for (int i = 0; i < 2; i++) {
            const __half* src;
            if (g.agather) {
                int wc = wbA[i] + ch - 3;
                wc = wc < 0 ? 0 : (wc > W_IMG - 1 ? W_IMG - 1 : wc);
                src = AsrcB[i] + (size_t)wc * NPAT;
            } else {
                src = AsrcB[i] + (size_t)ch * BK;
            }
            cp16(AdstB[i] + so, src);
            cp16(BdstB[i] + so, BsrcB[i] + (size_t)ch * BK);
        }
    };

    // --- ldmatrix lane mappings ---
    const int a_roff = (((lane >> 3) & 1) << 3) + (lane & 7);
    const int a_kb   = lane >> 4;            // k granule +0/+1
    const int b_roff = (((lane >> 4) & 1) << 3) + (lane & 7);
    const int b_kb   = (lane >> 3) & 1;

    float c[4][4][4];
#pragma unroll
    for (int i = 0; i < 4; i++)
#pragma unroll
        for (int j = 0; j < 4; j++)
#pragma unroll
            for (int r = 0; r < 4; r++) c[i][j][r] = 0.0f;

    // --- prologue: 4 chunks in flight ---
#pragma unroll
    for (int s = 0; s < NPRO; s++) {
        loadAB(s, s);
        cp_commit();
    }

    for (int ch = 0; ch < nch; ch++) {
        cp_wait3();          // oldest outstanding group (= chunk ch) landed
        __syncthreads();     // visibility + slot-reuse ordering
        if (ch + NPRO < nch) loadAB(ch + NPRO, (ch + NPRO) % NSTAGE);
        cp_commit();

        const uint32_t st_b = sb + (uint32_t)(ch % NSTAGE) * ST_BYTES;

#pragma unroll
        for (int ks = 0; ks < 2; ks++) {      // two k16 steps per 32-chunk
            uint32_t af[4][4];
#pragma unroll
            for (int mf = 0; mf < 4; mf++) {
                int row = wm * 64 + mf * 16 + a_roff;
                int gk  = 2 * ks + a_kb;      // A granule 0..3
                uint32_t addr = st_b + (uint32_t)row * 128 +
                                (((uint32_t)gk ^ (row & 7)) << 4);
                asm volatile(
                    "ldmatrix.sync.aligned.m8n8.x4.shared.b16 {%0,%1,%2,%3}, [%4];"
                    : "=r"(af[mf][0]), "=r"(af[mf][1]),
                      "=r"(af[mf][2]), "=r"(af[mf][3])
                    : "r"(addr));
            }
            uint32_t bf[4][2];
#pragma unroll
            for (int p = 0; p < 2; p++) {     // 2 nf per x4
                int row = wn * 32 + p * 16 + b_roff;
                int gk  = 4 + 2 * ks + b_kb;  // B granule 4..7
                uint32_t addr = st_b + (uint32_t)row * 128 +
                                (((uint32_t)gk ^ (row & 7)) << 4);
                asm volatile(
                    "ldmatrix.sync.aligned.m8n8.x4.shared.b16 {%0,%1,%2,%3}, [%4];"
                    : "=r"(bf[2 * p][0]), "=r"(bf[2 * p][1]),
                      "=r"(bf[2 * p + 1][0]), "=r"(bf[2 * p + 1][1])
                    : "r"(addr));
            }
#pragma unroll
            for (int mf = 0; mf < 4; mf++)
#pragma unroll
                for (int nf = 0; nf < 4; nf++) {
                    asm volatile(
                        "mma.sync.aligned.m16n8k16.row.col.f32.f16.f16.f32 "
                        "{%0,%1,%2,%3}, {%4,%5,%6,%7}, {%8,%9}, {%0,%1,%2,%3};"
                        : "+f"(c[mf][nf][0]), "+f"(c[mf][nf][1]),
                          "+f"(c[mf][nf][2]), "+f"(c[mf][nf][3])
                        : "r"(af[mf][0]), "r"(af[mf][1]),
                          "r"(af[mf][2]), "r"(af[mf][3]),
                          "r"(bf[nf][0]), "r"(bf[nf][1]));
                }
        }
    }

    // --- stage residual P-tile (fp16) into now-free pipeline smem ---
    const int dogather = ((MODE & 4) && g.resgather) ||
                         ((MODE & 16) && g.res2gather);
    if (dogather) {
        __syncthreads();
#pragma unroll
        for (int i = 0; i < 8; i++) {
            int idx = t + 256 * i;     // 2048 granules (128 rows x 16)
            int r   = idx >> 4;
            int q   = idx & 15;        // 8-half granule within row
            if (n0 + q * 8 < N) {
                int s  = m0 + r;
                int j  = (n0 >> 5) + (q >> 2);
                int wc = (s & (W_IMG - 1)) + j - 3;
                wc = wc < 0 ? 0 : (wc > W_IMG - 1 ? W_IMG - 1 : wc);
                const __half* src = g.camA +
                    (((size_t)(s & ~(W_IMG - 1)) + wc) << 5) + (q & 3) * 8;
                cp16(sb + (uint32_t)r * (GS * 2) + q * 16, src);
            }
        }
        cp_commit();
        cp_wait0();
        __syncthreads();
    }

    const int lq = lane >> 2;
    const int lr = lane & 3;

    float ss[8], qq[8];
    if (MODE & 128) {
#pragma unroll
        for (int e = 0; e < 8; e++) { ss[e] = 0.f; qq[e] = 0.f; }
    }

    // --- epilogue ---
#pragma unroll
    for (int mf = 0; mf < 4; mf++) {
        int row = m0 + wm * 64 + mf * 16 + lq;
        float inv0 = 1.f, inv1 = 1.f;
        if (MODE & 32) {
            float4 s0v = *(const float4*)(statsin + (size_t)row * 4);
            float4 s1v = *(const float4*)(statsin + (size_t)(row + 8) * 4);
            float sa = s0v.x + s0v.z, qa = s0v.y + s0v.w;
            float sb2 = s1v.x + s1v.z, qb = s1v.y + s1v.w;
            inv0 = rsqrtf(qa - sa * sa * (1.0f / FEAT));
            inv1 = rsqrtf(qb - sb2 * sb2 * (1.0f / FEAT));
        }
#pragma unroll
        for (int nf = 0; nf < 4; nf++) {
            int col = n0 + wn * 32 + nf * 8 + lr * 2;
            if (col < N) {
                float b0 = 0.f, b1 = 0.f;
                if (MODE & 1) { b0 = g.bias[col]; b1 = g.bias[col + 1]; }
#pragma unroll
                for (int half_ = 0; half_ < 2; half_++) {
                    int r = row + half_ * 8;
                    float v0 = c[mf][nf][half_ * 2 + 0];
                    float v1 = c[mf][nf][half_ * 2 + 1];
                    if (MODE & 1) { v0 += b0; v1 += b1; }
                    if (MODE & 2) { v0 = fmaxf(v0, 0.f); v1 = fmaxf(v1, 0.f); }
                    size_t o = (size_t)r * N + col;
                    if (MODE & 4) {
                        float2 rv;
                        if (g.resgather) {
                            rv = __half22float2(
                                *(const __half2*)(smh + (r - m0) * GS + (col - n0)));
                        } else {
                            rv = __half22float2(*(const __half2*)(g.Res + o));
                        }
                        v0 += rv.x; v1 += rv.y;
                    }
                    if (MODE & 16) {
                        float2 rv;
                        if (g.res2gather) {
                            rv = __half22float2(
                                *(const __half2*)(smh + (r - m0) * GS + (col - n0)));
                        } else {
                            rv = __half22float2(*(const __half2*)(g.Res2 + o));
                        }
                        v0 += rv.x; v1 += rv.y;
                    }
                    if (MODE & 32) {
                        float sc = half_ ? inv1 : inv0;
                        v0 *= sc; v1 *= sc;
                    }
                    if (MODE & 8) {
                        __half2 hv = __floats2half2_rn(v0, v1);
                        *((__half2*)((__half*)g.C + o)) = hv;
                        if (MODE & 128) {
                            float2 fr = __half22float2(hv);
                            v0 = fr.x; v1 = fr.y;
                        }
                    } else {
                        *((float2*)((float*)g.C + o)) = make_float2(v0, v1);
                    }
                    if (MODE & 128) {
                        int e = mf * 2 + half_;
                        ss[e] += v0 + v1;
                        qq[e] += v0 * v0 + v1 * v1;
                    }
                }
            }
        }
    }

    if (MODE & 128) {
#pragma unroll
        for (int e = 0; e < 8; e++) {
            ss[e] += __shfl_xor_sync(0xffffffffu, ss[e], 1);
            ss[e] += __shfl_xor_sync(0xffffffffu, ss[e], 2);
            qq[e] += __shfl_xor_sync(0xffffffffu, qq[e], 1);
            qq[e] += __shfl_xor_sync(0xffffffffu, qq[e], 2);
        }
        __syncthreads();
        if (lr == 0) {
#pragma unroll
            for (int e = 0; e < 8; e++) {
                int rl = wm * 64 + (e >> 1) * 16 + lq + (e & 1) * 8;
                atomicAdd(&smstat[rl * 2 + 0], ss[e]);
                atomicAdd(&smstat[rl * 2 + 1], qq[e]);
            }
        }
        __syncthreads();
        if (t < 128 && g.stats) {
            *(float2*)(g.stats + (size_t)(m0 + t) * 4 + blockIdx.x * 2) =
                make_float2(smstat[t * 2], smstat[t * 2 + 1]);
        }
    }
}

// ---------------------------------------------------------------------------
// Proj normalize: Bnorm[m,:] = (Y[m,:] - mean) / ||Y - mean||  (fp16 out)
// ---------------------------------------------------------------------------
__global__ void normalize_proj(const __half* __restrict__ Y,
                               __half* __restrict__ Out, int M) {
    int warp = (blockIdx.x * blockDim.x + threadIdx.x) >> 5;
    int lane = threadIdx.x & 31;
    if (warp >= M) return;
    size_t base = (size_t)warp * FEAT;
    float y[7];
    float sum = 0.f;
#pragma unroll
    for (int i = 0; i < 7; i++) {
        y[i] = __half2float(Y[base + lane + i * 32]);
        sum += y[i];
    }
#pragma unroll
    for (int o = 16; o > 0; o >>= 1) sum += __shfl_xor_sync(0xffffffffu, sum, o);
    float mean = sum * (1.0f / FEAT);
    float sq = 0.f;
#pragma unroll
    for (int i = 0; i < 7; i++) {
        y[i] -= mean;
        sq += y[i] * y[i];
    }
#pragma unroll
    for (int o = 16; o > 0; o >>= 1) sq += __shfl_xor_sync(0xffffffffu, sq, o);
    float inv = rsqrtf(sq);
#pragma unroll
    for (int i = 0; i < 7; i++)
        Out[base + lane + i * 32] = __float2half_rn(y[i] * inv);
}

// ---------------------------------------------------------------------------
extern "C" void kernel_launch(void* const* d_in, const int* in_sizes, int n_in,
                              void* d_out, int out_size) {
    const float* cam_code  = (const float*)d_in[0];
    const float* proj_code = (const float*)d_in[1];
    const float* cam_w0 = (const float*)d_in[2];
    const float* cam_b0 = (const float*)d_in[3];
    const float* cam_w1 = (const float*)d_in[4];
    const float* cam_b1 = (const float*)d_in[5];
    const float* proj_w0 = (const float*)d_in[6];
    const float* proj_b0 = (const float*)d_in[7];
    const float* proj_w1 = (const float*)d_in[8];
    const float* proj_b1 = (const float*)d_in[9];
    float* out = (float*)d_out;

    __half *X, *Hc, *CH, *Pp, *Xp, *Hp, *W0c, *W1c, *W0p, *W1p;
    float *ST;
    cudaGetSymbolAddress((void**)&X,   g_X);
    cudaGetSymbolAddress((void**)&Hc,  g_Hc);
    cudaGetSymbolAddress((void**)&ST,  g_stats);
    cudaGetSymbolAddress((void**)&CH,  g_camh);
    cudaGetSymbolAddress((void**)&Pp,  g_Pp);
    cudaGetSymbolAddress((void**)&Xp,  g_Xp);
    cudaGetSymbolAddress((void**)&Hp,  g_Hp);
    cudaGetSymbolAddress((void**)&W0c, g_W0c);
    cudaGetSymbolAddress((void**)&W1c, g_W1c);
    cudaGetSymbolAddress((void**)&W0p, g_W0p);
    cudaGetSymbolAddress((void**)&W1p, g_W1p);

    cudaFuncSetAttribute(tgemm<11>,  cudaFuncAttributeMaxDynamicSharedMemorySize, SMEM_BYTES);
    cudaFuncSetAttribute(tgemm<13>,  cudaFuncAttributeMaxDynamicSharedMemorySize, SMEM_BYTES);
    cudaFuncSetAttribute(tgemm<157>, cudaFuncAttributeMaxDynamicSharedMemorySize, SMEM_BYTES);
    cudaFuncSetAttribute(tgemm<32>,  cudaFuncAttributeMaxDynamicSharedMemorySize, SMEM_BYTES);

    // 1) Preprocessing
    round_weights<<<(2 * F2 + 255) / 256, 256>>>(cam_w0, W0c, cam_w1, W1c,
                                                 proj_w0, W0p, proj_w1, W1p);
    round_cam<<<(NCAM + 255) / 256, 256>>>(cam_code, CH);
    build_pproj<<<(S_PROJ * FEAT + 255) / 256, 256>>>(proj_code, Pp);

    const int TC = S_CAM / 128;   // 1024
    const int TP = S_PROJ / 128;  // 8
    dim3 gmlp((FEAT + 127) / 128, TC + TP);

    GArg c0, p0;
    // layer 0, GEMM 0: H = relu(P @ W0^T + b0); cam P gathered from g_camh
    c0 = {nullptr, W0c, nullptr, nullptr, CH, cam_b0, Hc, nullptr,
          S_CAM,  FEAT, 1, 0, 0};
    p0 = {Pp,      W0p, nullptr, nullptr, nullptr, proj_b0, Hp, nullptr,
          S_PROJ, FEAT, 0, 0, 0};
    tgemm<11><<<gmlp, 256, SMEM_BYTES>>>(c0, p0, nullptr, FEAT);

    // layer 0, GEMM 1: X = P + H @ W1^T + b1  (cam residual staged gather)
    c0 = {Hc, W1c, nullptr, nullptr, CH, cam_b1, X, nullptr,
          S_CAM,  FEAT, 0, 1, 0};
    p0 = {Hp, W1p, Pp,      nullptr, nullptr, proj_b1, Xp, nullptr,
          S_PROJ, FEAT, 0, 0, 0};
    tgemm<13><<<gmlp, 256, SMEM_BYTES>>>(c0, p0, nullptr, FEAT);

    // layer 1, GEMM 0: H = relu(X @ W0^T + b0)
    c0 = {X,  W0c + F2, nullptr, nullptr, nullptr, cam_b0 + FEAT,  Hc, nullptr,
          S_CAM,  FEAT, 0, 0, 0};
    p0 = {Xp, W0p + F2, nullptr, nullptr, nullptr, proj_b0 + FEAT, Hp, nullptr,
          S_PROJ, FEAT, 0, 0, 0};
    tgemm<11><<<gmlp, 256, SMEM_BYTES>>>(c0, p0, nullptr, FEAT);

    // layer 1, GEMM 1: Y = X + H @ W1^T + b1 + P  (+ per-row stats, cam)
    c0 = {Hc, W1c + F2, X,  nullptr, CH, cam_b1 + FEAT,  X,  ST,
          S_CAM,  FEAT, 0, 0, 1};
    p0 = {Hp, W1p + F2, Xp, Pp,      nullptr, proj_b1 + FEAT, Xp, nullptr,
          S_PROJ, FEAT, 0, 0, 0};
    tgemm<157><<<gmlp, 256, SMEM_BYTES>>>(c0, p0, nullptr, FEAT);

    // 3) Proj normalize (cam stats already emitted by tgemm<157>)
    normalize_proj<<<(S_PROJ + 7) / 8, 256>>>(Xp, Hp, S_PROJ);

    // 4) ZNCC correlation: out[s,m] = inv_a[s] * (Y[s,:] . Bnorm[m,:])
    dim3 gfin(W_PAT / 128, TC);
    GArg f0 = {X, Hp, nullptr, nullptr, nullptr, nullptr, out, nullptr,
               S_CAM, W_PAT, 0, 0, 0};
    tgemm<32><<<gfin, 256, SMEM_BYTES>>>(f0, f0, ST, FEAT);
}

// round 11
// speedup vs baseline: 6.1462x; 1.0012x over previous
#include <cuda_runtime.h>
#include <cuda_fp16.h>
#include <cstdint>

// Problem constants
#define FEAT   224
#define NPAT   32
#define H_IMG  256
#define W_IMG  512
#define W_PAT  1024
#define S_CAM  (H_IMG * W_IMG)   // 131072
#define S_PROJ W_PAT             // 1024
#define F2     (FEAT * FEAT)
#define NCAM   (H_IMG * W_IMG * NPAT)   // 4194304

// Scratch (device globals) — all GEMM operands fp16
__device__ __half g_X    [S_CAM * FEAT];   // cam running x / final Y
__device__ __half g_Hc   [S_CAM * FEAT];   // cam hidden
__device__ float  g_stats[S_CAM * 4];      // per-row {s,q} x 2 N-tiles
__device__ __half g_camh [NCAM];           // fp16-rounded cam_code
__device__ __half g_Pp   [S_PROJ * FEAT];  // proj p
__device__ __half g_Xp   [S_PROJ * FEAT];  // proj running x / Yp
__device__ __half g_Hp   [S_PROJ * FEAT];  // proj hidden / Bnorm
__device__ __half g_W0c  [2 * F2];
__device__ __half g_W1c  [2 * F2];
__device__ __half g_W0p  [2 * F2];
__device__ __half g_W1p  [2 * F2];

// ---------------------------------------------------------------------------
// Helpers
// ---------------------------------------------------------------------------
__device__ __forceinline__ uint32_t smem_u32(const void* p) {
    uint32_t a;
    asm("{ .reg .u64 t; cvta.to.shared.u64 t, %1; cvt.u32.u64 %0, t; }"
        : "=r"(a) : "l"(p));
    return a;
}
__device__ __forceinline__ void cp16(uint32_t dst, const void* src) {
    asm volatile("cp.async.cg.shared.global [%0], [%1], 16;"
                 :: "r"(dst), "l"(src) : "memory");
}
__device__ __forceinline__ void cp_commit() {
    asm volatile("cp.async.commit_group;" ::: "memory");
}
__device__ __forceinline__ void cp_wait1() {
    asm volatile("cp.async.wait_group 1;" ::: "memory");
}
__device__ __forceinline__ void cp_wait0() {
    asm volatile("cp.async.wait_group 0;" ::: "memory");
}

// ---------------------------------------------------------------------------
// Preprocessing kernels
// ---------------------------------------------------------------------------
__global__ void build_pproj(const float* __restrict__ proj,
                            __half* __restrict__ P) {
    int idx = blockIdx.x * blockDim.x + threadIdx.x;
    if (idx >= S_PROJ * FEAT) return;
    int m = idx / FEAT;
    int f = idx - m * FEAT;
    int j = f / NPAT;
    int k = f - j * NPAT;
    int mp = m + j - 3;
    mp = mp < 0 ? 0 : (mp > W_PAT - 1 ? W_PAT - 1 : mp);
    P[idx] = __float2half_rn(proj[k * W_PAT + mp]);
}

__global__ void round_weights(const float* __restrict__ s0, __half* __restrict__ d0,
                              const float* __restrict__ s1, __half* __restrict__ d1,
                              const float* __restrict__ s2, __half* __restrict__ d2,
                              const float* __restrict__ s3, __half* __restrict__ d3) {
    int i = blockIdx.x * blockDim.x + threadIdx.x;
    if (i >= 2 * F2) return;
    d0[i] = __float2half_rn(s0[i]);
    d1[i] = __float2half_rn(s1[i]);
    d2[i] = __float2half_rn(s2[i]);
    d3[i] = __float2half_rn(s3[i]);
}

__global__ void round_cam(const float* __restrict__ src, __half* __restrict__ dst) {
    int i = blockIdx.x * blockDim.x + threadIdx.x;
    if (i < NCAM) dst[i] = __float2half_rn(src[i]);
}

// ---------------------------------------------------------------------------
// FP16 mma.sync m16n8k16 GEMM (fp32 accumulate), cp.async pipeline with
// TWO chunks per barrier (6 slots, paired commit groups) + ldmatrix.
// Stage layout: 128 rows x 128 B; row r = [A chunk 64B | B chunk 64B],
// granule (16B) position = g ^ (r&7)  -> LDSM conflict-free.
// MODE bits: 1 +bias, 2 relu, 4 +Res, 8 store half (else fp32),
//            16 +Res2, 32 row-scale from stats, 128 emit per-row stats.
// ---------------------------------------------------------------------------
#define BK        32                       // K halves per chunk
#define ST_BYTES  16384                    // 128 rows x 128 B
#define NSTAGE    6
#define STAT_BYTE (NSTAGE * ST_BYTES)      // 98304
#define SMEM_BYTES (STAT_BYTE + 1024)      // 99328
#define GS        136                      // staged residual row stride (halves)

struct GArg {
    const __half *A, *W, *Res, *Res2, *camA;
    const float *bias;
    void *C;                // __half* (MODE&8) or float*
    float *stats;
    int M, N;
    int agather, resgather, res2gather;
};

template <int MODE>
__global__ void __launch_bounds__(256, 2)
tgemm(GArg a0, GArg a1, const float* __restrict__ statsin, int K) {
    extern __shared__ char smc[];
    __half* smh = (__half*)smc;
    float* smstat = (float*)(smc + STAT_BYTE);
    const uint32_t sb = smem_u32(smc);

    const int t    = threadIdx.x;
    const int lane = t & 31;
    const int wid  = t >> 5;
    const int wm   = wid & 1;
    const int wn   = wid >> 1;
    const int n0   = blockIdx.x * 128;
    const int nch  = K / BK;     // 7
    const int nit  = (nch + 1) >> 1;   // 4 barrier iterations

    const int tiles0 = a0.M >> 7;
    GArg g;
    int m0;
    if ((int)blockIdx.y < tiles0) { g = a0; m0 = blockIdx.y * 128; }
    else                          { g = a1; m0 = (blockIdx.y - tiles0) * 128; }
    const int N = g.N;

    if (MODE & 128) {
        if (t < 256) smstat[t] = 0.f;
    }

    // --- loader mapping: 2 A granules + 2 B granules per thread per chunk ---
    const __half* AsrcB[2];
    const __half* BsrcB[2];
    int wbA[2];
    uint32_t AdstB[2], BdstB[2];
#pragma unroll
    for (int i = 0; i < 2; i++) {
        int idx = t + 256 * i;      // 0..511
        int r = idx >> 2;           // 0..127
        int gq = idx & 3;           // granule within 64B
        int s = m0 + r;
        if (g.agather) {
            wbA[i]   = s & (W_IMG - 1);
            AsrcB[i] = g.camA + ((size_t)(s & ~(W_IMG - 1)) << 5) + gq * 8;
        } else {
            wbA[i]   = 0;
            AsrcB[i] = g.A + (size_t)s * K + gq * 8;
        }
        int br = n0 + r; if (br > N - 1) br = N - 1;
        BsrcB[i] = g.W + (size_t)br * K + gq * 8;
        AdstB[i] = sb + (uint32_t)r * 128 + (((uint32_t)gq       ^ (r & 7)) << 4);
        BdstB[i] = sb + (uint32_t)r * 128 + (((uint32_t)(gq + 4) ^ (r & 7)) << 4);
    }

    auto loadAB = [&](int ch) {
        uint32_t so = (uint32_t)(ch % NSTAGE) * ST_BYTES;
#pragma unroll
        for (int i = 0; i < 2; i++) {
            const __half* src;
            if (g.agather) {
                int wc = wbA[i] + ch - 3;
                wc = wc < 0 ? 0 : (wc > W_IMG - 1 ? W_IMG - 1 : wc);
                src = AsrcB[i] + (size_t)wc * NPAT;
            } else {
                src = AsrcB[i] + (size_t)ch * BK;
            }
            cp16(AdstB[i] + so, src);
            cp16(BdstB[i] + so, BsrcB[i] + (size_t)ch * BK);
        }
    };

    // --- ldmatrix lane mappings ---
    const int a_roff = (((lane >> 3) & 1) << 3) + (lane & 7);
    const int a_kb   = lane >> 4;            // k granule +0/+1
    const int b_roff = (((lane >> 4) & 1) << 3) + (lane & 7);
    const int b_kb   = (lane >> 3) & 1;

    float c[4][4][4];
#pragma unroll
    for (int i = 0; i < 4; i++)
#pragma unroll
        for (int j = 0; j < 4; j++)
#pragma unroll
            for (int r = 0; r < 4; r++) c[i][j][r] = 0.0f;

    // chunk compute body (two k16 steps)
    auto do_chunk = [&](int ch) {
        const uint32_t st_b = sb + (uint32_t)(ch % NSTAGE) * ST_BYTES;
#pragma unroll
        for (int ks = 0; ks < 2; ks++) {
            uint32_t af[4][4];
#pragma unroll
            for (int mf = 0; mf < 4; mf++) {
                int row = wm * 64 + mf * 16 + a_roff;
                int gk  = 2 * ks + a_kb;
                uint32_t addr = st_b + (uint32_t)row * 128 +
                                (((uint32_t)gk ^ (row & 7)) << 4);
                asm volatile(
                    "ldmatrix.sync.aligned.m8n8.x4.shared.b16 {%0,%1,%2,%3}, [%4];"
                    : "=r"(af[mf][0]), "=r"(af[mf][1]),
                      "=r"(af[mf][2]), "=r"(af[mf][3])
                    : "r"(addr));
            }
            uint32_t bf[4][2];
#pragma unroll
            for (int p = 0; p < 2; p++) {
                int row = wn * 32 + p * 16 + b_roff;
                int gk  = 4 + 2 * ks + b_kb;
                uint32_t addr = st_b + (uint32_t)row * 128 +
                                (((uint32_t)gk ^ (row & 7)) << 4);
                asm volatile(
                    "ldmatrix.sync.aligned.m8n8.x4.shared.b16 {%0,%1,%2,%3}, [%4];"
                    : "=r"(bf[2 * p][0]), "=r"(bf[2 * p][1]),
                      "=r"(bf[2 * p + 1][0]), "=r"(bf[2 * p + 1][1])
                    : "r"(addr));
            }
#pragma unroll
            for (int mf = 0; mf < 4; mf++)
#pragma unroll
                for (int nf = 0; nf < 4; nf++) {
                    asm volatile(
                        "mma.sync.aligned.m16n8k16.row.col.f32.f16.f16.f32 "
                        "{%0,%1,%2,%3}, {%4,%5,%6,%7}, {%8,%9}, {%0,%1,%2,%3};"
                        : "+f"(c[mf][nf][0]), "+f"(c[mf][nf][1]),
                          "+f"(c[mf][nf][2]), "+f"(c[mf][nf][3])
                        : "r"(af[mf][0]), "r"(af[mf][1]),
                          "r"(af[mf][2]), "r"(af[mf][3]),
                          "r"(bf[nf][0]), "r"(bf[nf][1]));
                }
        }
    };

    // --- prologue: chunks 0..3 as two paired commit groups ---
    loadAB(0); if (1 < nch) loadAB(1);
    cp_commit();
    if (2 < nch) { loadAB(2); if (3 < nch) loadAB(3); }
    cp_commit();

    // --- mainloop: 2 chunks per barrier ---
    for (int it = 0; it < nit; it++) {
        const int c0 = 2 * it;
        const int c1 = c0 + 1;
        if (it + 1 < nit) cp_wait1(); else cp_wait0();
        __syncthreads();     // visibility + slot-reuse ordering
        const int c4 = c0 + 4;
        if (c4 < nch) {
            loadAB(c4);
            if (c4 + 1 < nch) loadAB(c4 + 1);
            cp_commit();
        }
        do_chunk(c0);
        if (c1 < nch) do_chunk(c1);
    }

    // --- stage residual P-tile (fp16) into now-free pipeline smem ---
    const int dogather = ((MODE & 4) && g.resgather) ||
                         ((MODE & 16) && g.res2gather);
    if (dogather) {
        __syncthreads();
#pragma unroll
        for (int i = 0; i < 8; i++) {
            int idx = t + 256 * i;     // 2048 granules (128 rows x 16)
            int r   = idx >> 4;
            int q   = idx & 15;        // 8-half granule within row
            if (n0 + q * 8 < N) {
                int s  = m0 + r;
                int j  = (n0 >> 5) + (q >> 2);
                int wc = (s & (W_IMG - 1)) + j - 3;
                wc = wc < 0 ? 0 : (wc > W_IMG - 1 ? W_IMG - 1 : wc);
                const __half* src = g.camA +
                    (((size_t)(s & ~(W_IMG - 1)) + wc) << 5) + (q & 3) * 8;
                cp16(sb + (uint32_t)r * (GS * 2) + q * 16, src);
            }
        }
        cp_commit();
        cp_wait0();
        __syncthreads();
    }

    const int lq = lane >> 2;
    const int lr = lane & 3;

    float ss[8], qq[8];
    if (MODE & 128) {
#pragma unroll
        for (int e = 0; e < 8; e++) { ss[e] = 0.f; qq[e] = 0.f; }
    }

    // --- epilogue ---
#pragma unroll
    for (int mf = 0; mf < 4; mf++) {
        int row = m0 + wm * 64 + mf * 16 + lq;
        float inv0 = 1.f, inv1 = 1.f;
        if (MODE & 32) {
            float4 s0v = *(const float4*)(statsin + (size_t)row * 4);
            float4 s1v = *(const float4*)(statsin + (size_t)(row + 8) * 4);
            float sa = s0v.x + s0v.z, qa = s0v.y + s0v.w;
            float sb2 = s1v.x + s1v.z, qb = s1v.y + s1v.w;
            inv0 = rsqrtf(qa - sa * sa * (1.0f / FEAT));
            inv1 = rsqrtf(qb - sb2 * sb2 * (1.0f / FEAT));
        }
#pragma unroll
        for (int nf = 0; nf < 4; nf++) {
            int col = n0 + wn * 32 + nf * 8 + lr * 2;
            if (col < N) {
                float b0 = 0.f, b1 = 0.f;
                if (MODE & 1) { b0 = g.bias[col]; b1 = g.bias[col + 1]; }
#pragma unroll
                for (int half_ = 0; half_ < 2; half_++) {
                    int r = row + half_ * 8;
                    float v0 = c[mf][nf][half_ * 2 + 0];
                    float v1 = c[mf][nf][half_ * 2 + 1];
                    if (MODE & 1) { v0 += b0; v1 += b1; }
                    if (MODE & 2) { v0 = fmaxf(v0, 0.f); v1 = fmaxf(v1, 0.f); }
                    size_t o = (size_t)r * N + col;
                    if (MODE & 4) {
                        float2 rv;
                        if (g.resgather) {
                            rv = __half22float2(
                                *(const __half2*)(smh + (r - m0) * GS + (col - n0)));
                        } else {
                            rv = __half22float2(*(const __half2*)(g.Res + o));
                        }
                        v0 += rv.x; v1 += rv.y;
                    }
                    if (MODE & 16) {
                        float2 rv;
                        if (g.res2gather) {
                            rv = __half22float2(
                                *(const __half2*)(smh + (r - m0) * GS + (col - n0)));
                        } else {
                            rv = __half22float2(*(const __half2*)(g.Res2 + o));
                        }
                        v0 += rv.x; v1 += rv.y;
                    }
                    if (MODE & 32) {
                        float sc = half_ ? inv1 : inv0;
                        v0 *= sc; v1 *= sc;
                    }
                    if (MODE & 8) {
                        __half2 hv = __floats2half2_rn(v0, v1);
                        *((__half2*)((__half*)g.C + o)) = hv;
                        if (MODE & 128) {
                            float2 fr = __half22float2(hv);
                            v0 = fr.x; v1 = fr.y;
                        }
                    } else {
                        *((float2*)((float*)g.C + o)) = make_float2(v0, v1);
                    }
                    if (MODE & 128) {
                        int e = mf * 2 + half_;
                        ss[e] += v0 + v1;
                        qq[e] += v0 * v0 + v1 * v1;
                    }
                }
            }
        }
    }

    if (MODE & 128) {
#pragma unroll
        for (int e = 0; e < 8; e++) {
            ss[e] += __shfl_xor_sync(0xffffffffu, ss[e], 1);
            ss[e] += __shfl_xor_sync(0xffffffffu, ss[e], 2);
            qq[e] += __shfl_xor_sync(0xffffffffu, qq[e], 1);
            qq[e] += __shfl_xor_sync(0xffffffffu, qq[e], 2);
        }
        __syncthreads();
        if (lr == 0) {
#pragma unroll
            for (int e = 0; e < 8; e++) {
                int rl = wm * 64 + (e >> 1) * 16 + lq + (e & 1) * 8;
                atomicAdd(&smstat[rl * 2 + 0], ss[e]);
                atomicAdd(&smstat[rl * 2 + 1], qq[e]);
            }
        }
        __syncthreads();
        if (t < 128 && g.stats) {
            *(float2*)(g.stats + (size_t)(m0 + t) * 4 + blockIdx.x * 2) =
                make_float2(smstat[t * 2], smstat[t * 2 + 1]);
        }
    }
}

// ---------------------------------------------------------------------------
// Proj normalize: Bnorm[m,:] = (Y[m,:] - mean) / ||Y - mean||  (fp16 out)
// ---------------------------------------------------------------------------
__global__ void normalize_proj(const __half* __restrict__ Y,
                               __half* __restrict__ Out, int M) {
    int warp = (blockIdx.x * blockDim.x + threadIdx.x) >> 5;
    int lane = threadIdx.x & 31;
    if (warp >= M) return;
    size_t base = (size_t)warp * FEAT;
    float y[7];
    float sum = 0.f;
#pragma unroll
    for (int i = 0; i < 7; i++) {
        y[i] = __half2float(Y[base + lane + i * 32]);
        sum += y[i];
    }
#pragma unroll
    for (int o = 16; o > 0; o >>= 1) sum += __shfl_xor_sync(0xffffffffu, sum, o);
    float mean = sum * (1.0f / FEAT);
    float sq = 0.f;
#pragma unroll
    for (int i = 0; i < 7; i++) {
        y[i] -= mean;
        sq += y[i] * y[i];
    }
#pragma unroll
    for (int o = 16; o > 0; o >>= 1) sq += __shfl_xor_sync(0xffffffffu, sq, o);
    float inv = rsqrtf(sq);
#pragma unroll
    for (int i = 0; i < 7; i++)
        Out[base + lane + i * 32] = __float2half_rn(y[i] * inv);
}

// ---------------------------------------------------------------------------
extern "C" void kernel_launch(void* const* d_in, const int* in_sizes, int n_in,
                              void* d_out, int out_size) {
    const float* cam_code  = (const float*)d_in[0];
    const float* proj_code = (const float*)d_in[1];
    const float* cam_w0 = (const float*)d_in[2];
    const float* cam_b0 = (const float*)d_in[3];
    const float* cam_w1 = (const float*)d_in[4];
    const float* cam_b1 = (const float*)d_in[5];
    const float* proj_w0 = (const float*)d_in[6];
    const float* proj_b0 = (const float*)d_in[7];
    const float* proj_w1 = (const float*)d_in[8];
    const float* proj_b1 = (const float*)d_in[9];
    float* out = (float*)d_out;

    __half *X, *Hc, *CH, *Pp, *Xp, *Hp, *W0c, *W1c, *W0p, *W1p;
    float *ST;
    cudaGetSymbolAddress((void**)&X,   g_X);
    cudaGetSymbolAddress((void**)&Hc,  g_Hc);
    cudaGetSymbolAddress((void**)&ST,  g_stats);
    cudaGetSymbolAddress((void**)&CH,  g_camh);
    cudaGetSymbolAddress((void**)&Pp,  g_Pp);
    cudaGetSymbolAddress((void**)&Xp,  g_Xp);
    cudaGetSymbolAddress((void**)&Hp,  g_Hp);
    cudaGetSymbolAddress((void**)&W0c, g_W0c);
    cudaGetSymbolAddress((void**)&W1c, g_W1c);
    cudaGetSymbolAddress((void**)&W0p, g_W0p);
    cudaGetSymbolAddress((void**)&W1p, g_W1p);

    cudaFuncSetAttribute(tgemm<11>,  cudaFuncAttributeMaxDynamicSharedMemorySize, SMEM_BYTES);
    cudaFuncSetAttribute(tgemm<13>,  cudaFuncAttributeMaxDynamicSharedMemorySize, SMEM_BYTES);
    cudaFuncSetAttribute(tgemm<157>, cudaFuncAttributeMaxDynamicSharedMemorySize, SMEM_BYTES);
    cudaFuncSetAttribute(tgemm<32>,  cudaFuncAttributeMaxDynamicSharedMemorySize, SMEM_BYTES);

    // 1) Preprocessing
    round_weights<<<(2 * F2 + 255) / 256, 256>>>(cam_w0, W0c, cam_w1, W1c,
                                                 proj_w0, W0p, proj_w1, W1p);
    round_cam<<<(NCAM + 255) / 256, 256>>>(cam_code, CH);
    build_pproj<<<(S_PROJ * FEAT + 255) / 256, 256>>>(proj_code, Pp);

    const int TC = S_CAM / 128;   // 1024
    const int TP = S_PROJ / 128;  // 8
    dim3 gmlp((FEAT + 127) / 128, TC + TP);

    GArg c0, p0;
    // layer 0, GEMM 0: H = relu(P @ W0^T + b0); cam P gathered from g_camh
    c0 = {nullptr, W0c, nullptr, nullptr, CH, cam_b0, Hc, nullptr,
          S_CAM,  FEAT, 1, 0, 0};
    p0 = {Pp,      W0p, nullptr, nullptr, nullptr, proj_b0, Hp, nullptr,
          S_PROJ, FEAT, 0, 0, 0};
    tgemm<11><<<gmlp, 256, SMEM_BYTES>>>(c0, p0, nullptr, FEAT);

    // layer 0, GEMM 1: X = P + H @ W1^T + b1  (cam residual staged gather)
    c0 = {Hc, W1c, nullptr, nullptr, CH, cam_b1, X, nullptr,
          S_CAM,  FEAT, 0, 1, 0};
    p0 = {Hp, W1p, Pp,      nullptr, nullptr, proj_b1, Xp, nullptr,
          S_PROJ, FEAT, 0, 0, 0};
    tgemm<13><<<gmlp, 256, SMEM_BYTES>>>(c0, p0, nullptr, FEAT);

    // layer 1, GEMM 0: H = relu(X @ W0^T + b0)
    c0 = {X,  W0c + F2, nullptr, nullptr, nullptr, cam_b0 + FEAT,  Hc, nullptr,
          S_CAM,  FEAT, 0, 0, 0};
    p0 = {Xp, W0p + F2, nullptr, nullptr, nullptr, proj_b0 + FEAT, Hp, nullptr,
          S_PROJ, FEAT, 0, 0, 0};
    tgemm<11><<<gmlp, 256, SMEM_BYTES>>>(c0, p0, nullptr, FEAT);

    // layer 1, GEMM 1: Y = X + H @ W1^T + b1 + P  (+ per-row stats, cam)
    c0 = {Hc, W1c + F2, X,  nullptr, CH, cam_b1 + FEAT,  X,  ST,
          S_CAM,  FEAT, 0, 0, 1};
    p0 = {Hp, W1p + F2, Xp, Pp,      nullptr, proj_b1 + FEAT, Xp, nullptr,
          S_PROJ, FEAT, 0, 0, 0};
    tgemm<157><<<gmlp, 256, SMEM_BYTES>>>(c0, p0, nullptr, FEAT);

    // 3) Proj normalize (cam stats already emitted by tgemm<157>)
    normalize_proj<<<(S_PROJ + 7) / 8, 256>>>(Xp, Hp, S_PROJ);

    // 4) ZNCC correlation: out[s,m] = inv_a[s] * (Y[s,:] . Bnorm[m,:])
    dim3 gfin(W_PAT / 128, TC);
    GArg f0 = {X, Hp, nullptr, nullptr, nullptr, nullptr, out, nullptr,
               S_CAM, W_PAT, 0, 0, 0};
    tgemm<32><<<gfin, 256, SMEM_BYTES>>>(f0, f0, ST, FEAT);
}

// round 12
// speedup vs baseline: 6.6243x; 1.0778x over previous
#include <cuda_runtime.h>
#include <cuda_fp16.h>
#include <cstdint>

// Problem constants
#define FEAT   224
#define NPAT   32
#define H_IMG  256
#define W_IMG  512
#define W_PAT  1024
#define S_CAM  (H_IMG * W_IMG)   // 131072
#define S_PROJ W_PAT             // 1024
#define F2     (FEAT * FEAT)
#define NCAM   (H_IMG * W_IMG * NPAT)   // 4194304

// Scratch (device globals) — all GEMM operands fp16
__device__ __half g_X    [S_CAM * FEAT];   // cam running x / final Y
__device__ __half g_Hc   [S_CAM * FEAT];   // cam hidden
__device__ float  g_stats[S_CAM * 4];      // per-row {s,q} x 2 N-tiles
__device__ __half g_camh [NCAM];           // fp16-rounded cam_code
__device__ __half g_Pp   [S_PROJ * FEAT];  // proj p
__device__ __half g_Xp   [S_PROJ * FEAT];  // proj running x / Yp
__device__ __half g_Hp   [S_PROJ * FEAT];  // proj hidden / Bnorm
__device__ __half g_W0c  [2 * F2];
__device__ __half g_W1c  [2 * F2];
__device__ __half g_W0p  [2 * F2];
__device__ __half g_W1p  [2 * F2];

// ---------------------------------------------------------------------------
// Helpers
// ---------------------------------------------------------------------------
__device__ __forceinline__ uint32_t smem_u32(const void* p) {
    uint32_t a;
    asm("{ .reg .u64 t; cvta.to.shared.u64 t, %1; cvt.u32.u64 %0, t; }"
        : "=r"(a) : "l"(p));
    return a;
}
__device__ __forceinline__ void cp16(uint32_t dst, const void* src) {
    asm volatile("cp.async.cg.shared.global [%0], [%1], 16;"
                 :: "r"(dst), "l"(src) : "memory");
}
__device__ __forceinline__ void cp_commit() {
    asm volatile("cp.async.commit_group;" ::: "memory");
}
__device__ __forceinline__ void cp_wait1() {
    asm volatile("cp.async.wait_group 1;" ::: "memory");
}
__device__ __forceinline__ void cp_wait0() {
    asm volatile("cp.async.wait_group 0;" ::: "memory");
}

// ---------------------------------------------------------------------------
// Preprocessing kernels
// ---------------------------------------------------------------------------
__global__ void build_pproj(const float* __restrict__ proj,
                            __half* __restrict__ P) {
    int idx = blockIdx.x * blockDim.x + threadIdx.x;
    if (idx >= S_PROJ * FEAT) return;
    int m = idx / FEAT;
    int f = idx - m * FEAT;
    int j = f / NPAT;
    int k = f - j * NPAT;
    int mp = m + j - 3;
    mp = mp < 0 ? 0 : (mp > W_PAT - 1 ? W_PAT - 1 : mp);
    P[idx] = __float2half_rn(proj[k * W_PAT + mp]);
}

__global__ void round_weights(const float* __restrict__ s0, __half* __restrict__ d0,
                              const float* __restrict__ s1, __half* __restrict__ d1,
                              const float* __restrict__ s2, __half* __restrict__ d2,
                              const float* __restrict__ s3, __half* __restrict__ d3) {
    int i = blockIdx.x * blockDim.x + threadIdx.x;
    if (i >= 2 * F2) return;
    d0[i] = __float2half_rn(s0[i]);
    d1[i] = __float2half_rn(s1[i]);
    d2[i] = __float2half_rn(s2[i]);
    d3[i] = __float2half_rn(s3[i]);
}

__global__ void round_cam(const float* __restrict__ src, __half* __restrict__ dst) {
    int i = blockIdx.x * blockDim.x + threadIdx.x;
    if (i < NCAM) dst[i] = __float2half_rn(src[i]);
}

// ---------------------------------------------------------------------------
// FP16 mma.sync m16n8k16 GEMM (fp32 accumulate).
// 128-thread CTAs, 4 warps as 2m x 2n, warp tile 64x64, 3 CTAs/SM.
// cp.async 3-stage pipeline + ldmatrix; stage = 128 rows x 128 B
// (row = [A 64B | B 64B], 16B granule g at position g ^ (r&7)).
// MODE bits: 1 +bias, 2 relu, 4 +Res, 8 store half (else fp32),
//            16 +Res2, 32 row-scale from stats, 128 emit per-row stats.
// ---------------------------------------------------------------------------
#define BK        32                       // K halves per chunk
#define ST_BYTES  16384                    // 128 rows x 128 B
#define NSTAGE    3
#define STAT_BYTE (NSTAGE * ST_BYTES)      // 49152
#define SMEM_BYTES (STAT_BYTE + 1024)      // 50176
#define GS        136                      // staged residual row stride (halves)

struct GArg {
    const __half *A, *W, *Res, *Res2, *camA;
    const float *bias;
    void *C;                // __half* (MODE&8) or float*
    float *stats;
    int M, N;
    int agather, resgather, res2gather;
};

template <int MODE>
__global__ void __launch_bounds__(128, 3)
tgemm(GArg a0, GArg a1, const float* __restrict__ statsin, int K) {
    extern __shared__ char smc[];
    __half* smh = (__half*)smc;
    float* smstat = (float*)(smc + STAT_BYTE);
    const uint32_t sb = smem_u32(smc);

    const int t    = threadIdx.x;
    const int lane = t & 31;
    const int wid  = t >> 5;     // 0..3
    const int wm   = wid & 1;    // 64-row slab
    const int wn   = wid >> 1;   // 64-col slab
    const int n0   = blockIdx.x * 128;
    const int nch  = K / BK;     // 7

    const int tiles0 = a0.M >> 7;
    GArg g;
    int m0;
    if ((int)blockIdx.y < tiles0) { g = a0; m0 = blockIdx.y * 128; }
    else                          { g = a1; m0 = (blockIdx.y - tiles0) * 128; }
    const int N = g.N;

    if (MODE & 128) {
        smstat[t] = 0.f;
        smstat[t + 128] = 0.f;
    }

    // --- loader mapping: 4 A granules + 4 B granules per thread per chunk ---
    // row block r0 + {0,32,64,96}; swizzle invariant across +32 (r&7 fixed).
    const int r0 = t >> 2;      // 0..31
    const int gq = t & 3;       // 16B granule within 64B
    const __half* Abase;
    int wb0 = 0;
    if (g.agather) {
        wb0   = (m0 & (W_IMG - 1)) + r0;
        Abase = g.camA + ((size_t)(m0 & ~(W_IMG - 1)) << 5) + gq * 8;
    } else {
        Abase = g.A + (size_t)(m0 + r0) * K + gq * 8;
    }
    const uint32_t Adst0 = sb + (uint32_t)r0 * 128 + (((uint32_t)gq       ^ (r0 & 7)) << 4);
    const uint32_t Bdst0 = sb + (uint32_t)r0 * 128 + (((uint32_t)(gq + 4) ^ (r0 & 7)) << 4);

    auto loadAB = [&](int ch) {
        uint32_t so = (uint32_t)(ch % NSTAGE) * ST_BYTES;
#pragma unroll
        for (int i = 0; i < 4; i++) {
            const __half* asrc;
            if (g.agather) {
                int wc = wb0 + 32 * i + ch - 3;
                wc = wc < 0 ? 0 : (wc > W_IMG - 1 ? W_IMG - 1 : wc);
                asrc = Abase + (size_t)wc * NPAT;
            } else {
                asrc = Abase + (size_t)(32 * i) * K + (size_t)ch * BK;
            }
            cp16(Adst0 + so + i * 4096, asrc);
            int br = n0 + r0 + 32 * i; if (br > N - 1) br = N - 1;
            cp16(Bdst0 + so + i * 4096,
                 g.W + (size_t)br * K + gq * 8 + (size_t)ch * BK);
        }
    };

    // --- ldmatrix lane mappings ---
    const int a_roff = (((lane >> 3) & 1) << 3) + (lane & 7);
    const int a_kb   = lane >> 4;            // k granule +0/+1
    const int b_roff = (((lane >> 4) & 1) << 3) + (lane & 7);
    const int b_kb   = (lane >> 3) & 1;

    float c[4][8][4];
#pragma unroll
    for (int i = 0; i < 4; i++)
#pragma unroll
        for (int j = 0; j < 8; j++)
#pragma unroll
            for (int r = 0; r < 4; r++) c[i][j][r] = 0.0f;

    auto do_chunk = [&](int ch) {
        const uint32_t st_b = sb + (uint32_t)(ch % NSTAGE) * ST_BYTES;
#pragma unroll
        for (int ks = 0; ks < 2; ks++) {
            uint32_t af[4][4];
#pragma unroll
            for (int mf = 0; mf < 4; mf++) {
                int row = wm * 64 + mf * 16 + a_roff;
                int gk  = 2 * ks + a_kb;
                uint32_t addr = st_b + (uint32_t)row * 128 +
                                (((uint32_t)gk ^ (row & 7)) << 4);
                asm volatile(
                    "ldmatrix.sync.aligned.m8n8.x4.shared.b16 {%0,%1,%2,%3}, [%4];"
                    : "=r"(af[mf][0]), "=r"(af[mf][1]),
                      "=r"(af[mf][2]), "=r"(af[mf][3])
                    : "r"(addr));
            }
#pragma unroll
            for (int p = 0; p < 4; p++) {    // 2 nf per x4 -> nf = 2p, 2p+1
                uint32_t bf0, bf1, bf2, bf3;
                int row = wn * 64 + p * 16 + b_roff;
                int gk  = 4 + 2 * ks + b_kb;
                uint32_t addr = st_b + (uint32_t)row * 128 +
                                (((uint32_t)gk ^ (row & 7)) << 4);
                asm volatile(
                    "ldmatrix.sync.aligned.m8n8.x4.shared.b16 {%0,%1,%2,%3}, [%4];"
                    : "=r"(bf0), "=r"(bf1), "=r"(bf2), "=r"(bf3)
                    : "r"(addr));
#pragma unroll
                for (int mf = 0; mf < 4; mf++) {
                    asm volatile(
                        "mma.sync.aligned.m16n8k16.row.col.f32.f16.f16.f32 "
                        "{%0,%1,%2,%3}, {%4,%5,%6,%7}, {%8,%9}, {%0,%1,%2,%3};"
                        : "+f"(c[mf][2 * p][0]), "+f"(c[mf][2 * p][1]),
                          "+f"(c[mf][2 * p][2]), "+f"(c[mf][2 * p][3])
                        : "r"(af[mf][0]), "r"(af[mf][1]),
                          "r"(af[mf][2]), "r"(af[mf][3]),
                          "r"(bf0), "r"(bf1));
                    asm volatile(
                        "mma.sync.aligned.m16n8k16.row.col.f32.f16.f16.f32 "
                        "{%0,%1,%2,%3}, {%4,%5,%6,%7}, {%8,%9}, {%0,%1,%2,%3};"
                        : "+f"(c[mf][2 * p + 1][0]), "+f"(c[mf][2 * p + 1][1]),
                          "+f"(c[mf][2 * p + 1][2]), "+f"(c[mf][2 * p + 1][3])
                        : "r"(af[mf][0]), "r"(af[mf][1]),
                          "r"(af[mf][2]), "r"(af[mf][3]),
                          "r"(bf2), "r"(bf3));
                }
            }
        }
    };

    // --- prologue ---
    loadAB(0); cp_commit();
    loadAB(1); cp_commit();

    // --- mainloop ---
    for (int ch = 0; ch < nch; ch++) {
        if (ch + 1 < nch) cp_wait1(); else cp_wait0();
        __syncthreads();     // visibility + slot-reuse ordering
        if (ch + 2 < nch) loadAB(ch + 2);
        cp_commit();
        do_chunk(ch);
    }

    // --- stage residual P-tile (fp16) into now-free pipeline smem ---
    const int dogather = ((MODE & 4) && g.resgather) ||
                         ((MODE & 16) && g.res2gather);
    if (dogather) {
        __syncthreads();
#pragma unroll
        for (int i = 0; i < 16; i++) {
            int idx = t + 128 * i;     // 2048 granules (128 rows x 16)
            int r   = idx >> 4;
            int q   = idx & 15;        // 8-half granule within row
            if (n0 + q * 8 < N) {
                int s  = m0 + r;
                int j  = (n0 >> 5) + (q >> 2);
                int wc = (s & (W_IMG - 1)) + j - 3;
                wc = wc < 0 ? 0 : (wc > W_IMG - 1 ? W_IMG - 1 : wc);
                const __half* src = g.camA +
                    (((size_t)(s & ~(W_IMG - 1)) + wc) << 5) + (q & 3) * 8;
                cp16(sb + (uint32_t)r * (GS * 2) + q * 16, src);
            }
        }
        cp_commit();
        cp_wait0();
        __syncthreads();
    }

    const int lq = lane >> 2;
    const int lr = lane & 3;

    float ss[8], qq[8];
    if (MODE & 128) {
#pragma unroll
        for (int e = 0; e < 8; e++) { ss[e] = 0.f; qq[e] = 0.f; }
    }

    // --- epilogue ---
#pragma unroll
    for (int mf = 0; mf < 4; mf++) {
        int row = m0 + wm * 64 + mf * 16 + lq;
        float inv0 = 1.f, inv1 = 1.f;
        if (MODE & 32) {
            float4 s0v = *(const float4*)(statsin + (size_t)row * 4);
            float4 s1v = *(const float4*)(statsin + (size_t)(row + 8) * 4);
            float sa = s0v.x + s0v.z, qa = s0v.y + s0v.w;
            float sb2 = s1v.x + s1v.z, qb = s1v.y + s1v.w;
            inv0 = rsqrtf(qa - sa * sa * (1.0f / FEAT));
            inv1 = rsqrtf(qb - sb2 * sb2 * (1.0f / FEAT));
        }
#pragma unroll
        for (int nf = 0; nf < 8; nf++) {
            int col = n0 + wn * 64 + nf * 8 + lr * 2;
            if (col < N) {
                float b0 = 0.f, b1 = 0.f;
                if (MODE & 1) { b0 = g.bias[col]; b1 = g.bias[col + 1]; }
#pragma unroll
                for (int half_ = 0; half_ < 2; half_++) {
                    int r = row + half_ * 8;
                    float v0 = c[mf][nf][half_ * 2 + 0];
                    float v1 = c[mf][nf][half_ * 2 + 1];
                    if (MODE & 1) { v0 += b0; v1 += b1; }
                    if (MODE & 2) { v0 = fmaxf(v0, 0.f); v1 = fmaxf(v1, 0.f); }
                    size_t o = (size_t)r * N + col;
                    if (MODE & 4) {
                        float2 rv;
                        if (g.resgather) {
                            rv = __half22float2(
                                *(const __half2*)(smh + (r - m0) * GS + (col - n0)));
                        } else {
                            rv = __half22float2(*(const __half2*)(g.Res + o));
                        }
                        v0 += rv.x; v1 += rv.y;
                    }
                    if (MODE & 16) {
                        float2 rv;
                        if (g.res2gather) {
                            rv = __half22float2(
                                *(const __half2*)(smh + (r - m0) * GS + (col - n0)));
                        } else {
                            rv = __half22float2(*(const __half2*)(g.Res2 + o));
                        }
                        v0 += rv.x; v1 += rv.y;
                    }
                    if (MODE & 32) {
                        float sc = half_ ? inv1 : inv0;
                        v0 *= sc; v1 *= sc;
                    }
                    if (MODE & 8) {
                        __half2 hv = __floats2half2_rn(v0, v1);
                        *((__half2*)((__half*)g.C + o)) = hv;
                        if (MODE & 128) {
                            float2 fr = __half22float2(hv);
                            v0 = fr.x; v1 = fr.y;
                        }
                    } else {
                        *((float2*)((float*)g.C + o)) = make_float2(v0, v1);
                    }
                    if (MODE & 128) {
                        int e = mf * 2 + half_;
                        ss[e] += v0 + v1;
                        qq[e] += v0 * v0 + v1 * v1;
                    }
                }
            }
        }
    }

    if (MODE & 128) {
#pragma unroll
        for (int e = 0; e < 8; e++) {
            ss[e] += __shfl_xor_sync(0xffffffffu, ss[e], 1);
            ss[e] += __shfl_xor_sync(0xffffffffu, ss[e], 2);
            qq[e] += __shfl_xor_sync(0xffffffffu, qq[e], 1);
            qq[e] += __shfl_xor_sync(0xffffffffu, qq[e], 2);
        }
        __syncthreads();
        if (lr == 0) {
#pragma unroll
            for (int e = 0; e < 8; e++) {
                int rl = wm * 64 + (e >> 1) * 16 + lq + (e & 1) * 8;
                atomicAdd(&smstat[rl * 2 + 0], ss[e]);
                atomicAdd(&smstat[rl * 2 + 1], qq[e]);
            }
        }
        __syncthreads();
        if (g.stats) {
            *(float2*)(g.stats + (size_t)(m0 + t) * 4 + blockIdx.x * 2) =
                make_float2(smstat[t * 2], smstat[t * 2 + 1]);
        }
    }
}

// ---------------------------------------------------------------------------
// Proj normalize: Bnorm[m,:] = (Y[m,:] - mean) / ||Y - mean||  (fp16 out)
// ---------------------------------------------------------------------------
__global__ void normalize_proj(const __half* __restrict__ Y,
                               __half* __restrict__ Out, int M) {
    int warp = (blockIdx.x * blockDim.x + threadIdx.x) >> 5;
    int lane = threadIdx.x & 31;
    if (warp >= M) return;
    size_t base = (size_t)warp * FEAT;
    float y[7];
    float sum = 0.f;
#pragma unroll
    for (int i = 0; i < 7; i++) {
        y[i] = __half2float(Y[base + lane + i * 32]);
        sum += y[i];
    }
#pragma unroll
    for (int o = 16; o > 0; o >>= 1) sum += __shfl_xor_sync(0xffffffffu, sum, o);
    float mean = sum * (1.0f / FEAT);
    float sq = 0.f;
#pragma unroll
    for (int i = 0; i < 7; i++) {
        y[i] -= mean;
        sq += y[i] * y[i];
    }
#pragma unroll
    for (int o = 16; o > 0; o >>= 1) sq += __shfl_xor_sync(0xffffffffu, sq, o);
    float inv = rsqrtf(sq);
#pragma unroll
    for (int i = 0; i < 7; i++)
        Out[base + lane + i * 32] = __float2half_rn(y[i] * inv);
}

// ---------------------------------------------------------------------------
extern "C" void kernel_launch(void* const* d_in, const int* in_sizes, int n_in,
                              void* d_out, int out_size) {
    const float* cam_code  = (const float*)d_in[0];
    const float* proj_code = (const float*)d_in[1];
    const float* cam_w0 = (const float*)d_in[2];
    const float* cam_b0 = (const float*)d_in[3];
    const float* cam_w1 = (const float*)d_in[4];
    const float* cam_b1 = (const float*)d_in[5];
    const float* proj_w0 = (const float*)d_in[6];
    const float* proj_b0 = (const float*)d_in[7];
    const float* proj_w1 = (const float*)d_in[8];
    const float* proj_b1 = (const float*)d_in[9];
    float* out = (float*)d_out;

    __half *X, *Hc, *CH, *Pp, *Xp, *Hp, *W0c, *W1c, *W0p, *W1p;
    float *ST;
    cudaGetSymbolAddress((void**)&X,   g_X);
    cudaGetSymbolAddress((void**)&Hc,  g_Hc);
    cudaGetSymbolAddress((void**)&ST,  g_stats);
    cudaGetSymbolAddress((void**)&CH,  g_camh);
    cudaGetSymbolAddress((void**)&Pp,  g_Pp);
    cudaGetSymbolAddress((void**)&Xp,  g_Xp);
    cudaGetSymbolAddress((void**)&Hp,  g_Hp);
    cudaGetSymbolAddress((void**)&W0c, g_W0c);
    cudaGetSymbolAddress((void**)&W1c, g_W1c);
    cudaGetSymbolAddress((void**)&W0p, g_W0p);
    cudaGetSymbolAddress((void**)&W1p, g_W1p);

    cudaFuncSetAttribute(tgemm<11>,  cudaFuncAttributeMaxDynamicSharedMemorySize, SMEM_BYTES);
    cudaFuncSetAttribute(tgemm<13>,  cudaFuncAttributeMaxDynamicSharedMemorySize, SMEM_BYTES);
    cudaFuncSetAttribute(tgemm<157>, cudaFuncAttributeMaxDynamicSharedMemorySize, SMEM_BYTES);
    cudaFuncSetAttribute(tgemm<32>,  cudaFuncAttributeMaxDynamicSharedMemorySize, SMEM_BYTES);

    // 1) Preprocessing
    round_weights<<<(2 * F2 + 255) / 256, 256>>>(cam_w0, W0c, cam_w1, W1c,
                                                 proj_w0, W0p, proj_w1, W1p);
    round_cam<<<(NCAM + 255) / 256, 256>>>(cam_code, CH);
    build_pproj<<<(S_PROJ * FEAT + 255) / 256, 256>>>(proj_code, Pp);

    const int TC = S_CAM / 128;   // 1024
    const int TP = S_PROJ / 128;  // 8
    dim3 gmlp((FEAT + 127) / 128, TC + TP);

    GArg c0, p0;
    // layer 0, GEMM 0: H = relu(P @ W0^T + b0); cam P gathered from g_camh
    c0 = {nullptr, W0c, nullptr, nullptr, CH, cam_b0, Hc, nullptr,
          S_CAM,  FEAT, 1, 0, 0};
    p0 = {Pp,      W0p, nullptr, nullptr, nullptr, proj_b0, Hp, nullptr,
          S_PROJ, FEAT, 0, 0, 0};
    tgemm<11><<<gmlp, 128, SMEM_BYTES>>>(c0, p0, nullptr, FEAT);

    // layer 0, GEMM 1: X = P + H @ W1^T + b1  (cam residual staged gather)
    c0 = {Hc, W1c, nullptr, nullptr, CH, cam_b1, X, nullptr,
          S_CAM,  FEAT, 0, 1, 0};
    p0 = {Hp, W1p, Pp,      nullptr, nullptr, proj_b1, Xp, nullptr,
          S_PROJ, FEAT, 0, 0, 0};
    tgemm<13><<<gmlp, 128, SMEM_BYTES>>>(c0, p0, nullptr, FEAT);

    // layer 1, GEMM 0: H = relu(X @ W0^T + b0)
    c0 = {X,  W0c + F2, nullptr, nullptr, nullptr, cam_b0 + FEAT,  Hc, nullptr,
          S_CAM,  FEAT, 0, 0, 0};
    p0 = {Xp, W0p + F2, nullptr, nullptr, nullptr, proj_b0 + FEAT, Hp, nullptr,
          S_PROJ, FEAT, 0, 0, 0};
    tgemm<11><<<gmlp, 128, SMEM_BYTES>>>(c0, p0, nullptr, FEAT);

    // layer 1, GEMM 1: Y = X + H @ W1^T + b1 + P  (+ per-row stats, cam)
    c0 = {Hc, W1c + F2, X,  nullptr, CH, cam_b1 + FEAT,  X,  ST,
          S_CAM,  FEAT, 0, 0, 1};
    p0 = {Hp, W1p + F2, Xp, Pp,      nullptr, proj_b1 + FEAT, Xp, nullptr,
          S_PROJ, FEAT, 0, 0, 0};
    tgemm<157><<<gmlp, 128, SMEM_BYTES>>>(c0, p0, nullptr, FEAT);

    // 3) Proj normalize (cam stats already emitted by tgemm<157>)
    normalize_proj<<<(S_PROJ + 7) / 8, 256>>>(Xp, Hp, S_PROJ);

    // 4) ZNCC correlation: out[s,m] = inv_a[s] * (Y[s,:] . Bnorm[m,:])
    dim3 gfin(W_PAT / 128, TC);
    GArg f0 = {X, Hp, nullptr, nullptr, nullptr, nullptr, out, nullptr,
               S_CAM, W_PAT, 0, 0, 0};
    tgemm<32><<<gfin, 128, SMEM_BYTES>>>(f0, f0, ST, FEAT);
}